// round 1
// baseline (speedup 1.0000x reference)
#include <cuda_runtime.h>
#include <math.h>

#define NN 50000
#define NE 500000
#define DA 128
#define DV 32
#define CH 32
#define LD 129   // padded smem leading dim (conflict-free)

// ---------------- scratch (device globals: allocation-free) ----------------
__device__ float g_L0[NN * CH];        // node scalar proj   [n][c]
__device__ float g_L1[NN * 3 * CH];    // node vector proj   [n][i][c]
__device__ float g_Y [(size_t)NE * 64]; // per-edge [y000|y110]  [e][64]

// ---------------- K0: node projections ----------------
__global__ void k_node(const float* __restrict__ xa, const float* __restrict__ xv,
                       const float* __restrict__ WL0, const float* __restrict__ WL1)
{
    __shared__ float sW0[128 * 32];  // [d][c]
    __shared__ float sW1[32 * 32];   // [d][c]
    __shared__ float sxa[8][128];
    __shared__ float sxv[8][96];
    int tid = threadIdx.x;
    for (int idx = tid; idx < 128 * 32; idx += 256) {
        int c = idx >> 7, d = idx & 127;
        sW0[d * 32 + c] = WL0[idx];
    }
    for (int idx = tid; idx < 32 * 32; idx += 256) {
        int c = idx >> 5, d = idx & 31;
        sW1[d * 32 + c] = WL1[idx];
    }
    int w = tid >> 5, lane = tid & 31;
    int n = blockIdx.x * 8 + w;
    if (n < NN) {
        for (int j = lane; j < 128; j += 32) sxa[w][j] = xa[n * 128 + j];
        for (int j = lane; j < 96;  j += 32) sxv[w][j] = xv[n * 96 + j];
    }
    __syncthreads();
    if (n >= NN) return;

    float acc = 0.f;
#pragma unroll 8
    for (int d = 0; d < 128; d++) acc += sxa[w][d] * sW0[d * 32 + lane];
    g_L0[n * 32 + lane] = acc;

#pragma unroll
    for (int i = 0; i < 3; i++) {
        float a = 0.f;
#pragma unroll 8
        for (int d = 0; d < 32; d++) a += sxv[w][d * 3 + i] * sW1[d * 32 + lane];
        g_L1[n * 96 + i * 32 + lane] = a;
    }
}

// ---------------- K1: edge light path (Y + psi_v scatter) ----------------
__global__ void k_edge1(const float* __restrict__ rij, const int* __restrict__ src,
                        const int* __restrict__ dst,
                        const float* __restrict__ Wenc, const float* __restrict__ benc,
                        const float* __restrict__ W011, const float* __restrict__ W101,
                        const float* __restrict__ W111,
                        float* __restrict__ Bv)
{
    __shared__ float s011[32 * 32], s101[32 * 32], s111[32 * 32]; // [c][d] transposed
    __shared__ float sWe[8 * 32];                                  // [k][c] transposed
    __shared__ float sbe[32];
    int tid = threadIdx.x;
    for (int idx = tid; idx < 1024; idx += 256) {
        int d = idx >> 5, c = idx & 31;
        s011[c * 32 + d] = W011[idx];
        s101[c * 32 + d] = W101[idx];
        s111[c * 32 + d] = W111[idx];
    }
    for (int idx = tid; idx < 256; idx += 256) {
        int c = idx >> 3, k = idx & 7;
        sWe[k * 32 + c] = Wenc[idx];
    }
    if (tid < 32) sbe[tid] = benc[tid];
    __syncthreads();

    int lane = tid & 31;
    int e = blockIdx.x * 8 + (tid >> 5);
    if (e >= NE) return;

    float rx = rij[e * 3 + 0], ry = rij[e * 3 + 1], rz = rij[e * 3 + 2];
    float rn = sqrtf(rx * rx + ry * ry + rz * rz);

    // rad_enc (gaussian RBF, centers k*5/7, width 0.625)
    float g = sbe[lane];
#pragma unroll
    for (int k = 0; k < 8; k++) {
        float t = (rn - (5.0f / 7.0f) * (float)k) * 1.6f;
        g += expf(-t * t) * sWe[k * 32 + lane];
    }

    // r_s = tens_sigmoid(1.4 * r)
    float n14 = 1.4f * rn;
    float sq  = tanhf(n14) / fmaxf(n14, 1e-6f);
    float sx = 1.4f * rx * sq, sy = 1.4f * ry * sq, sz = 1.4f * rz * sq;

    int dn = dst[e];
    float la  = g_L0[dn * 32 + lane];
    float lvx = g_L1[dn * 96 +      lane];
    float lvy = g_L1[dn * 96 + 32 + lane];
    float lvz = g_L1[dn * 96 + 64 + lane];

    // Y = [y000 | y110]
    g_Y[(size_t)e * 64 + lane]      = la * g;
    g_Y[(size_t)e * 64 + 32 + lane] = (lvx * sx + lvy * sy + lvz * sz) * g;

    // per-channel vectors for psi_v
    float s0 = g * la;
    float bx = g * lvx, by = g * lvy, bz = g * lvz;
    float cxv = g * (lvy * sz - lvz * sy);
    float cyv = g * (lvz * sx - lvx * sz);
    float czv = g * (lvx * sy - lvy * sx);

    float q = 0.f, vx = 0.f, vy = 0.f, vz = 0.f;
#pragma unroll
    for (int c = 0; c < 32; c++) {
        float ss  = __shfl_sync(0xffffffffu, s0,  c);
        float tbx = __shfl_sync(0xffffffffu, bx,  c);
        float tby = __shfl_sync(0xffffffffu, by,  c);
        float tbz = __shfl_sync(0xffffffffu, bz,  c);
        float tcx = __shfl_sync(0xffffffffu, cxv, c);
        float tcy = __shfl_sync(0xffffffffu, cyv, c);
        float tcz = __shfl_sync(0xffffffffu, czv, c);
        float w0 = s011[c * 32 + lane];
        float w1 = s101[c * 32 + lane];
        float w2 = s111[c * 32 + lane];
        q  += w0 * ss;
        vx += w1 * tbx + w2 * tcx;
        vy += w1 * tby + w2 * tcy;
        vz += w1 * tbz + w2 * tcz;
    }
    int sn = src[e];
    float px = 0.1f * (q * sx + vx);
    float py = 0.1f * (q * sy + vy);
    float pz = 0.1f * (q * sz + vz);
    atomicAdd(&Bv[sn * 96 + lane * 3 + 0], px);
    atomicAdd(&Bv[sn * 96 + lane * 3 + 1], py);
    atomicAdd(&Bv[sn * 96 + lane * 3 + 2], pz);
}

// ---------------- K2: fused edge MLP chain + B_a scatter ----------------
__device__ __forceinline__ void gemm_acc(const float* __restrict__ A,
                                         const float* __restrict__ W,
                                         int rb, int cb, int K, float acc[8][8])
{
#pragma unroll 4
    for (int k = 0; k < K; k++) {
        float a[8], w[8];
        const float* Ar = A + k * LD + rb;
        const float* Wr = W + k * LD + cb;
#pragma unroll
        for (int i = 0; i < 8; i++) a[i] = Ar[i];
#pragma unroll
        for (int j = 0; j < 8; j++) w[j] = Wr[j];
#pragma unroll
        for (int i = 0; i < 8; i++)
#pragma unroll
            for (int j = 0; j < 8; j++) acc[i][j] += a[i] * w[j];
    }
}

__global__ void __launch_bounds__(256)
k_edge2(const float* __restrict__ Wy000, const float* __restrict__ Wy110,
        const float* __restrict__ Wm1, const float* __restrict__ bm1,
        const float* __restrict__ Wm2, const float* __restrict__ bm2,
        const float* __restrict__ Wm3, const int* __restrict__ src,
        float* __restrict__ Ba)
{
    extern __shared__ float sm[];
    float* bufA = sm;              // [k][e], 128*LD
    float* bufB = sm + 128 * LD;   // psi0 [feat][e]
    float* bufW = sm + 2 * 128 * LD; // [k][a]
    __shared__ int s_src[128];

    int tid = threadIdx.x;
    int e0  = blockIdx.x * 128;

    // stage Y (transposed)
    for (int idx = tid; idx < 128 * 64; idx += 256) {
        int r = idx >> 6, k = idx & 63;
        int e = e0 + r;
        bufA[k * LD + r] = (e < NE) ? g_Y[(size_t)e * 64 + k] : 0.f;
    }
    // stage Wcat = [Wy000 | Wy110] as [k][a]
    for (int idx = tid; idx < 128 * 64; idx += 256) {
        int a = idx >> 6, k = idx & 63;
        float w = (k < 32) ? Wy000[a * 32 + k] : Wy110[a * 32 + (k - 32)];
        bufW[k * LD + a] = w;
    }
    if (tid < 128) s_src[tid] = (e0 + tid < NE) ? src[e0 + tid] : -1;
    __syncthreads();

    int ty = tid >> 4, tx = tid & 15;
    int rb = ty * 8, cb = tx * 8;
    float acc[8][8];

    // biases for this thread's 8 columns
    float b1[8], b2[8];
#pragma unroll
    for (int j = 0; j < 8; j++) { b1[j] = __ldg(&bm1[cb + j]); b2[j] = __ldg(&bm2[cb + j]); }

    // GEMM1: psi0 = Y @ Wcat^T   (K=64)
#pragma unroll
    for (int i = 0; i < 8; i++)
#pragma unroll
        for (int j = 0; j < 8; j++) acc[i][j] = 0.f;
    gemm_acc(bufA, bufW, rb, cb, 64, acc);
    __syncthreads();
#pragma unroll
    for (int i = 0; i < 8; i++)
#pragma unroll
        for (int j = 0; j < 8; j++) bufB[(cb + j) * LD + rb + i] = acc[i][j];
    for (int idx = tid; idx < 128 * 128; idx += 256) {
        int a = idx >> 7, k = idx & 127;
        bufW[k * LD + a] = Wm1[idx];
    }
    __syncthreads();

    // GEMM2: h1 = leaky(psi0 @ Wm1^T + bm1)
#pragma unroll
    for (int i = 0; i < 8; i++)
#pragma unroll
        for (int j = 0; j < 8; j++) acc[i][j] = 0.f;
    gemm_acc(bufB, bufW, rb, cb, 128, acc);
    __syncthreads();
#pragma unroll
    for (int i = 0; i < 8; i++)
#pragma unroll
        for (int j = 0; j < 8; j++) {
            float t = acc[i][j] + b1[j];
            bufA[(cb + j) * LD + rb + i] = (t >= 0.f) ? t : 0.1f * t;
        }
    for (int idx = tid; idx < 128 * 128; idx += 256) {
        int a = idx >> 7, k = idx & 127;
        bufW[k * LD + a] = Wm2[idx];
    }
    __syncthreads();

    // GEMM3: h2 = leaky(h1 @ Wm2^T + bm2)
#pragma unroll
    for (int i = 0; i < 8; i++)
#pragma unroll
        for (int j = 0; j < 8; j++) acc[i][j] = 0.f;
    gemm_acc(bufA, bufW, rb, cb, 128, acc);
    __syncthreads();
#pragma unroll
    for (int i = 0; i < 8; i++)
#pragma unroll
        for (int j = 0; j < 8; j++) {
            float t = acc[i][j] + b2[j];
            bufA[(cb + j) * LD + rb + i] = (t >= 0.f) ? t : 0.1f * t;
        }
    for (int idx = tid; idx < 128 * 128; idx += 256) {
        int a = idx >> 7, k = idx & 127;
        bufW[k * LD + a] = Wm3[idx];
    }
    __syncthreads();

    // GEMM4: psi_a = psi0 + h2 @ Wm3^T ; scatter 0.1*psi_a
#pragma unroll
    for (int i = 0; i < 8; i++)
#pragma unroll
        for (int j = 0; j < 8; j++) acc[i][j] = 0.f;
    gemm_acc(bufA, bufW, rb, cb, 128, acc);

#pragma unroll
    for (int i = 0; i < 8; i++) {
        int sn = s_src[rb + i];
        if (sn < 0) continue;
#pragma unroll
        for (int j = 0; j < 8; j++) {
            float out = 0.1f * (acc[i][j] + bufB[(cb + j) * LD + rb + i]);
            atomicAdd(&Ba[sn * 128 + cb + j], out);
        }
    }
}

// ---------------- launch ----------------
extern "C" void kernel_launch(void* const* d_in, const int* in_sizes, int n_in,
                              void* d_out, int out_size)
{
    const float* x_a   = (const float*)d_in[0];
    const float* x_v   = (const float*)d_in[1];
    const float* r_ij  = (const float*)d_in[2];
    const int*   src   = (const int*)  d_in[3];
    const int*   dst   = (const int*)  d_in[4];
    const float* WL0   = (const float*)d_in[5];
    const float* WL1   = (const float*)d_in[6];
    const float* Wenc  = (const float*)d_in[7];
    const float* benc  = (const float*)d_in[8];
    const float* Wy000 = (const float*)d_in[9];
    const float* Wy110 = (const float*)d_in[10];
    const float* Wy011 = (const float*)d_in[11];
    const float* Wy101 = (const float*)d_in[12];
    const float* Wy111 = (const float*)d_in[13];
    const float* Wm1   = (const float*)d_in[14];
    const float* bm1   = (const float*)d_in[15];
    const float* Wm2   = (const float*)d_in[16];
    const float* bm2   = (const float*)d_in[17];
    const float* Wm3   = (const float*)d_in[18];
    float* out = (float*)d_out;

    cudaMemsetAsync(out, 0, (size_t)out_size * sizeof(float), 0);

    k_node<<<(NN + 7) / 8, 256>>>(x_a, x_v, WL0, WL1);

    k_edge1<<<(NE + 7) / 8, 256>>>(r_ij, src, dst, Wenc, benc,
                                   Wy011, Wy101, Wy111,
                                   out + (size_t)NN * 128);

    int smem = 3 * 128 * LD * (int)sizeof(float);
    cudaFuncSetAttribute(k_edge2, cudaFuncAttributeMaxDynamicSharedMemorySize, smem);
    k_edge2<<<(NE + 127) / 128, 256, smem>>>(Wy000, Wy110, Wm1, bm1, Wm2, bm2, Wm3,
                                             src, out);
}

// round 3
// speedup vs baseline: 1.7893x; 1.7893x over previous
#include <cuda_runtime.h>
#include <cstdint>
#include <math.h>

#define NN 50000
#define NE 500000
#define NE_PAD 500096           // 3907 * 128
#define LDW 132                 // smem leading dim (floats): bank-perfect for frag loads
#define WBLOB (128 * LDW)       // one weight image (floats)

// ---------------- scratch (device globals: allocation-free) ----------------
__device__ float g_L0[NN * 32];
__device__ float g_L1[NN * 3 * 32];
__device__ __align__(16) float g_Y[(size_t)NE_PAD * 64];  // tf32-rounded [e][64]
__device__ __align__(16) float g_Wb[4][WBLOB];            // pre-swizzled tf32 weights

// ================= helpers =================
__device__ __forceinline__ uint32_t smem_u32(const void* p) {
    uint32_t a;
    asm("{ .reg .u64 t; cvta.to.shared.u64 t, %1; cvt.u32.u64 %0, t; }" : "=r"(a) : "l"(p));
    return a;
}
__device__ __forceinline__ uint32_t cvt_tf32(float f) {
    uint32_t r; asm("cvt.rna.tf32.f32 %0, %1;" : "=r"(r) : "f"(f)); return r;
}
__device__ __forceinline__ float tf32f(float f) { return __uint_as_float(cvt_tf32(f)); }

__device__ __forceinline__ void cp16(uint32_t d, const void* s) {
    asm volatile("cp.async.cg.shared.global [%0], [%1], 16;" :: "r"(d), "l"(s) : "memory");
}
#define CP_COMMIT() asm volatile("cp.async.commit_group;" ::: "memory")
#define CP_WAIT(n)  asm volatile("cp.async.wait_group %0;" :: "n"(n) : "memory")

__device__ __forceinline__ void red2(float* p, float a, float b) {
    asm volatile("red.global.add.v2.f32 [%0], {%1, %2};" :: "l"(p), "f"(a), "f"(b) : "memory");
}
__device__ __forceinline__ float lk(float t) { return (t >= 0.f) ? t : 0.1f * t; }

__device__ __forceinline__ void mma8(float* c, const uint32_t* a, const uint32_t* b) {
    asm volatile("mma.sync.aligned.m16n8k8.row.col.f32.tf32.tf32.f32 "
        "{%0,%1,%2,%3}, {%4,%5,%6,%7}, {%8,%9}, {%0,%1,%2,%3};"
        : "+f"(c[0]), "+f"(c[1]), "+f"(c[2]), "+f"(c[3])
        : "r"(a[0]), "r"(a[1]), "r"(a[2]), "r"(a[3]), "r"(b[0]), "r"(b[1]));
}

// A[m][k], W[n][k] in smem, LDW leading dim. warp tile 32x64.
__device__ __forceinline__ void gemm_ws(const float* __restrict__ As,
                                        const float* __restrict__ Ws,
                                        int ksteps, int m0, int n0, int lane,
                                        float acc[2][8][4])
{
    int ar = lane >> 2, ac = lane & 3;
    const float* Ap0 = As + (m0 + ar) * LDW + ac;
    const float* Ap1 = As + (m0 + 16 + ar) * LDW + ac;
    const float* Wp  = Ws + (n0 + ar) * LDW + ac;
#pragma unroll 2
    for (int ks = 0; ks < ksteps; ks++) {
        int k0 = ks * 8;
        uint32_t a[2][4], b[8][2];
        a[0][0] = __float_as_uint(Ap0[k0]);
        a[0][1] = __float_as_uint(Ap0[k0 + 8 * LDW]);
        a[0][2] = __float_as_uint(Ap0[k0 + 4]);
        a[0][3] = __float_as_uint(Ap0[k0 + 8 * LDW + 4]);
        a[1][0] = __float_as_uint(Ap1[k0]);
        a[1][1] = __float_as_uint(Ap1[k0 + 8 * LDW]);
        a[1][2] = __float_as_uint(Ap1[k0 + 4]);
        a[1][3] = __float_as_uint(Ap1[k0 + 8 * LDW + 4]);
#pragma unroll
        for (int ni = 0; ni < 8; ni++) {
            const float* q = Wp + ni * 8 * LDW + k0;
            b[ni][0] = __float_as_uint(q[0]);
            b[ni][1] = __float_as_uint(q[4]);
        }
#pragma unroll
        for (int mi = 0; mi < 2; mi++)
#pragma unroll
            for (int ni = 0; ni < 8; ni++) mma8(acc[mi][ni], a[mi], b[ni]);
    }
}

// ---------------- K_prep: weights -> tf32 swizzled blobs ----------------
__global__ void k_prep(const float* __restrict__ Wy000, const float* __restrict__ Wy110,
                       const float* __restrict__ Wm1, const float* __restrict__ Wm2,
                       const float* __restrict__ Wm3)
{
    int idx = blockIdx.x * 256 + threadIdx.x;
    if (idx >= WBLOB) return;
    int n = idx / LDW, k = idx % LDW;
    float w0 = 0.f, w1 = 0.f, w2 = 0.f, w3 = 0.f;
    if (k < 64)  w0 = (k < 32) ? Wy000[n * 32 + k] : Wy110[n * 32 + (k - 32)];
    if (k < 128) { w1 = Wm1[n * 128 + k]; w2 = Wm2[n * 128 + k]; w3 = Wm3[n * 128 + k]; }
    g_Wb[0][idx] = tf32f(w0);
    g_Wb[1][idx] = tf32f(w1);
    g_Wb[2][idx] = tf32f(w2);
    g_Wb[3][idx] = tf32f(w3);
}

// ---------------- K0: node projections ----------------
__global__ void k_node(const float* __restrict__ xa, const float* __restrict__ xv,
                       const float* __restrict__ WL0, const float* __restrict__ WL1)
{
    __shared__ float sW0[128 * 32];
    __shared__ float sW1[32 * 32];
    __shared__ float sxa[8][128];
    __shared__ float sxv[8][96];
    int tid = threadIdx.x;
    for (int idx = tid; idx < 128 * 32; idx += 256) {
        int c = idx >> 7, d = idx & 127;
        sW0[d * 32 + c] = WL0[idx];
    }
    for (int idx = tid; idx < 32 * 32; idx += 256) {
        int c = idx >> 5, d = idx & 31;
        sW1[d * 32 + c] = WL1[idx];
    }
    int w = tid >> 5, lane = tid & 31;
    int n = blockIdx.x * 8 + w;
    if (n < NN) {
        for (int j = lane; j < 128; j += 32) sxa[w][j] = xa[n * 128 + j];
        for (int j = lane; j < 96;  j += 32) sxv[w][j] = xv[n * 96 + j];
    }
    __syncthreads();
    if (n >= NN) return;

    float acc = 0.f;
#pragma unroll 8
    for (int d = 0; d < 128; d++) acc += sxa[w][d] * sW0[d * 32 + lane];
    g_L0[n * 32 + lane] = acc;

#pragma unroll
    for (int i = 0; i < 3; i++) {
        float a = 0.f;
#pragma unroll 8
        for (int d = 0; d < 32; d++) a += sxv[w][d * 3 + i] * sW1[d * 32 + lane];
        g_L1[n * 96 + i * 32 + lane] = a;
    }
}

// ---------------- K1: edge light path (Y + psi_v scatter) ----------------
__global__ void k_edge1(const float* __restrict__ rij, const int* __restrict__ src,
                        const int* __restrict__ dst,
                        const float* __restrict__ Wenc, const float* __restrict__ benc,
                        const float* __restrict__ W011, const float* __restrict__ W101,
                        const float* __restrict__ W111,
                        float* __restrict__ Bv)
{
    __shared__ float s011[32 * 32], s101[32 * 32], s111[32 * 32];
    __shared__ float sWe[8 * 32];
    __shared__ float sbe[32];
    int tid = threadIdx.x;
    for (int idx = tid; idx < 1024; idx += 256) {
        int d = idx >> 5, c = idx & 31;
        s011[c * 32 + d] = W011[idx];
        s101[c * 32 + d] = W101[idx];
        s111[c * 32 + d] = W111[idx];
    }
    for (int idx = tid; idx < 256; idx += 256) {
        int c = idx >> 3, k = idx & 7;
        sWe[k * 32 + c] = Wenc[idx];
    }
    if (tid < 32) sbe[tid] = benc[tid];
    __syncthreads();

    int lane = tid & 31;
    int e = blockIdx.x * 8 + (tid >> 5);
    if (e >= NE) return;

    float rx = rij[e * 3 + 0], ry = rij[e * 3 + 1], rz = rij[e * 3 + 2];
    float rn = sqrtf(rx * rx + ry * ry + rz * rz);

    float g = sbe[lane];
#pragma unroll
    for (int k = 0; k < 8; k++) {
        float t = (rn - (5.0f / 7.0f) * (float)k) * 1.6f;
        g += expf(-t * t) * sWe[k * 32 + lane];
    }

    float n14 = 1.4f * rn;
    float sq  = tanhf(n14) / fmaxf(n14, 1e-6f);
    float sx = 1.4f * rx * sq, sy = 1.4f * ry * sq, sz = 1.4f * rz * sq;

    int dn = dst[e];
    float la  = g_L0[dn * 32 + lane];
    float lvx = g_L1[dn * 96 +      lane];
    float lvy = g_L1[dn * 96 + 32 + lane];
    float lvz = g_L1[dn * 96 + 64 + lane];

    // Y = [y000 | y110], pre-rounded to tf32 for the MMA chain
    g_Y[(size_t)e * 64 + lane]      = tf32f(la * g);
    g_Y[(size_t)e * 64 + 32 + lane] = tf32f((lvx * sx + lvy * sy + lvz * sz) * g);

    float s0 = g * la;
    float bx = g * lvx, by = g * lvy, bz = g * lvz;
    float cxv = g * (lvy * sz - lvz * sy);
    float cyv = g * (lvz * sx - lvx * sz);
    float czv = g * (lvx * sy - lvy * sx);

    float q = 0.f, vx = 0.f, vy = 0.f, vz = 0.f;
#pragma unroll
    for (int c = 0; c < 32; c++) {
        float ss  = __shfl_sync(0xffffffffu, s0,  c);
        float tbx = __shfl_sync(0xffffffffu, bx,  c);
        float tby = __shfl_sync(0xffffffffu, by,  c);
        float tbz = __shfl_sync(0xffffffffu, bz,  c);
        float tcx = __shfl_sync(0xffffffffu, cxv, c);
        float tcy = __shfl_sync(0xffffffffu, cyv, c);
        float tcz = __shfl_sync(0xffffffffu, czv, c);
        float w0 = s011[c * 32 + lane];
        float w1 = s101[c * 32 + lane];
        float w2 = s111[c * 32 + lane];
        q  += w0 * ss;
        vx += w1 * tbx + w2 * tcx;
        vy += w1 * tby + w2 * tcy;
        vz += w1 * tbz + w2 * tcz;
    }
    int sn = src[e];
    atomicAdd(&Bv[sn * 96 + lane * 3 + 0], 0.1f * (q * sx + vx));
    atomicAdd(&Bv[sn * 96 + lane * 3 + 1], 0.1f * (q * sy + vy));
    atomicAdd(&Bv[sn * 96 + lane * 3 + 2], 0.1f * (q * sz + vz));
}

// ---------------- K2: tf32 mma.sync fused MLP chain + B_a scatter ----------------
__global__ void __launch_bounds__(256)
k_edge2(const float* __restrict__ bm1, const float* __restrict__ bm2,
        const int* __restrict__ src, float* __restrict__ Ba)
{
    extern __shared__ __align__(16) float sm[];
    float* As = sm;                 // 128 x LDW
    float* W0 = sm + WBLOB;
    float* W1 = sm + 2 * WBLOB;
    __shared__ float s_b1[128], s_b2[128];
    __shared__ int s_src[128];

    int tid = threadIdx.x, wid = tid >> 5, lane = tid & 31;
    int m0 = (wid >> 1) * 32, n0 = (wid & 1) * 64;
    int ar = lane >> 2, ac = lane & 3;
    int e0 = blockIdx.x * 128;

    if (tid < 128) {
        s_b1[tid] = bm1[tid];
        s_b2[tid] = bm2[tid];
        int e = e0 + tid;
        s_src[tid] = (e < NE) ? src[e] : -1;
    }

    uint32_t uA  = smem_u32(As);
    uint32_t uW0 = smem_u32(W0);
    uint32_t uW1 = smem_u32(W1);

    // group1: Y rows + Wcat image
    for (int idx = tid; idx < 2048; idx += 256) {
        int m = idx >> 4, c = idx & 15;
        cp16(uA + (uint32_t)(m * LDW * 4 + c * 16),
             (const char*)(g_Y + (size_t)(e0 + m) * 64) + c * 16);
    }
    for (int idx = tid; idx < 4224; idx += 256)
        cp16(uW0 + (uint32_t)(idx * 16), (const char*)g_Wb[0] + idx * 16);
    CP_COMMIT();
    // group2: Wm1 (overlaps GEMM1)
    for (int idx = tid; idx < 4224; idx += 256)
        cp16(uW1 + (uint32_t)(idx * 16), (const char*)g_Wb[1] + idx * 16);
    CP_COMMIT();
    CP_WAIT(1);
    __syncthreads();

    float acc[2][8][4];
#pragma unroll
    for (int mi = 0; mi < 2; mi++)
#pragma unroll
        for (int ni = 0; ni < 8; ni++)
#pragma unroll
            for (int j = 0; j < 4; j++) acc[mi][ni][j] = 0.f;

    // ---- GEMM1: psi0 = Y @ Wcat^T (K=64) ----
    gemm_ws(As, W0, 8, m0, n0, lane, acc);

    float psi[2][8][4];
#pragma unroll
    for (int mi = 0; mi < 2; mi++)
#pragma unroll
        for (int ni = 0; ni < 8; ni++)
#pragma unroll
            for (int j = 0; j < 4; j++) psi[mi][ni][j] = acc[mi][ni][j];

    __syncthreads();   // all reads of As done before overwrite
#pragma unroll
    for (int mi = 0; mi < 2; mi++)
#pragma unroll
        for (int ni = 0; ni < 8; ni++) {
            int row = m0 + mi * 16 + ar;
            int col = n0 + ni * 8 + 2 * ac;
            float2 v0 = make_float2(tf32f(acc[mi][ni][0]), tf32f(acc[mi][ni][1]));
            float2 v1 = make_float2(tf32f(acc[mi][ni][2]), tf32f(acc[mi][ni][3]));
            *(float2*)(As + row * LDW + col) = v0;
            *(float2*)(As + (row + 8) * LDW + col) = v1;
        }
    // group3: Wm2 -> W0
    for (int idx = tid; idx < 4224; idx += 256)
        cp16(uW0 + (uint32_t)(idx * 16), (const char*)g_Wb[2] + idx * 16);
    CP_COMMIT();
    CP_WAIT(1);
    __syncthreads();

    // ---- GEMM2: h1 = leaky(psi0 @ Wm1^T + b1) ----
#pragma unroll
    for (int mi = 0; mi < 2; mi++)
#pragma unroll
        for (int ni = 0; ni < 8; ni++)
#pragma unroll
            for (int j = 0; j < 4; j++) acc[mi][ni][j] = 0.f;
    gemm_ws(As, W1, 16, m0, n0, lane, acc);
    __syncthreads();
#pragma unroll
    for (int mi = 0; mi < 2; mi++)
#pragma unroll
        for (int ni = 0; ni < 8; ni++) {
            int row = m0 + mi * 16 + ar;
            int col = n0 + ni * 8 + 2 * ac;
            float2 bb = *(const float2*)(s_b1 + col);
            float2 v0 = make_float2(tf32f(lk(acc[mi][ni][0] + bb.x)), tf32f(lk(acc[mi][ni][1] + bb.y)));
            float2 v1 = make_float2(tf32f(lk(acc[mi][ni][2] + bb.x)), tf32f(lk(acc[mi][ni][3] + bb.y)));
            *(float2*)(As + row * LDW + col) = v0;
            *(float2*)(As + (row + 8) * LDW + col) = v1;
        }
    // group4: Wm3 -> W1
    for (int idx = tid; idx < 4224; idx += 256)
        cp16(uW1 + (uint32_t)(idx * 16), (const char*)g_Wb[3] + idx * 16);
    CP_COMMIT();
    CP_WAIT(1);
    __syncthreads();

    // ---- GEMM3: h2 = leaky(h1 @ Wm2^T + b2) ----
#pragma unroll
    for (int mi = 0; mi < 2; mi++)
#pragma unroll
        for (int ni = 0; ni < 8; ni++)
#pragma unroll
            for (int j = 0; j < 4; j++) acc[mi][ni][j] = 0.f;
    gemm_ws(As, W0, 16, m0, n0, lane, acc);
    __syncthreads();
#pragma unroll
    for (int mi = 0; mi < 2; mi++)
#pragma unroll
        for (int ni = 0; ni < 8; ni++) {
            int row = m0 + mi * 16 + ar;
            int col = n0 + ni * 8 + 2 * ac;
            float2 bb = *(const float2*)(s_b2 + col);
            float2 v0 = make_float2(tf32f(lk(acc[mi][ni][0] + bb.x)), tf32f(lk(acc[mi][ni][1] + bb.y)));
            float2 v1 = make_float2(tf32f(lk(acc[mi][ni][2] + bb.x)), tf32f(lk(acc[mi][ni][3] + bb.y)));
            *(float2*)(As + row * LDW + col) = v0;
            *(float2*)(As + (row + 8) * LDW + col) = v1;
        }
    CP_WAIT(0);
    __syncthreads();

    // ---- GEMM4: psi_a = psi0 + h2 @ Wm3^T ; scatter 0.1*psi_a ----
#pragma unroll
    for (int mi = 0; mi < 2; mi++)
#pragma unroll
        for (int ni = 0; ni < 8; ni++)
#pragma unroll
            for (int j = 0; j < 4; j++) acc[mi][ni][j] = psi[mi][ni][j];
    gemm_ws(As, W1, 16, m0, n0, lane, acc);

#pragma unroll
    for (int mi = 0; mi < 2; mi++) {
        int row = m0 + mi * 16 + ar;
        int sn0 = s_src[row];
        int sn1 = s_src[row + 8];
#pragma unroll
        for (int ni = 0; ni < 8; ni++) {
            int col = n0 + ni * 8 + 2 * ac;
            if (sn0 >= 0)
                red2(Ba + (size_t)sn0 * 128 + col,
                     0.1f * acc[mi][ni][0], 0.1f * acc[mi][ni][1]);
            if (sn1 >= 0)
                red2(Ba + (size_t)sn1 * 128 + col,
                     0.1f * acc[mi][ni][2], 0.1f * acc[mi][ni][3]);
        }
    }
}

// ---------------- launch ----------------
extern "C" void kernel_launch(void* const* d_in, const int* in_sizes, int n_in,
                              void* d_out, int out_size)
{
    const float* x_a   = (const float*)d_in[0];
    const float* x_v   = (const float*)d_in[1];
    const float* r_ij  = (const float*)d_in[2];
    const int*   src   = (const int*)  d_in[3];
    const int*   dst   = (const int*)  d_in[4];
    const float* WL0   = (const float*)d_in[5];
    const float* WL1   = (const float*)d_in[6];
    const float* Wenc  = (const float*)d_in[7];
    const float* benc  = (const float*)d_in[8];
    const float* Wy000 = (const float*)d_in[9];
    const float* Wy110 = (const float*)d_in[10];
    const float* Wy011 = (const float*)d_in[11];
    const float* Wy101 = (const float*)d_in[12];
    const float* Wy111 = (const float*)d_in[13];
    const float* Wm1   = (const float*)d_in[14];
    const float* bm1   = (const float*)d_in[15];
    const float* Wm2   = (const float*)d_in[16];
    const float* bm2   = (const float*)d_in[17];
    const float* Wm3   = (const float*)d_in[18];
    float* out = (float*)d_out;

    cudaMemsetAsync(out, 0, (size_t)out_size * sizeof(float), 0);

    k_prep<<<(WBLOB + 255) / 256, 256>>>(Wy000, Wy110, Wm1, Wm2, Wm3);

    k_node<<<(NN + 7) / 8, 256>>>(x_a, x_v, WL0, WL1);

    k_edge1<<<(NE + 7) / 8, 256>>>(r_ij, src, dst, Wenc, benc,
                                   Wy011, Wy101, Wy111,
                                   out + (size_t)NN * 128);

    int smem = 3 * WBLOB * (int)sizeof(float);   // 202,752 B
    cudaFuncSetAttribute(k_edge2, cudaFuncAttributeMaxDynamicSharedMemorySize, smem);
    k_edge2<<<(NE + 127) / 128, 256, smem>>>(bm1, bm2, src, out);
}

// round 4
// speedup vs baseline: 3.6439x; 2.0365x over previous
#include <cuda_runtime.h>
#include <cstdint>
#include <math.h>

#define NN 50000
#define NE 500000
#define NE_PAD 500096           // 3907 * 128
#define LDW 132                 // k_edge2 smem leading dim
#define WBLOB (128 * LDW)
#define LD1 36                  // k_edge1 smem leading dim (bank-perfect frags)

// ---------------- scratch (device globals: allocation-free) ----------------
__device__ float g_L0[NN * 32];
__device__ float g_L1[NN * 3 * 32];
__device__ __align__(16) float g_Y[(size_t)NE_PAD * 64];  // tf32 [e][64]
__device__ __align__(16) float g_Wb[4][WBLOB];            // pre-swizzled tf32 weights

// ================= helpers =================
__device__ __forceinline__ uint32_t smem_u32(const void* p) {
    uint32_t a;
    asm("{ .reg .u64 t; cvta.to.shared.u64 t, %1; cvt.u32.u64 %0, t; }" : "=r"(a) : "l"(p));
    return a;
}
__device__ __forceinline__ uint32_t cvt_tf32(float f) {
    uint32_t r; asm("cvt.rna.tf32.f32 %0, %1;" : "=r"(r) : "f"(f)); return r;
}
__device__ __forceinline__ float tf32f(float f) { return __uint_as_float(cvt_tf32(f)); }

__device__ __forceinline__ void cp16(uint32_t d, const void* s) {
    asm volatile("cp.async.cg.shared.global [%0], [%1], 16;" :: "r"(d), "l"(s) : "memory");
}
#define CP_COMMIT() asm volatile("cp.async.commit_group;" ::: "memory")
#define CP_WAIT(n)  asm volatile("cp.async.wait_group %0;" :: "n"(n) : "memory")

__device__ __forceinline__ void red2(float* p, float a, float b) {
    asm volatile("red.global.add.v2.f32 [%0], {%1, %2};" :: "l"(p), "f"(a), "f"(b) : "memory");
}
__device__ __forceinline__ void red1(float* p, float a) {
    asm volatile("red.global.add.f32 [%0], %1;" :: "l"(p), "f"(a) : "memory");
}
__device__ __forceinline__ float lk(float t) { return (t >= 0.f) ? t : 0.1f * t; }

__device__ __forceinline__ void mma8(float* c, const uint32_t* a, const uint32_t* b) {
    asm volatile("mma.sync.aligned.m16n8k8.row.col.f32.tf32.tf32.f32 "
        "{%0,%1,%2,%3}, {%4,%5,%6,%7}, {%8,%9}, {%0,%1,%2,%3};"
        : "+f"(c[0]), "+f"(c[1]), "+f"(c[2]), "+f"(c[3])
        : "r"(a[0]), "r"(a[1]), "r"(a[2]), "r"(a[3]), "r"(b[0]), "r"(b[1]));
}

// A[m][k], W[n][k] in smem, LDW leading dim. warp tile 32x64. (k_edge2)
__device__ __forceinline__ void gemm_ws(const float* __restrict__ As,
                                        const float* __restrict__ Ws,
                                        int ksteps, int m0, int n0, int lane,
                                        float acc[2][8][4])
{
    int ar = lane >> 2, ac = lane & 3;
    const float* Ap0 = As + (m0 + ar) * LDW + ac;
    const float* Ap1 = As + (m0 + 16 + ar) * LDW + ac;
    const float* Wp  = Ws + (n0 + ar) * LDW + ac;
#pragma unroll 2
    for (int ks = 0; ks < ksteps; ks++) {
        int k0 = ks * 8;
        uint32_t a[2][4], b[8][2];
        a[0][0] = __float_as_uint(Ap0[k0]);
        a[0][1] = __float_as_uint(Ap0[k0 + 8 * LDW]);
        a[0][2] = __float_as_uint(Ap0[k0 + 4]);
        a[0][3] = __float_as_uint(Ap0[k0 + 8 * LDW + 4]);
        a[1][0] = __float_as_uint(Ap1[k0]);
        a[1][1] = __float_as_uint(Ap1[k0 + 8 * LDW]);
        a[1][2] = __float_as_uint(Ap1[k0 + 4]);
        a[1][3] = __float_as_uint(Ap1[k0 + 8 * LDW + 4]);
#pragma unroll
        for (int ni = 0; ni < 8; ni++) {
            const float* q = Wp + ni * 8 * LDW + k0;
            b[ni][0] = __float_as_uint(q[0]);
            b[ni][1] = __float_as_uint(q[4]);
        }
#pragma unroll
        for (int mi = 0; mi < 2; mi++)
#pragma unroll
            for (int ni = 0; ni < 8; ni++) mma8(acc[mi][ni], a[mi], b[ni]);
    }
}

// ---------------- K_prep: weights -> tf32 swizzled blobs ----------------
__global__ void k_prep(const float* __restrict__ Wy000, const float* __restrict__ Wy110,
                       const float* __restrict__ Wm1, const float* __restrict__ Wm2,
                       const float* __restrict__ Wm3)
{
    int idx = blockIdx.x * 256 + threadIdx.x;
    if (idx >= WBLOB) return;
    int n = idx / LDW, k = idx % LDW;
    float w0 = 0.f, w1 = 0.f, w2 = 0.f, w3 = 0.f;
    if (k < 64)  w0 = (k < 32) ? Wy000[n * 32 + k] : Wy110[n * 32 + (k - 32)];
    if (k < 128) { w1 = Wm1[n * 128 + k]; w2 = Wm2[n * 128 + k]; w3 = Wm3[n * 128 + k]; }
    g_Wb[0][idx] = tf32f(w0);
    g_Wb[1][idx] = tf32f(w1);
    g_Wb[2][idx] = tf32f(w2);
    g_Wb[3][idx] = tf32f(w3);
}

// ---------------- K0: node projections (float4 smem) ----------------
__global__ void __launch_bounds__(256) k_node(
    const float* __restrict__ xa, const float* __restrict__ xv,
    const float* __restrict__ WL0, const float* __restrict__ WL1)
{
    __shared__ float sW0t[32][132];   // [c][d]
    __shared__ float sW1t[32][33];    // [c][d]
    __shared__ float sxa[8][128];
    __shared__ float sxv[8][96];
    int tid = threadIdx.x;
    for (int idx = tid; idx < 4096; idx += 256) {
        int c = idx >> 7, d = idx & 127;
        sW0t[c][d] = WL0[idx];
    }
    for (int idx = tid; idx < 1024; idx += 256) {
        int c = idx >> 5, d = idx & 31;
        sW1t[c][d] = WL1[idx];
    }
    int w = tid >> 5, lane = tid & 31;
    int n = blockIdx.x * 8 + w;
    if (n < NN) {
        for (int j = lane; j < 128; j += 32) sxa[w][j] = xa[n * 128 + j];
        for (int j = lane; j < 96;  j += 32) sxv[w][j] = xv[n * 96 + j];
    }
    __syncthreads();
    if (n >= NN) return;

    const float4* wv = (const float4*)&sW0t[lane][0];
    const float4* x4 = (const float4*)&sxa[w][0];
    float acc = 0.f;
#pragma unroll 8
    for (int d4 = 0; d4 < 32; d4++) {
        float4 a = x4[d4], b = wv[d4];
        acc += a.x * b.x + a.y * b.y + a.z * b.z + a.w * b.w;
    }
    g_L0[n * 32 + lane] = acc;

    float a0 = 0.f, a1 = 0.f, a2 = 0.f;
#pragma unroll 8
    for (int d = 0; d < 32; d++) {
        float wd = sW1t[lane][d];
        a0 += sxv[w][3 * d]     * wd;
        a1 += sxv[w][3 * d + 1] * wd;
        a2 += sxv[w][3 * d + 2] * wd;
    }
    g_L1[n * 96 +      lane] = a0;
    g_L1[n * 96 + 32 + lane] = a1;
    g_L1[n * 96 + 64 + lane] = a2;
}

// ---------------- K1: edge light path, tensor-core psi_v ----------------
__global__ void __launch_bounds__(256, 2) k_edge1(
    const float* __restrict__ rij, const int* __restrict__ src,
    const int* __restrict__ dst,
    const float* __restrict__ Wenc, const float* __restrict__ benc,
    const float* __restrict__ W011, const float* __restrict__ W101,
    const float* __restrict__ W111,
    float* __restrict__ Bv)
{
    extern __shared__ __align__(16) float s1[];
    float* sY0 = s1;                   // 128 x LD1
    float* sGx = sY0 + 128 * LD1;
    float* sGy = sGx + 128 * LD1;
    float* sGz = sGy + 128 * LD1;
    float* sW  = sGz + 128 * LD1;      // 3 x 32 x LD1
    float* s_rs = sW + 3 * 32 * LD1;   // 128 x 4
    __shared__ float sWe[8 * 32];      // [k][c]
    __shared__ float sbe[32];
    __shared__ int   s_src[128];

    int tid = threadIdx.x, wid = tid >> 5, lane = tid & 31;
    int e0 = blockIdx.x * 128;

    for (int idx = tid; idx < 256; idx += 256) {
        int c = idx >> 3, k = idx & 7;
        sWe[k * 32 + c] = Wenc[idx];
    }
    if (tid < 32) sbe[tid] = benc[tid];
    for (int idx = tid; idx < 3 * 1024; idx += 256) {
        int wi = idx >> 10, r = idx & 1023;
        int d = r >> 5, c = r & 31;
        const float* Wsrc = (wi == 0) ? W011 : ((wi == 1) ? W101 : W111);
        sW[wi * 32 * LD1 + d * LD1 + c] = tf32f(Wsrc[d * 32 + c]);
    }
    if (tid < 128) s_src[tid] = (e0 + tid < NE) ? src[e0 + tid] : -1;
    __syncthreads();   // sbe/sWe ready for phase 1

    // ---- phase 1: per-edge elementwise (warp per edge) ----
    for (int it = 0; it < 16; it++) {
        int el = it * 8 + wid;
        int e  = e0 + el;
        float y0 = 0.f, gx = 0.f, gy = 0.f, gz = 0.f;
        float sx = 0.f, sy = 0.f, sz = 0.f;
        if (e < NE) {
            float rx = rij[3 * e], ry = rij[3 * e + 1], rz = rij[3 * e + 2];
            float rn = sqrtf(rx * rx + ry * ry + rz * rz);
            float ek = 0.f;
            if (lane < 8) {
                float t = (rn - (5.0f / 7.0f) * (float)lane) * 1.6f;
                ek = expf(-t * t);
            }
            float sq_l = 0.f;
            if (lane == 8) {
                float n14 = 1.4f * rn;
                sq_l = tanhf(n14) / fmaxf(n14, 1e-6f);
            }
            float sq = __shfl_sync(0xffffffffu, sq_l, 8);
            sx = 1.4f * rx * sq; sy = 1.4f * ry * sq; sz = 1.4f * rz * sq;

            float g = sbe[lane];
#pragma unroll
            for (int k = 0; k < 8; k++)
                g += __shfl_sync(0xffffffffu, ek, k) * sWe[k * 32 + lane];

            int dn = dst[e];
            float la  = g_L0[dn * 32 + lane];
            float lvx = g_L1[dn * 96 +      lane];
            float lvy = g_L1[dn * 96 + 32 + lane];
            float lvz = g_L1[dn * 96 + 64 + lane];

            y0 = tf32f(la * g);
            gx = tf32f(g * lvx); gy = tf32f(g * lvy); gz = tf32f(g * lvz);

            g_Y[(size_t)e * 64 + lane]      = y0;
            g_Y[(size_t)e * 64 + 32 + lane] = tf32f((lvx * sx + lvy * sy + lvz * sz) * g);
        }
        sY0[el * LD1 + lane] = y0;
        sGx[el * LD1 + lane] = gx;
        sGy[el * LD1 + lane] = gy;
        sGz[el * LD1 + lane] = gz;
        if (lane == 0) {
            s_rs[el * 4]     = sx;
            s_rs[el * 4 + 1] = sy;
            s_rs[el * 4 + 2] = sz;
        }
    }
    __syncthreads();

    // ---- phase 2: 7 GEMMs (q, u_xyz, v_xyz) + combine + scatter ----
    int cg = wid & 1, rg = wid >> 1;
    int n0 = cg * 16;
    int ar = lane >> 2, ac = lane & 3;

#pragma unroll 1
    for (int pass = 0; pass < 2; pass++) {
        int m0 = pass * 64 + rg * 16;
        float q[2][4], u[3][2][4], vv[3][2][4];
#pragma unroll
        for (int ni = 0; ni < 2; ni++)
#pragma unroll
            for (int j = 0; j < 4; j++) {
                q[ni][j] = 0.f;
#pragma unroll
                for (int i = 0; i < 3; i++) { u[i][ni][j] = 0.f; vv[i][ni][j] = 0.f; }
            }

        const float* Ay = sY0 + (m0 + ar) * LD1 + ac;
        const float* Agx = sGx + (m0 + ar) * LD1 + ac;
        const float* Agy = sGy + (m0 + ar) * LD1 + ac;
        const float* Agz = sGz + (m0 + ar) * LD1 + ac;
        const float* B0 = sW + 0 * 32 * LD1 + (n0 + ar) * LD1 + ac;
        const float* B1 = sW + 1 * 32 * LD1 + (n0 + ar) * LD1 + ac;
        const float* B2 = sW + 2 * 32 * LD1 + (n0 + ar) * LD1 + ac;

#pragma unroll
        for (int ks = 0; ks < 4; ks++) {
            int k0 = ks * 8;
            uint32_t ay[4], ag[3][4];
            ay[0] = __float_as_uint(Ay[k0]);
            ay[1] = __float_as_uint(Ay[k0 + 8 * LD1]);
            ay[2] = __float_as_uint(Ay[k0 + 4]);
            ay[3] = __float_as_uint(Ay[k0 + 8 * LD1 + 4]);
            const float* Ags[3] = {Agx, Agy, Agz};
#pragma unroll
            for (int i = 0; i < 3; i++) {
                ag[i][0] = __float_as_uint(Ags[i][k0]);
                ag[i][1] = __float_as_uint(Ags[i][k0 + 8 * LD1]);
                ag[i][2] = __float_as_uint(Ags[i][k0 + 4]);
                ag[i][3] = __float_as_uint(Ags[i][k0 + 8 * LD1 + 4]);
            }
            uint32_t b0[2][2], b1[2][2], b2[2][2];
#pragma unroll
            for (int ni = 0; ni < 2; ni++) {
                b0[ni][0] = __float_as_uint(B0[ni * 8 * LD1 + k0]);
                b0[ni][1] = __float_as_uint(B0[ni * 8 * LD1 + k0 + 4]);
                b1[ni][0] = __float_as_uint(B1[ni * 8 * LD1 + k0]);
                b1[ni][1] = __float_as_uint(B1[ni * 8 * LD1 + k0 + 4]);
                b2[ni][0] = __float_as_uint(B2[ni * 8 * LD1 + k0]);
                b2[ni][1] = __float_as_uint(B2[ni * 8 * LD1 + k0 + 4]);
            }
#pragma unroll
            for (int ni = 0; ni < 2; ni++) {
                mma8(q[ni], ay, b0[ni]);
#pragma unroll
                for (int i = 0; i < 3; i++) {
                    mma8(u[i][ni],  ag[i], b1[ni]);
                    mma8(vv[i][ni], ag[i], b2[ni]);
                }
            }
        }

        int r0 = m0 + ar, r1 = m0 + ar + 8;
        float rx0 = s_rs[r0 * 4], ry0 = s_rs[r0 * 4 + 1], rz0 = s_rs[r0 * 4 + 2];
        float rx1 = s_rs[r1 * 4], ry1 = s_rs[r1 * 4 + 1], rz1 = s_rs[r1 * 4 + 2];
        int sn0 = s_src[r0], sn1 = s_src[r1];

#pragma unroll
        for (int ni = 0; ni < 2; ni++)
#pragma unroll
            for (int cc = 0; cc < 2; cc++) {
                int col = n0 + ni * 8 + 2 * ac + cc;
                if (sn0 >= 0) {
                    float qq = q[ni][cc];
                    float px = qq * rx0 + u[0][ni][cc] + vv[1][ni][cc] * rz0 - vv[2][ni][cc] * ry0;
                    float py = qq * ry0 + u[1][ni][cc] + vv[2][ni][cc] * rx0 - vv[0][ni][cc] * rz0;
                    float pz = qq * rz0 + u[2][ni][cc] + vv[0][ni][cc] * ry0 - vv[1][ni][cc] * rx0;
                    float* p = Bv + (size_t)sn0 * 96 + col * 3;
                    red1(p,     0.1f * px);
                    red1(p + 1, 0.1f * py);
                    red1(p + 2, 0.1f * pz);
                }
                if (sn1 >= 0) {
                    int j = cc + 2;
                    float qq = q[ni][j];
                    float px = qq * rx1 + u[0][ni][j] + vv[1][ni][j] * rz1 - vv[2][ni][j] * ry1;
                    float py = qq * ry1 + u[1][ni][j] + vv[2][ni][j] * rx1 - vv[0][ni][j] * rz1;
                    float pz = qq * rz1 + u[2][ni][j] + vv[0][ni][j] * ry1 - vv[1][ni][j] * rx1;
                    float* p = Bv + (size_t)sn1 * 96 + col * 3;
                    red1(p,     0.1f * px);
                    red1(p + 1, 0.1f * py);
                    red1(p + 2, 0.1f * pz);
                }
            }
    }
}

// ---------------- K2: tf32 mma.sync fused MLP chain + B_a scatter ----------------
__global__ void __launch_bounds__(256)
k_edge2(const float* __restrict__ bm1, const float* __restrict__ bm2,
        const int* __restrict__ src, float* __restrict__ Ba)
{
    extern __shared__ __align__(16) float sm[];
    float* As = sm;
    float* W0 = sm + WBLOB;
    float* W1 = sm + 2 * WBLOB;
    __shared__ float s_b1[128], s_b2[128];
    __shared__ int s_src[128];

    int tid = threadIdx.x, wid = tid >> 5, lane = tid & 31;
    int m0 = (wid >> 1) * 32, n0 = (wid & 1) * 64;
    int ar = lane >> 2, ac = lane & 3;
    int e0 = blockIdx.x * 128;

    if (tid < 128) {
        s_b1[tid] = bm1[tid];
        s_b2[tid] = bm2[tid];
        int e = e0 + tid;
        s_src[tid] = (e < NE) ? src[e] : -1;
    }

    uint32_t uA  = smem_u32(As);
    uint32_t uW0 = smem_u32(W0);
    uint32_t uW1 = smem_u32(W1);

    for (int idx = tid; idx < 2048; idx += 256) {
        int m = idx >> 4, c = idx & 15;
        cp16(uA + (uint32_t)(m * LDW * 4 + c * 16),
             (const char*)(g_Y + (size_t)(e0 + m) * 64) + c * 16);
    }
    for (int idx = tid; idx < 4224; idx += 256)
        cp16(uW0 + (uint32_t)(idx * 16), (const char*)g_Wb[0] + idx * 16);
    CP_COMMIT();
    for (int idx = tid; idx < 4224; idx += 256)
        cp16(uW1 + (uint32_t)(idx * 16), (const char*)g_Wb[1] + idx * 16);
    CP_COMMIT();
    CP_WAIT(1);
    __syncthreads();

    float acc[2][8][4];
#pragma unroll
    for (int mi = 0; mi < 2; mi++)
#pragma unroll
        for (int ni = 0; ni < 8; ni++)
#pragma unroll
            for (int j = 0; j < 4; j++) acc[mi][ni][j] = 0.f;

    gemm_ws(As, W0, 8, m0, n0, lane, acc);

    float psi[2][8][4];
#pragma unroll
    for (int mi = 0; mi < 2; mi++)
#pragma unroll
        for (int ni = 0; ni < 8; ni++)
#pragma unroll
            for (int j = 0; j < 4; j++) psi[mi][ni][j] = acc[mi][ni][j];

    __syncthreads();
#pragma unroll
    for (int mi = 0; mi < 2; mi++)
#pragma unroll
        for (int ni = 0; ni < 8; ni++) {
            int row = m0 + mi * 16 + ar;
            int col = n0 + ni * 8 + 2 * ac;
            float2 v0 = make_float2(tf32f(acc[mi][ni][0]), tf32f(acc[mi][ni][1]));
            float2 v1 = make_float2(tf32f(acc[mi][ni][2]), tf32f(acc[mi][ni][3]));
            *(float2*)(As + row * LDW + col) = v0;
            *(float2*)(As + (row + 8) * LDW + col) = v1;
        }
    for (int idx = tid; idx < 4224; idx += 256)
        cp16(uW0 + (uint32_t)(idx * 16), (const char*)g_Wb[2] + idx * 16);
    CP_COMMIT();
    CP_WAIT(1);
    __syncthreads();

#pragma unroll
    for (int mi = 0; mi < 2; mi++)
#pragma unroll
        for (int ni = 0; ni < 8; ni++)
#pragma unroll
            for (int j = 0; j < 4; j++) acc[mi][ni][j] = 0.f;
    gemm_ws(As, W1, 16, m0, n0, lane, acc);
    __syncthreads();
#pragma unroll
    for (int mi = 0; mi < 2; mi++)
#pragma unroll
        for (int ni = 0; ni < 8; ni++) {
            int row = m0 + mi * 16 + ar;
            int col = n0 + ni * 8 + 2 * ac;
            float2 bb = *(const float2*)(s_b1 + col);
            float2 v0 = make_float2(tf32f(lk(acc[mi][ni][0] + bb.x)), tf32f(lk(acc[mi][ni][1] + bb.y)));
            float2 v1 = make_float2(tf32f(lk(acc[mi][ni][2] + bb.x)), tf32f(lk(acc[mi][ni][3] + bb.y)));
            *(float2*)(As + row * LDW + col) = v0;
            *(float2*)(As + (row + 8) * LDW + col) = v1;
        }
    for (int idx = tid; idx < 4224; idx += 256)
        cp16(uW1 + (uint32_t)(idx * 16), (const char*)g_Wb[3] + idx * 16);
    CP_COMMIT();
    CP_WAIT(1);
    __syncthreads();

#pragma unroll
    for (int mi = 0; mi < 2; mi++)
#pragma unroll
        for (int ni = 0; ni < 8; ni++)
#pragma unroll
            for (int j = 0; j < 4; j++) acc[mi][ni][j] = 0.f;
    gemm_ws(As, W0, 16, m0, n0, lane, acc);
    __syncthreads();
#pragma unroll
    for (int mi = 0; mi < 2; mi++)
#pragma unroll
        for (int ni = 0; ni < 8; ni++) {
            int row = m0 + mi * 16 + ar;
            int col = n0 + ni * 8 + 2 * ac;
            float2 bb = *(const float2*)(s_b2 + col);
            float2 v0 = make_float2(tf32f(lk(acc[mi][ni][0] + bb.x)), tf32f(lk(acc[mi][ni][1] + bb.y)));
            float2 v1 = make_float2(tf32f(lk(acc[mi][ni][2] + bb.x)), tf32f(lk(acc[mi][ni][3] + bb.y)));
            *(float2*)(As + row * LDW + col) = v0;
            *(float2*)(As + (row + 8) * LDW + col) = v1;
        }
    CP_WAIT(0);
    __syncthreads();

#pragma unroll
    for (int mi = 0; mi < 2; mi++)
#pragma unroll
        for (int ni = 0; ni < 8; ni++)
#pragma unroll
            for (int j = 0; j < 4; j++) acc[mi][ni][j] = psi[mi][ni][j];
    gemm_ws(As, W1, 16, m0, n0, lane, acc);

#pragma unroll
    for (int mi = 0; mi < 2; mi++) {
        int row = m0 + mi * 16 + ar;
        int sn0 = s_src[row];
        int sn1 = s_src[row + 8];
#pragma unroll
        for (int ni = 0; ni < 8; ni++) {
            int col = n0 + ni * 8 + 2 * ac;
            if (sn0 >= 0)
                red2(Ba + (size_t)sn0 * 128 + col,
                     0.1f * acc[mi][ni][0], 0.1f * acc[mi][ni][1]);
            if (sn1 >= 0)
                red2(Ba + (size_t)sn1 * 128 + col,
                     0.1f * acc[mi][ni][2], 0.1f * acc[mi][ni][3]);
        }
    }
}

// ---------------- launch ----------------
extern "C" void kernel_launch(void* const* d_in, const int* in_sizes, int n_in,
                              void* d_out, int out_size)
{
    const float* x_a   = (const float*)d_in[0];
    const float* x_v   = (const float*)d_in[1];
    const float* r_ij  = (const float*)d_in[2];
    const int*   src   = (const int*)  d_in[3];
    const int*   dst   = (const int*)  d_in[4];
    const float* WL0   = (const float*)d_in[5];
    const float* WL1   = (const float*)d_in[6];
    const float* Wenc  = (const float*)d_in[7];
    const float* benc  = (const float*)d_in[8];
    const float* Wy000 = (const float*)d_in[9];
    const float* Wy110 = (const float*)d_in[10];
    const float* Wy011 = (const float*)d_in[11];
    const float* Wy101 = (const float*)d_in[12];
    const float* Wy111 = (const float*)d_in[13];
    const float* Wm1   = (const float*)d_in[14];
    const float* bm1   = (const float*)d_in[15];
    const float* Wm2   = (const float*)d_in[16];
    const float* bm2   = (const float*)d_in[17];
    const float* Wm3   = (const float*)d_in[18];
    float* out = (float*)d_out;

    cudaMemsetAsync(out, 0, (size_t)out_size * sizeof(float), 0);

    k_prep<<<(WBLOB + 255) / 256, 256>>>(Wy000, Wy110, Wm1, Wm2, Wm3);

    k_node<<<(NN + 7) / 8, 256>>>(x_a, x_v, WL0, WL1);

    int smem1 = (4 * 128 * LD1 + 3 * 32 * LD1 + 128 * 4) * (int)sizeof(float); // 89,600 B
    cudaFuncSetAttribute(k_edge1, cudaFuncAttributeMaxDynamicSharedMemorySize, smem1);
    k_edge1<<<(NE + 127) / 128, 256, smem1>>>(r_ij, src, dst, Wenc, benc,
                                              Wy011, Wy101, Wy111,
                                              out + (size_t)NN * 128);

    int smem2 = 3 * WBLOB * (int)sizeof(float);   // 202,752 B
    cudaFuncSetAttribute(k_edge2, cudaFuncAttributeMaxDynamicSharedMemorySize, smem2);
    k_edge2<<<(NE + 127) / 128, 256, smem2>>>(bm1, bm2, src, out);
}

// round 5
// speedup vs baseline: 3.7279x; 1.0230x over previous
#include <cuda_runtime.h>
#include <cstdint>
#include <math.h>

#define NN 50000
#define NE 500000
#define NE_PAD 500096           // 3907 * 128
#define LDW 132                 // k_edge2 smem leading dim
#define WBLOB (128 * LDW)
#define LD1 36                  // k_edge1 smem leading dim

// ---------------- scratch (device globals: allocation-free) ----------------
__device__ float g_L0[NN * 32];
__device__ float g_L1[NN * 3 * 32];
__device__ __align__(16) float g_Y[(size_t)NE_PAD * 64];  // tf32 [e][64]
__device__ __align__(16) float g_Wb[4][WBLOB];            // pre-swizzled tf32 weights

// ================= helpers =================
__device__ __forceinline__ uint32_t smem_u32(const void* p) {
    uint32_t a;
    asm("{ .reg .u64 t; cvta.to.shared.u64 t, %1; cvt.u32.u64 %0, t; }" : "=r"(a) : "l"(p));
    return a;
}
__device__ __forceinline__ uint32_t cvt_tf32(float f) {
    uint32_t r; asm("cvt.rna.tf32.f32 %0, %1;" : "=r"(r) : "f"(f)); return r;
}
__device__ __forceinline__ float tf32f(float f) { return __uint_as_float(cvt_tf32(f)); }

__device__ __forceinline__ void cp16(uint32_t d, const void* s) {
    asm volatile("cp.async.cg.shared.global [%0], [%1], 16;" :: "r"(d), "l"(s) : "memory");
}
#define CP_COMMIT() asm volatile("cp.async.commit_group;" ::: "memory")
#define CP_WAIT(n)  asm volatile("cp.async.wait_group %0;" :: "n"(n) : "memory")

__device__ __forceinline__ void red2(float* p, float a, float b) {
    asm volatile("red.global.add.v2.f32 [%0], {%1, %2};" :: "l"(p), "f"(a), "f"(b) : "memory");
}
__device__ __forceinline__ void red4(float* p, float a, float b, float c, float d) {
    asm volatile("red.global.add.v4.f32 [%0], {%1, %2, %3, %4};"
                 :: "l"(p), "f"(a), "f"(b), "f"(c), "f"(d) : "memory");
}
__device__ __forceinline__ float lk(float t) { return (t >= 0.f) ? t : 0.1f * t; }

__device__ __forceinline__ void mma8(float* c, const uint32_t* a, const uint32_t* b) {
    asm volatile("mma.sync.aligned.m16n8k8.row.col.f32.tf32.tf32.f32 "
        "{%0,%1,%2,%3}, {%4,%5,%6,%7}, {%8,%9}, {%0,%1,%2,%3};"
        : "+f"(c[0]), "+f"(c[1]), "+f"(c[2]), "+f"(c[3])
        : "r"(a[0]), "r"(a[1]), "r"(a[2]), "r"(a[3]), "r"(b[0]), "r"(b[1]));
}

// warp tile 16x64 (1 m-frag x 8 n-frags), 16 warps cover 128x128.
__device__ __forceinline__ void gemm_ws16(const float* __restrict__ As,
                                          const float* __restrict__ Ws,
                                          int ksteps, int m0, int n0, int lane,
                                          float acc[8][4])
{
    int ar = lane >> 2, ac = lane & 3;
    const float* Ap = As + (m0 + ar) * LDW + ac;
    const float* Wp = Ws + (n0 + ar) * LDW + ac;
#pragma unroll 2
    for (int ks = 0; ks < ksteps; ks++) {
        int k0 = ks * 8;
        uint32_t a[4], b[8][2];
        a[0] = __float_as_uint(Ap[k0]);
        a[1] = __float_as_uint(Ap[k0 + 8 * LDW]);
        a[2] = __float_as_uint(Ap[k0 + 4]);
        a[3] = __float_as_uint(Ap[k0 + 8 * LDW + 4]);
#pragma unroll
        for (int ni = 0; ni < 8; ni++) {
            const float* q = Wp + ni * 8 * LDW + k0;
            b[ni][0] = __float_as_uint(q[0]);
            b[ni][1] = __float_as_uint(q[4]);
        }
#pragma unroll
        for (int ni = 0; ni < 8; ni++) mma8(acc[ni], a, b[ni]);
    }
}

// ---------------- K_prep ----------------
__global__ void k_prep(const float* __restrict__ Wy000, const float* __restrict__ Wy110,
                       const float* __restrict__ Wm1, const float* __restrict__ Wm2,
                       const float* __restrict__ Wm3)
{
    int idx = blockIdx.x * 256 + threadIdx.x;
    if (idx >= WBLOB) return;
    int n = idx / LDW, k = idx % LDW;
    float w0 = 0.f, w1 = 0.f, w2 = 0.f, w3 = 0.f;
    if (k < 64)  w0 = (k < 32) ? Wy000[n * 32 + k] : Wy110[n * 32 + (k - 32)];
    if (k < 128) { w1 = Wm1[n * 128 + k]; w2 = Wm2[n * 128 + k]; w3 = Wm3[n * 128 + k]; }
    g_Wb[0][idx] = tf32f(w0);
    g_Wb[1][idx] = tf32f(w1);
    g_Wb[2][idx] = tf32f(w2);
    g_Wb[3][idx] = tf32f(w3);
}

// ---------------- K0: node projections ----------------
__global__ void __launch_bounds__(256) k_node(
    const float* __restrict__ xa, const float* __restrict__ xv,
    const float* __restrict__ WL0, const float* __restrict__ WL1)
{
    __shared__ float sW0t[32][132];
    __shared__ float sW1t[32][33];
    __shared__ float sxa[8][128];
    __shared__ float sxv[8][96];
    int tid = threadIdx.x;
    for (int idx = tid; idx < 4096; idx += 256) {
        int c = idx >> 7, d = idx & 127;
        sW0t[c][d] = WL0[idx];
    }
    for (int idx = tid; idx < 1024; idx += 256) {
        int c = idx >> 5, d = idx & 31;
        sW1t[c][d] = WL1[idx];
    }
    int w = tid >> 5, lane = tid & 31;
    int n = blockIdx.x * 8 + w;
    if (n < NN) {
        for (int j = lane; j < 128; j += 32) sxa[w][j] = xa[n * 128 + j];
        for (int j = lane; j < 96;  j += 32) sxv[w][j] = xv[n * 96 + j];
    }
    __syncthreads();
    if (n >= NN) return;

    const float4* wv = (const float4*)&sW0t[lane][0];
    const float4* x4 = (const float4*)&sxa[w][0];
    float acc = 0.f;
#pragma unroll 8
    for (int d4 = 0; d4 < 32; d4++) {
        float4 a = x4[d4], b = wv[d4];
        acc += a.x * b.x + a.y * b.y + a.z * b.z + a.w * b.w;
    }
    g_L0[n * 32 + lane] = acc;

    float a0 = 0.f, a1 = 0.f, a2 = 0.f;
#pragma unroll 8
    for (int d = 0; d < 32; d++) {
        float wd = sW1t[lane][d];
        a0 += sxv[w][3 * d]     * wd;
        a1 += sxv[w][3 * d + 1] * wd;
        a2 += sxv[w][3 * d + 2] * wd;
    }
    g_L1[n * 96 +      lane] = a0;
    g_L1[n * 96 + 32 + lane] = a1;
    g_L1[n * 96 + 64 + lane] = a2;
}

// ---------------- K1: edge light path, tensor-core psi_v, red4 scatter ----------------
__global__ void __launch_bounds__(256, 2) k_edge1(
    const float* __restrict__ rij, const int* __restrict__ src,
    const int* __restrict__ dst,
    const float* __restrict__ Wenc, const float* __restrict__ benc,
    const float* __restrict__ W011, const float* __restrict__ W101,
    const float* __restrict__ W111,
    float* __restrict__ Bv)
{
    extern __shared__ __align__(16) float s1[];
    float* sY0 = s1;                   // 128 x LD1
    float* sGx = sY0 + 128 * LD1;
    float* sGy = sGx + 128 * LD1;
    float* sGz = sGy + 128 * LD1;
    float* sW  = sGz + 128 * LD1;      // 3 x 32 x LD1
    float* s_rs = sW + 3 * 32 * LD1;   // 128 x 4
    float* sP  = s1;                   // reuse after GEMMs: 128 x 96
    __shared__ float sWe[8 * 32];
    __shared__ float sbe[32];
    __shared__ int   s_src[128];

    int tid = threadIdx.x, wid = tid >> 5, lane = tid & 31;
    int e0 = blockIdx.x * 128;

    for (int idx = tid; idx < 256; idx += 256) {
        int c = idx >> 3, k = idx & 7;
        sWe[k * 32 + c] = Wenc[idx];
    }
    if (tid < 32) sbe[tid] = benc[tid];
    for (int idx = tid; idx < 3 * 1024; idx += 256) {
        int wi = idx >> 10, r = idx & 1023;
        int d = r >> 5, c = r & 31;
        const float* Wsrc = (wi == 0) ? W011 : ((wi == 1) ? W101 : W111);
        sW[wi * 32 * LD1 + d * LD1 + c] = tf32f(Wsrc[d * 32 + c]);
    }
    if (tid < 128) s_src[tid] = (e0 + tid < NE) ? src[e0 + tid] : -1;
    __syncthreads();

    // ---- phase 1: per-edge elementwise (warp per edge) ----
    for (int it = 0; it < 16; it++) {
        int el = it * 8 + wid;
        int e  = e0 + el;
        float y0 = 0.f, gx = 0.f, gy = 0.f, gz = 0.f;
        float sx = 0.f, sy = 0.f, sz = 0.f;
        if (e < NE) {
            float rx = rij[3 * e], ry = rij[3 * e + 1], rz = rij[3 * e + 2];
            float rn = sqrtf(rx * rx + ry * ry + rz * rz);
            float ek = 0.f;
            if (lane < 8) {
                float t = (rn - (5.0f / 7.0f) * (float)lane) * 1.6f;
                ek = expf(-t * t);
            }
            float sq_l = 0.f;
            if (lane == 8) {
                float n14 = 1.4f * rn;
                sq_l = tanhf(n14) / fmaxf(n14, 1e-6f);
            }
            float sq = __shfl_sync(0xffffffffu, sq_l, 8);
            sx = 1.4f * rx * sq; sy = 1.4f * ry * sq; sz = 1.4f * rz * sq;

            float g = sbe[lane];
#pragma unroll
            for (int k = 0; k < 8; k++)
                g += __shfl_sync(0xffffffffu, ek, k) * sWe[k * 32 + lane];

            int dn = dst[e];
            float la  = g_L0[dn * 32 + lane];
            float lvx = g_L1[dn * 96 +      lane];
            float lvy = g_L1[dn * 96 + 32 + lane];
            float lvz = g_L1[dn * 96 + 64 + lane];

            y0 = tf32f(la * g);
            gx = tf32f(g * lvx); gy = tf32f(g * lvy); gz = tf32f(g * lvz);

            g_Y[(size_t)e * 64 + lane]      = y0;
            g_Y[(size_t)e * 64 + 32 + lane] = tf32f((lvx * sx + lvy * sy + lvz * sz) * g);
        }
        sY0[el * LD1 + lane] = y0;
        sGx[el * LD1 + lane] = gx;
        sGy[el * LD1 + lane] = gy;
        sGz[el * LD1 + lane] = gz;
        if (lane == 0) {
            s_rs[el * 4]     = sx;
            s_rs[el * 4 + 1] = sy;
            s_rs[el * 4 + 2] = sz;
        }
    }
    __syncthreads();

    // ---- phase 2: 7 GEMMs per pass (q, u_xyz, v_xyz), results to registers ----
    int cg = wid & 1, rg = wid >> 1;
    int n0 = cg * 16;
    int ar = lane >> 2, ac = lane & 3;

    float P[2][2][4][3];    // [pass][ni][j][xyz] — 0.1*psi_v

#pragma unroll
    for (int pass = 0; pass < 2; pass++) {
        int m0 = pass * 64 + rg * 16;
        float q[2][4], u[3][2][4], vv[3][2][4];
#pragma unroll
        for (int ni = 0; ni < 2; ni++)
#pragma unroll
            for (int j = 0; j < 4; j++) {
                q[ni][j] = 0.f;
#pragma unroll
                for (int i = 0; i < 3; i++) { u[i][ni][j] = 0.f; vv[i][ni][j] = 0.f; }
            }

        const float* Ay  = sY0 + (m0 + ar) * LD1 + ac;
        const float* Agx = sGx + (m0 + ar) * LD1 + ac;
        const float* Agy = sGy + (m0 + ar) * LD1 + ac;
        const float* Agz = sGz + (m0 + ar) * LD1 + ac;
        const float* B0 = sW + 0 * 32 * LD1 + (n0 + ar) * LD1 + ac;
        const float* B1 = sW + 1 * 32 * LD1 + (n0 + ar) * LD1 + ac;
        const float* B2 = sW + 2 * 32 * LD1 + (n0 + ar) * LD1 + ac;

#pragma unroll
        for (int ks = 0; ks < 4; ks++) {
            int k0 = ks * 8;
            uint32_t ay[4], ag[3][4];
            ay[0] = __float_as_uint(Ay[k0]);
            ay[1] = __float_as_uint(Ay[k0 + 8 * LD1]);
            ay[2] = __float_as_uint(Ay[k0 + 4]);
            ay[3] = __float_as_uint(Ay[k0 + 8 * LD1 + 4]);
            const float* Ags[3] = {Agx, Agy, Agz};
#pragma unroll
            for (int i = 0; i < 3; i++) {
                ag[i][0] = __float_as_uint(Ags[i][k0]);
                ag[i][1] = __float_as_uint(Ags[i][k0 + 8 * LD1]);
                ag[i][2] = __float_as_uint(Ags[i][k0 + 4]);
                ag[i][3] = __float_as_uint(Ags[i][k0 + 8 * LD1 + 4]);
            }
            uint32_t b0[2][2], b1[2][2], b2[2][2];
#pragma unroll
            for (int ni = 0; ni < 2; ni++) {
                b0[ni][0] = __float_as_uint(B0[ni * 8 * LD1 + k0]);
                b0[ni][1] = __float_as_uint(B0[ni * 8 * LD1 + k0 + 4]);
                b1[ni][0] = __float_as_uint(B1[ni * 8 * LD1 + k0]);
                b1[ni][1] = __float_as_uint(B1[ni * 8 * LD1 + k0 + 4]);
                b2[ni][0] = __float_as_uint(B2[ni * 8 * LD1 + k0]);
                b2[ni][1] = __float_as_uint(B2[ni * 8 * LD1 + k0 + 4]);
            }
#pragma unroll
            for (int ni = 0; ni < 2; ni++) {
                mma8(q[ni], ay, b0[ni]);
#pragma unroll
                for (int i = 0; i < 3; i++) {
                    mma8(u[i][ni],  ag[i], b1[ni]);
                    mma8(vv[i][ni], ag[i], b2[ni]);
                }
            }
        }

        int r0 = m0 + ar, r1 = r0 + 8;
        float rx0 = s_rs[r0 * 4], ry0 = s_rs[r0 * 4 + 1], rz0 = s_rs[r0 * 4 + 2];
        float rx1 = s_rs[r1 * 4], ry1 = s_rs[r1 * 4 + 1], rz1 = s_rs[r1 * 4 + 2];
#pragma unroll
        for (int ni = 0; ni < 2; ni++)
#pragma unroll
            for (int j = 0; j < 4; j++) {
                float rx = (j < 2) ? rx0 : rx1;
                float ry = (j < 2) ? ry0 : ry1;
                float rz = (j < 2) ? rz0 : rz1;
                float qq = q[ni][j];
                P[pass][ni][j][0] = 0.1f * (qq * rx + u[0][ni][j] + vv[1][ni][j] * rz - vv[2][ni][j] * ry);
                P[pass][ni][j][1] = 0.1f * (qq * ry + u[1][ni][j] + vv[2][ni][j] * rx - vv[0][ni][j] * rz);
                P[pass][ni][j][2] = 0.1f * (qq * rz + u[2][ni][j] + vv[0][ni][j] * ry - vv[1][ni][j] * rx);
            }
    }
    __syncthreads();   // all GEMM smem reads done; safe to overwrite with sP

    // ---- transpose to sP[128][96] ----
#pragma unroll
    for (int pass = 0; pass < 2; pass++)
#pragma unroll
        for (int ni = 0; ni < 2; ni++)
#pragma unroll
            for (int j = 0; j < 4; j++) {
                int row = pass * 64 + rg * 16 + ar + ((j >= 2) ? 8 : 0);
                int col = n0 + ni * 8 + 2 * ac + (j & 1);
                float* p = sP + row * 96 + col * 3;
                p[0] = P[pass][ni][j][0];
                p[1] = P[pass][ni][j][1];
                p[2] = P[pass][ni][j][2];
            }
    __syncthreads();

    // ---- vector scatter: 24 red4 per edge ----
    const float4* sP4 = (const float4*)sP;
    for (int it = 0; it < 16; it++) {
        int el = it * 8 + wid;
        int sn = s_src[el];
        if (sn >= 0 && lane < 24) {
            float4 v = sP4[el * 24 + lane];
            red4(Bv + (size_t)sn * 96 + lane * 4, v.x, v.y, v.z, v.w);
        }
    }
}

// ---------------- K2: tf32 mma.sync fused MLP chain (512 thr) ----------------
__global__ void __launch_bounds__(512)
k_edge2(const float* __restrict__ bm1, const float* __restrict__ bm2,
        const int* __restrict__ src, float* __restrict__ Ba)
{
    extern __shared__ __align__(16) float sm[];
    float* As = sm;
    float* W0 = sm + WBLOB;
    float* W1 = sm + 2 * WBLOB;
    __shared__ float s_b1[128], s_b2[128];
    __shared__ int s_src[128];

    int tid = threadIdx.x, wid = tid >> 5, lane = tid & 31;
    int m0 = (wid >> 1) * 16, n0 = (wid & 1) * 64;
    int ar = lane >> 2, ac = lane & 3;
    int e0 = blockIdx.x * 128;

    if (tid < 128) {
        s_b1[tid] = bm1[tid];
        s_b2[tid] = bm2[tid];
        int e = e0 + tid;
        s_src[tid] = (e < NE) ? src[e] : -1;
    }

    uint32_t uA  = smem_u32(As);
    uint32_t uW0 = smem_u32(W0);
    uint32_t uW1 = smem_u32(W1);

    for (int idx = tid; idx < 2048; idx += 512) {
        int m = idx >> 4, c = idx & 15;
        cp16(uA + (uint32_t)(m * LDW * 4 + c * 16),
             (const char*)(g_Y + (size_t)(e0 + m) * 64) + c * 16);
    }
    for (int idx = tid; idx < 4224; idx += 512)
        cp16(uW0 + (uint32_t)(idx * 16), (const char*)g_Wb[0] + idx * 16);
    CP_COMMIT();
    for (int idx = tid; idx < 4224; idx += 512)
        cp16(uW1 + (uint32_t)(idx * 16), (const char*)g_Wb[1] + idx * 16);
    CP_COMMIT();
    CP_WAIT(1);
    __syncthreads();

    float acc[8][4], psi[8][4];
#pragma unroll
    for (int ni = 0; ni < 8; ni++)
#pragma unroll
        for (int j = 0; j < 4; j++) acc[ni][j] = 0.f;

    // ---- GEMM1: psi0 = Y @ Wcat^T (K=64) ----
    gemm_ws16(As, W0, 8, m0, n0, lane, acc);
#pragma unroll
    for (int ni = 0; ni < 8; ni++)
#pragma unroll
        for (int j = 0; j < 4; j++) psi[ni][j] = acc[ni][j];

    __syncthreads();
#pragma unroll
    for (int ni = 0; ni < 8; ni++) {
        int row = m0 + ar;
        int col = n0 + ni * 8 + 2 * ac;
        *(float2*)(As + row * LDW + col) = make_float2(tf32f(acc[ni][0]), tf32f(acc[ni][1]));
        *(float2*)(As + (row + 8) * LDW + col) = make_float2(tf32f(acc[ni][2]), tf32f(acc[ni][3]));
    }
    for (int idx = tid; idx < 4224; idx += 512)
        cp16(uW0 + (uint32_t)(idx * 16), (const char*)g_Wb[2] + idx * 16);
    CP_COMMIT();
    CP_WAIT(1);
    __syncthreads();

    // ---- GEMM2: h1 = leaky(psi0 @ Wm1^T + b1) ----
#pragma unroll
    for (int ni = 0; ni < 8; ni++)
#pragma unroll
        for (int j = 0; j < 4; j++) acc[ni][j] = 0.f;
    gemm_ws16(As, W1, 16, m0, n0, lane, acc);
    __syncthreads();
#pragma unroll
    for (int ni = 0; ni < 8; ni++) {
        int row = m0 + ar;
        int col = n0 + ni * 8 + 2 * ac;
        float2 bb = *(const float2*)(s_b1 + col);
        *(float2*)(As + row * LDW + col) =
            make_float2(tf32f(lk(acc[ni][0] + bb.x)), tf32f(lk(acc[ni][1] + bb.y)));
        *(float2*)(As + (row + 8) * LDW + col) =
            make_float2(tf32f(lk(acc[ni][2] + bb.x)), tf32f(lk(acc[ni][3] + bb.y)));
    }
    for (int idx = tid; idx < 4224; idx += 512)
        cp16(uW1 + (uint32_t)(idx * 16), (const char*)g_Wb[3] + idx * 16);
    CP_COMMIT();
    CP_WAIT(1);
    __syncthreads();

    // ---- GEMM3: h2 = leaky(h1 @ Wm2^T + b2) ----
#pragma unroll
    for (int ni = 0; ni < 8; ni++)
#pragma unroll
        for (int j = 0; j < 4; j++) acc[ni][j] = 0.f;
    gemm_ws16(As, W0, 16, m0, n0, lane, acc);
    __syncthreads();
#pragma unroll
    for (int ni = 0; ni < 8; ni++) {
        int row = m0 + ar;
        int col = n0 + ni * 8 + 2 * ac;
        float2 bb = *(const float2*)(s_b2 + col);
        *(float2*)(As + row * LDW + col) =
            make_float2(tf32f(lk(acc[ni][0] + bb.x)), tf32f(lk(acc[ni][1] + bb.y)));
        *(float2*)(As + (row + 8) * LDW + col) =
            make_float2(tf32f(lk(acc[ni][2] + bb.x)), tf32f(lk(acc[ni][3] + bb.y)));
    }
    CP_WAIT(0);
    __syncthreads();

    // ---- GEMM4: psi_a = psi0 + h2 @ Wm3^T ; scatter ----
#pragma unroll
    for (int ni = 0; ni < 8; ni++)
#pragma unroll
        for (int j = 0; j < 4; j++) acc[ni][j] = psi[ni][j];
    gemm_ws16(As, W1, 16, m0, n0, lane, acc);

    {
        int row = m0 + ar;
        int sn0 = s_src[row];
        int sn1 = s_src[row + 8];
#pragma unroll
        for (int ni = 0; ni < 8; ni++) {
            int col = n0 + ni * 8 + 2 * ac;
            if (sn0 >= 0)
                red2(Ba + (size_t)sn0 * 128 + col, 0.1f * acc[ni][0], 0.1f * acc[ni][1]);
            if (sn1 >= 0)
                red2(Ba + (size_t)sn1 * 128 + col, 0.1f * acc[ni][2], 0.1f * acc[ni][3]);
        }
    }
}

// ---------------- launch ----------------
extern "C" void kernel_launch(void* const* d_in, const int* in_sizes, int n_in,
                              void* d_out, int out_size)
{
    const float* x_a   = (const float*)d_in[0];
    const float* x_v   = (const float*)d_in[1];
    const float* r_ij  = (const float*)d_in[2];
    const int*   src   = (const int*)  d_in[3];
    const int*   dst   = (const int*)  d_in[4];
    const float* WL0   = (const float*)d_in[5];
    const float* WL1   = (const float*)d_in[6];
    const float* Wenc  = (const float*)d_in[7];
    const float* benc  = (const float*)d_in[8];
    const float* Wy000 = (const float*)d_in[9];
    const float* Wy110 = (const float*)d_in[10];
    const float* Wy011 = (const float*)d_in[11];
    const float* Wy101 = (const float*)d_in[12];
    const float* Wy111 = (const float*)d_in[13];
    const float* Wm1   = (const float*)d_in[14];
    const float* bm1   = (const float*)d_in[15];
    const float* Wm2   = (const float*)d_in[16];
    const float* bm2   = (const float*)d_in[17];
    const float* Wm3   = (const float*)d_in[18];
    float* out = (float*)d_out;

    cudaMemsetAsync(out, 0, (size_t)out_size * sizeof(float), 0);

    k_prep<<<(WBLOB + 255) / 256, 256>>>(Wy000, Wy110, Wm1, Wm2, Wm3);

    k_node<<<(NN + 7) / 8, 256>>>(x_a, x_v, WL0, WL1);

    int smem1 = (4 * 128 * LD1 + 3 * 32 * LD1 + 128 * 4) * (int)sizeof(float); // 89,600 B
    cudaFuncSetAttribute(k_edge1, cudaFuncAttributeMaxDynamicSharedMemorySize, smem1);
    k_edge1<<<(NE + 127) / 128, 256, smem1>>>(r_ij, src, dst, Wenc, benc,
                                              Wy011, Wy101, Wy111,
                                              out + (size_t)NN * 128);

    int smem2 = 3 * WBLOB * (int)sizeof(float);   // 202,752 B
    cudaFuncSetAttribute(k_edge2, cudaFuncAttributeMaxDynamicSharedMemorySize, smem2);
    k_edge2<<<(NE + 127) / 128, 512, smem2>>>(bm1, bm2, src, out);
}

// round 6
// speedup vs baseline: 3.9137x; 1.0498x over previous
#include <cuda_runtime.h>
#include <cstdint>
#include <math.h>

#define NN 50000
#define NE 500000
#define NE_PAD 500096           // 3907 * 128
#define EA_END 249984           // 1953 * 128 — chunk A end
#define LDW 132                 // k_edge2 smem leading dim
#define WBLOB (128 * LDW)
#define LD1 36                  // k_edge1 smem leading dim

// ---------------- scratch (device globals: allocation-free) ----------------
__device__ float g_L0[NN * 32];
__device__ float g_L1[NN * 3 * 32];
__device__ __align__(16) float g_Y[(size_t)NE_PAD * 64];  // tf32 [e][64]
__device__ __align__(16) float g_Wb[4][WBLOB];            // pre-swizzled tf32 weights

// ================= helpers =================
__device__ __forceinline__ uint32_t smem_u32(const void* p) {
    uint32_t a;
    asm("{ .reg .u64 t; cvta.to.shared.u64 t, %1; cvt.u32.u64 %0, t; }" : "=r"(a) : "l"(p));
    return a;
}
__device__ __forceinline__ uint32_t cvt_tf32(float f) {
    uint32_t r; asm("cvt.rna.tf32.f32 %0, %1;" : "=r"(r) : "f"(f)); return r;
}
__device__ __forceinline__ float tf32f(float f) { return __uint_as_float(cvt_tf32(f)); }

__device__ __forceinline__ void cp16(uint32_t d, const void* s) {
    asm volatile("cp.async.cg.shared.global [%0], [%1], 16;" :: "r"(d), "l"(s) : "memory");
}
#define CP_COMMIT() asm volatile("cp.async.commit_group;" ::: "memory")
#define CP_WAIT(n)  asm volatile("cp.async.wait_group %0;" :: "n"(n) : "memory")

__device__ __forceinline__ void red2(float* p, float a, float b) {
    asm volatile("red.global.add.v2.f32 [%0], {%1, %2};" :: "l"(p), "f"(a), "f"(b) : "memory");
}
__device__ __forceinline__ void red4(float* p, float a, float b, float c, float d) {
    asm volatile("red.global.add.v4.f32 [%0], {%1, %2, %3, %4};"
                 :: "l"(p), "f"(a), "f"(b), "f"(c), "f"(d) : "memory");
}
__device__ __forceinline__ float lk(float t) { return (t >= 0.f) ? t : 0.1f * t; }

__device__ __forceinline__ void mma8(float* c, const uint32_t* a, const uint32_t* b) {
    asm volatile("mma.sync.aligned.m16n8k8.row.col.f32.tf32.tf32.f32 "
        "{%0,%1,%2,%3}, {%4,%5,%6,%7}, {%8,%9}, {%0,%1,%2,%3};"
        : "+f"(c[0]), "+f"(c[1]), "+f"(c[2]), "+f"(c[3])
        : "r"(a[0]), "r"(a[1]), "r"(a[2]), "r"(a[3]), "r"(b[0]), "r"(b[1]));
}

// A[m][k], W[n][k] in smem, LDW leading dim. warp tile 32x64. (8 warps)
__device__ __forceinline__ void gemm_ws(const float* __restrict__ As,
                                        const float* __restrict__ Ws,
                                        int ksteps, int m0, int n0, int lane,
                                        float acc[2][8][4])
{
    int ar = lane >> 2, ac = lane & 3;
    const float* Ap0 = As + (m0 + ar) * LDW + ac;
    const float* Ap1 = As + (m0 + 16 + ar) * LDW + ac;
    const float* Wp  = Ws + (n0 + ar) * LDW + ac;
#pragma unroll 2
    for (int ks = 0; ks < ksteps; ks++) {
        int k0 = ks * 8;
        uint32_t a[2][4], b[8][2];
        a[0][0] = __float_as_uint(Ap0[k0]);
        a[0][1] = __float_as_uint(Ap0[k0 + 8 * LDW]);
        a[0][2] = __float_as_uint(Ap0[k0 + 4]);
        a[0][3] = __float_as_uint(Ap0[k0 + 8 * LDW + 4]);
        a[1][0] = __float_as_uint(Ap1[k0]);
        a[1][1] = __float_as_uint(Ap1[k0 + 8 * LDW]);
        a[1][2] = __float_as_uint(Ap1[k0 + 4]);
        a[1][3] = __float_as_uint(Ap1[k0 + 8 * LDW + 4]);
#pragma unroll
        for (int ni = 0; ni < 8; ni++) {
            const float* q = Wp + ni * 8 * LDW + k0;
            b[ni][0] = __float_as_uint(q[0]);
            b[ni][1] = __float_as_uint(q[4]);
        }
#pragma unroll
        for (int mi = 0; mi < 2; mi++)
#pragma unroll
            for (int ni = 0; ni < 8; ni++) mma8(acc[mi][ni], a[mi], b[ni]);
    }
}

// ---------------- K_prep ----------------
__global__ void k_prep(const float* __restrict__ Wy000, const float* __restrict__ Wy110,
                       const float* __restrict__ Wm1, const float* __restrict__ Wm2,
                       const float* __restrict__ Wm3)
{
    int idx = blockIdx.x * 256 + threadIdx.x;
    if (idx >= WBLOB) return;
    int n = idx / LDW, k = idx % LDW;
    float w0 = 0.f, w1 = 0.f, w2 = 0.f, w3 = 0.f;
    if (k < 64)  w0 = (k < 32) ? Wy000[n * 32 + k] : Wy110[n * 32 + (k - 32)];
    if (k < 128) { w1 = Wm1[n * 128 + k]; w2 = Wm2[n * 128 + k]; w3 = Wm3[n * 128 + k]; }
    g_Wb[0][idx] = tf32f(w0);
    g_Wb[1][idx] = tf32f(w1);
    g_Wb[2][idx] = tf32f(w2);
    g_Wb[3][idx] = tf32f(w3);
}

// ---------------- K0: node projections (64 nodes/block) ----------------
__global__ void __launch_bounds__(256) k_node(
    const float* __restrict__ xa, const float* __restrict__ xv,
    const float* __restrict__ WL0, const float* __restrict__ WL1)
{
    __shared__ float sW0t[32][132];   // [c][d]
    __shared__ float sW1t[32][33];    // [c][d]
    int tid = threadIdx.x;
    for (int idx = tid; idx < 4096; idx += 256) {
        int c = idx >> 7, d = idx & 127;
        sW0t[c][d] = WL0[idx];
    }
    for (int idx = tid; idx < 1024; idx += 256) {
        int c = idx >> 5, d = idx & 31;
        sW1t[c][d] = WL1[idx];
    }
    __syncthreads();

    int w = tid >> 5, lane = tid & 31;
    const float4* wv = (const float4*)&sW0t[lane][0];

#pragma unroll 2
    for (int it = 0; it < 8; it++) {
        int n = blockIdx.x * 64 + it * 8 + w;
        if (n >= NN) return;

        const float4* x4 = (const float4*)(xa + n * 128);
        float acc = 0.f;
#pragma unroll 8
        for (int d4 = 0; d4 < 32; d4++) {
            float4 a = __ldg(x4 + d4), b = wv[d4];
            acc += a.x * b.x + a.y * b.y + a.z * b.z + a.w * b.w;
        }
        g_L0[n * 32 + lane] = acc;

        const float* xvp = xv + n * 96;
        float a0 = 0.f, a1 = 0.f, a2 = 0.f;
#pragma unroll 8
        for (int d = 0; d < 32; d++) {
            float wd = sW1t[lane][d];
            a0 += __ldg(xvp + 3 * d)     * wd;
            a1 += __ldg(xvp + 3 * d + 1) * wd;
            a2 += __ldg(xvp + 3 * d + 2) * wd;
        }
        g_L1[n * 96 +      lane] = a0;
        g_L1[n * 96 + 32 + lane] = a1;
        g_L1[n * 96 + 64 + lane] = a2;
    }
}

// ---------------- K1: edge light path, tensor-core psi_v, red4 scatter ----------------
__global__ void __launch_bounds__(256, 2) k_edge1(
    const float* __restrict__ rij, const int* __restrict__ src,
    const int* __restrict__ dst,
    const float* __restrict__ Wenc, const float* __restrict__ benc,
    const float* __restrict__ W011, const float* __restrict__ W101,
    const float* __restrict__ W111,
    float* __restrict__ Bv, int e_base, int e_end)
{
    extern __shared__ __align__(16) float s1[];
    float* sY0 = s1;                   // 128 x LD1
    float* sGx = sY0 + 128 * LD1;
    float* sGy = sGx + 128 * LD1;
    float* sGz = sGy + 128 * LD1;
    float* sW  = sGz + 128 * LD1;      // 3 x 32 x LD1
    float* s_rs = sW + 3 * 32 * LD1;   // 128 x 4
    float* sP  = s1;                   // reuse after GEMMs: 128 x 96
    __shared__ float sWe[8 * 32];
    __shared__ float sbe[32];
    __shared__ int   s_src[128];

    int tid = threadIdx.x, wid = tid >> 5, lane = tid & 31;
    int e0 = e_base + blockIdx.x * 128;

    for (int idx = tid; idx < 256; idx += 256) {
        int c = idx >> 3, k = idx & 7;
        sWe[k * 32 + c] = Wenc[idx];
    }
    if (tid < 32) sbe[tid] = benc[tid];
    for (int idx = tid; idx < 3 * 1024; idx += 256) {
        int wi = idx >> 10, r = idx & 1023;
        int d = r >> 5, c = r & 31;
        const float* Wsrc = (wi == 0) ? W011 : ((wi == 1) ? W101 : W111);
        sW[wi * 32 * LD1 + d * LD1 + c] = tf32f(Wsrc[d * 32 + c]);
    }
    if (tid < 128) s_src[tid] = (e0 + tid < e_end) ? src[e0 + tid] : -1;
    __syncthreads();

    // ---- phase 1: per-edge elementwise (warp per edge) ----
    for (int it = 0; it < 16; it++) {
        int el = it * 8 + wid;
        int e  = e0 + el;
        float y0 = 0.f, gx = 0.f, gy = 0.f, gz = 0.f;
        float sx = 0.f, sy = 0.f, sz = 0.f;
        if (e < e_end) {
            float rx = rij[3 * e], ry = rij[3 * e + 1], rz = rij[3 * e + 2];
            float rn = sqrtf(rx * rx + ry * ry + rz * rz);
            float ek = 0.f;
            if (lane < 8) {
                float t = (rn - (5.0f / 7.0f) * (float)lane) * 1.6f;
                ek = expf(-t * t);
            }
            float sq_l = 0.f;
            if (lane == 8) {
                float n14 = 1.4f * rn;
                sq_l = tanhf(n14) / fmaxf(n14, 1e-6f);
            }
            float sq = __shfl_sync(0xffffffffu, sq_l, 8);
            sx = 1.4f * rx * sq; sy = 1.4f * ry * sq; sz = 1.4f * rz * sq;

            float g = sbe[lane];
#pragma unroll
            for (int k = 0; k < 8; k++)
                g += __shfl_sync(0xffffffffu, ek, k) * sWe[k * 32 + lane];

            int dn = dst[e];
            float la  = g_L0[dn * 32 + lane];
            float lvx = g_L1[dn * 96 +      lane];
            float lvy = g_L1[dn * 96 + 32 + lane];
            float lvz = g_L1[dn * 96 + 64 + lane];

            y0 = tf32f(la * g);
            gx = tf32f(g * lvx); gy = tf32f(g * lvy); gz = tf32f(g * lvz);

            g_Y[(size_t)e * 64 + lane]      = y0;
            g_Y[(size_t)e * 64 + 32 + lane] = tf32f((lvx * sx + lvy * sy + lvz * sz) * g);
        }
        sY0[el * LD1 + lane] = y0;
        sGx[el * LD1 + lane] = gx;
        sGy[el * LD1 + lane] = gy;
        sGz[el * LD1 + lane] = gz;
        if (lane == 0) {
            s_rs[el * 4]     = sx;
            s_rs[el * 4 + 1] = sy;
            s_rs[el * 4 + 2] = sz;
        }
    }
    __syncthreads();

    // ---- phase 2: 7 GEMMs per pass (q, u_xyz, v_xyz), results to registers ----
    int cg = wid & 1, rg = wid >> 1;
    int n0 = cg * 16;
    int ar = lane >> 2, ac = lane & 3;

    float P[2][2][4][3];    // [pass][ni][j][xyz] — 0.1*psi_v

#pragma unroll
    for (int pass = 0; pass < 2; pass++) {
        int m0 = pass * 64 + rg * 16;
        float q[2][4], u[3][2][4], vv[3][2][4];
#pragma unroll
        for (int ni = 0; ni < 2; ni++)
#pragma unroll
            for (int j = 0; j < 4; j++) {
                q[ni][j] = 0.f;
#pragma unroll
                for (int i = 0; i < 3; i++) { u[i][ni][j] = 0.f; vv[i][ni][j] = 0.f; }
            }

        const float* Ay  = sY0 + (m0 + ar) * LD1 + ac;
        const float* Agx = sGx + (m0 + ar) * LD1 + ac;
        const float* Agy = sGy + (m0 + ar) * LD1 + ac;
        const float* Agz = sGz + (m0 + ar) * LD1 + ac;
        const float* B0 = sW + 0 * 32 * LD1 + (n0 + ar) * LD1 + ac;
        const float* B1 = sW + 1 * 32 * LD1 + (n0 + ar) * LD1 + ac;
        const float* B2 = sW + 2 * 32 * LD1 + (n0 + ar) * LD1 + ac;

#pragma unroll
        for (int ks = 0; ks < 4; ks++) {
            int k0 = ks * 8;
            uint32_t ay[4], ag[3][4];
            ay[0] = __float_as_uint(Ay[k0]);
            ay[1] = __float_as_uint(Ay[k0 + 8 * LD1]);
            ay[2] = __float_as_uint(Ay[k0 + 4]);
            ay[3] = __float_as_uint(Ay[k0 + 8 * LD1 + 4]);
            const float* Ags[3] = {Agx, Agy, Agz};
#pragma unroll
            for (int i = 0; i < 3; i++) {
                ag[i][0] = __float_as_uint(Ags[i][k0]);
                ag[i][1] = __float_as_uint(Ags[i][k0 + 8 * LD1]);
                ag[i][2] = __float_as_uint(Ags[i][k0 + 4]);
                ag[i][3] = __float_as_uint(Ags[i][k0 + 8 * LD1 + 4]);
            }
            uint32_t b0[2][2], b1[2][2], b2[2][2];
#pragma unroll
            for (int ni = 0; ni < 2; ni++) {
                b0[ni][0] = __float_as_uint(B0[ni * 8 * LD1 + k0]);
                b0[ni][1] = __float_as_uint(B0[ni * 8 * LD1 + k0 + 4]);
                b1[ni][0] = __float_as_uint(B1[ni * 8 * LD1 + k0]);
                b1[ni][1] = __float_as_uint(B1[ni * 8 * LD1 + k0 + 4]);
                b2[ni][0] = __float_as_uint(B2[ni * 8 * LD1 + k0]);
                b2[ni][1] = __float_as_uint(B2[ni * 8 * LD1 + k0 + 4]);
            }
#pragma unroll
            for (int ni = 0; ni < 2; ni++) {
                mma8(q[ni], ay, b0[ni]);
#pragma unroll
                for (int i = 0; i < 3; i++) {
                    mma8(u[i][ni],  ag[i], b1[ni]);
                    mma8(vv[i][ni], ag[i], b2[ni]);
                }
            }
        }

        int r0 = m0 + ar, r1 = r0 + 8;
        float rx0 = s_rs[r0 * 4], ry0 = s_rs[r0 * 4 + 1], rz0 = s_rs[r0 * 4 + 2];
        float rx1 = s_rs[r1 * 4], ry1 = s_rs[r1 * 4 + 1], rz1 = s_rs[r1 * 4 + 2];
#pragma unroll
        for (int ni = 0; ni < 2; ni++)
#pragma unroll
            for (int j = 0; j < 4; j++) {
                float rx = (j < 2) ? rx0 : rx1;
                float ry = (j < 2) ? ry0 : ry1;
                float rz = (j < 2) ? rz0 : rz1;
                float qq = q[ni][j];
                P[pass][ni][j][0] = 0.1f * (qq * rx + u[0][ni][j] + vv[1][ni][j] * rz - vv[2][ni][j] * ry);
                P[pass][ni][j][1] = 0.1f * (qq * ry + u[1][ni][j] + vv[2][ni][j] * rx - vv[0][ni][j] * rz);
                P[pass][ni][j][2] = 0.1f * (qq * rz + u[2][ni][j] + vv[0][ni][j] * ry - vv[1][ni][j] * rx);
            }
    }
    __syncthreads();

    // ---- transpose to sP[128][96] ----
#pragma unroll
    for (int pass = 0; pass < 2; pass++)
#pragma unroll
        for (int ni = 0; ni < 2; ni++)
#pragma unroll
            for (int j = 0; j < 4; j++) {
                int row = pass * 64 + rg * 16 + ar + ((j >= 2) ? 8 : 0);
                int col = n0 + ni * 8 + 2 * ac + (j & 1);
                float* p = sP + row * 96 + col * 3;
                p[0] = P[pass][ni][j][0];
                p[1] = P[pass][ni][j][1];
                p[2] = P[pass][ni][j][2];
            }
    __syncthreads();

    // ---- vector scatter: 24 red4 per edge ----
    const float4* sP4 = (const float4*)sP;
    for (int it = 0; it < 16; it++) {
        int el = it * 8 + wid;
        int sn = s_src[el];
        if (sn >= 0 && lane < 24) {
            float4 v = sP4[el * 24 + lane];
            red4(Bv + (size_t)sn * 96 + lane * 4, v.x, v.y, v.z, v.w);
        }
    }
}

// ---------------- K2: tf32 mma.sync fused MLP chain (256 thr, 8 warps) ----------------
__global__ void __launch_bounds__(256)
k_edge2(const float* __restrict__ bm1, const float* __restrict__ bm2,
        const int* __restrict__ src, float* __restrict__ Ba, int e_base, int e_end)
{
    extern __shared__ __align__(16) float sm[];
    float* As = sm;
    float* W0 = sm + WBLOB;
    float* W1 = sm + 2 * WBLOB;
    __shared__ float s_b1[128], s_b2[128];
    __shared__ int s_src[128];

    int tid = threadIdx.x, wid = tid >> 5, lane = tid & 31;
    int m0 = (wid >> 1) * 32, n0 = (wid & 1) * 64;
    int ar = lane >> 2, ac = lane & 3;
    int e0 = e_base + blockIdx.x * 128;

    if (tid < 128) {
        s_b1[tid] = bm1[tid];
        s_b2[tid] = bm2[tid];
        int e = e0 + tid;
        s_src[tid] = (e < e_end) ? src[e] : -1;
    }

    uint32_t uA  = smem_u32(As);
    uint32_t uW0 = smem_u32(W0);
    uint32_t uW1 = smem_u32(W1);

    for (int idx = tid; idx < 2048; idx += 256) {
        int m = idx >> 4, c = idx & 15;
        cp16(uA + (uint32_t)(m * LDW * 4 + c * 16),
             (const char*)(g_Y + (size_t)(e0 + m) * 64) + c * 16);
    }
    for (int idx = tid; idx < 4224; idx += 256)
        cp16(uW0 + (uint32_t)(idx * 16), (const char*)g_Wb[0] + idx * 16);
    CP_COMMIT();
    for (int idx = tid; idx < 4224; idx += 256)
        cp16(uW1 + (uint32_t)(idx * 16), (const char*)g_Wb[1] + idx * 16);
    CP_COMMIT();
    CP_WAIT(1);
    __syncthreads();

    float acc[2][8][4];
#pragma unroll
    for (int mi = 0; mi < 2; mi++)
#pragma unroll
        for (int ni = 0; ni < 8; ni++)
#pragma unroll
            for (int j = 0; j < 4; j++) acc[mi][ni][j] = 0.f;

    // ---- GEMM1: psi0 = Y @ Wcat^T (K=64) ----
    gemm_ws(As, W0, 8, m0, n0, lane, acc);

    float psi[2][8][4];
#pragma unroll
    for (int mi = 0; mi < 2; mi++)
#pragma unroll
        for (int ni = 0; ni < 8; ni++)
#pragma unroll
            for (int j = 0; j < 4; j++) psi[mi][ni][j] = acc[mi][ni][j];

    __syncthreads();
#pragma unroll
    for (int mi = 0; mi < 2; mi++)
#pragma unroll
        for (int ni = 0; ni < 8; ni++) {
            int row = m0 + mi * 16 + ar;
            int col = n0 + ni * 8 + 2 * ac;
            *(float2*)(As + row * LDW + col) = make_float2(tf32f(acc[mi][ni][0]), tf32f(acc[mi][ni][1]));
            *(float2*)(As + (row + 8) * LDW + col) = make_float2(tf32f(acc[mi][ni][2]), tf32f(acc[mi][ni][3]));
        }
    for (int idx = tid; idx < 4224; idx += 256)
        cp16(uW0 + (uint32_t)(idx * 16), (const char*)g_Wb[2] + idx * 16);
    CP_COMMIT();
    CP_WAIT(1);
    __syncthreads();

    // ---- GEMM2: h1 = leaky(psi0 @ Wm1^T + b1) ----
#pragma unroll
    for (int mi = 0; mi < 2; mi++)
#pragma unroll
        for (int ni = 0; ni < 8; ni++)
#pragma unroll
            for (int j = 0; j < 4; j++) acc[mi][ni][j] = 0.f;
    gemm_ws(As, W1, 16, m0, n0, lane, acc);
    __syncthreads();
#pragma unroll
    for (int mi = 0; mi < 2; mi++)
#pragma unroll
        for (int ni = 0; ni < 8; ni++) {
            int row = m0 + mi * 16 + ar;
            int col = n0 + ni * 8 + 2 * ac;
            float2 bb = *(const float2*)(s_b1 + col);
            *(float2*)(As + row * LDW + col) =
                make_float2(tf32f(lk(acc[mi][ni][0] + bb.x)), tf32f(lk(acc[mi][ni][1] + bb.y)));
            *(float2*)(As + (row + 8) * LDW + col) =
                make_float2(tf32f(lk(acc[mi][ni][2] + bb.x)), tf32f(lk(acc[mi][ni][3] + bb.y)));
        }
    for (int idx = tid; idx < 4224; idx += 256)
        cp16(uW1 + (uint32_t)(idx * 16), (const char*)g_Wb[3] + idx * 16);
    CP_COMMIT();
    CP_WAIT(1);
    __syncthreads();

    // ---- GEMM3: h2 = leaky(h1 @ Wm2^T + b2) ----
#pragma unroll
    for (int mi = 0; mi < 2; mi++)
#pragma unroll
        for (int ni = 0; ni < 8; ni++)
#pragma unroll
            for (int j = 0; j < 4; j++) acc[mi][ni][j] = 0.f;
    gemm_ws(As, W0, 16, m0, n0, lane, acc);
    __syncthreads();
#pragma unroll
    for (int mi = 0; mi < 2; mi++)
#pragma unroll
        for (int ni = 0; ni < 8; ni++) {
            int row = m0 + mi * 16 + ar;
            int col = n0 + ni * 8 + 2 * ac;
            float2 bb = *(const float2*)(s_b2 + col);
            *(float2*)(As + row * LDW + col) =
                make_float2(tf32f(lk(acc[mi][ni][0] + bb.x)), tf32f(lk(acc[mi][ni][1] + bb.y)));
            *(float2*)(As + (row + 8) * LDW + col) =
                make_float2(tf32f(lk(acc[mi][ni][2] + bb.x)), tf32f(lk(acc[mi][ni][3] + bb.y)));
        }
    CP_WAIT(0);
    __syncthreads();

    // ---- GEMM4: psi_a = psi0 + h2 @ Wm3^T ; scatter ----
#pragma unroll
    for (int mi = 0; mi < 2; mi++)
#pragma unroll
        for (int ni = 0; ni < 8; ni++)
#pragma unroll
            for (int j = 0; j < 4; j++) acc[mi][ni][j] = psi[mi][ni][j];
    gemm_ws(As, W1, 16, m0, n0, lane, acc);

#pragma unroll
    for (int mi = 0; mi < 2; mi++) {
        int row = m0 + mi * 16 + ar;
        int sn0 = s_src[row];
        int sn1 = s_src[row + 8];
#pragma unroll
        for (int ni = 0; ni < 8; ni++) {
            int col = n0 + ni * 8 + 2 * ac;
            if (sn0 >= 0)
                red2(Ba + (size_t)sn0 * 128 + col, 0.1f * acc[mi][ni][0], 0.1f * acc[mi][ni][1]);
            if (sn1 >= 0)
                red2(Ba + (size_t)sn1 * 128 + col, 0.1f * acc[mi][ni][2], 0.1f * acc[mi][ni][3]);
        }
    }
}

// ---------------- launch (multi-stream graph fork) ----------------
extern "C" void kernel_launch(void* const* d_in, const int* in_sizes, int n_in,
                              void* d_out, int out_size)
{
    const float* x_a   = (const float*)d_in[0];
    const float* x_v   = (const float*)d_in[1];
    const float* r_ij  = (const float*)d_in[2];
    const int*   src   = (const int*)  d_in[3];
    const int*   dst   = (const int*)  d_in[4];
    const float* WL0   = (const float*)d_in[5];
    const float* WL1   = (const float*)d_in[6];
    const float* Wenc  = (const float*)d_in[7];
    const float* benc  = (const float*)d_in[8];
    const float* Wy000 = (const float*)d_in[9];
    const float* Wy110 = (const float*)d_in[10];
    const float* Wy011 = (const float*)d_in[11];
    const float* Wy101 = (const float*)d_in[12];
    const float* Wy111 = (const float*)d_in[13];
    const float* Wm1   = (const float*)d_in[14];
    const float* bm1   = (const float*)d_in[15];
    const float* Wm2   = (const float*)d_in[16];
    const float* bm2   = (const float*)d_in[17];
    const float* Wm3   = (const float*)d_in[18];
    float* out = (float*)d_out;
    float* Bv  = out + (size_t)NN * 128;

    static cudaStream_t sA = nullptr, sB = nullptr;
    static cudaEvent_t evRoot, evM, evN, evPd, ev1B;
    if (!sA) {
        cudaStreamCreateWithFlags(&sA, cudaStreamNonBlocking);
        cudaStreamCreateWithFlags(&sB, cudaStreamNonBlocking);
        cudaEventCreateWithFlags(&evRoot, cudaEventDisableTiming);
        cudaEventCreateWithFlags(&evM,    cudaEventDisableTiming);
        cudaEventCreateWithFlags(&evN,    cudaEventDisableTiming);
        cudaEventCreateWithFlags(&evPd,   cudaEventDisableTiming);
        cudaEventCreateWithFlags(&ev1B,   cudaEventDisableTiming);

        int smem1 = (4 * 128 * LD1 + 3 * 32 * LD1 + 128 * 4) * (int)sizeof(float);
        int smem2 = 3 * WBLOB * (int)sizeof(float);
        cudaFuncSetAttribute(k_edge1, cudaFuncAttributeMaxDynamicSharedMemorySize, smem1);
        cudaFuncSetAttribute(k_edge2, cudaFuncAttributeMaxDynamicSharedMemorySize, smem2);
    }
    const int smem1 = (4 * 128 * LD1 + 3 * 32 * LD1 + 128 * 4) * (int)sizeof(float); // 89,600
    const int smem2 = 3 * WBLOB * (int)sizeof(float);                                // 202,752

    // fork
    cudaEventRecord(evRoot, 0);
    cudaStreamWaitEvent(sA, evRoot, 0);
    cudaStreamWaitEvent(sB, evRoot, 0);

    // head: memset (s0) || prep (sA) || node (sB)
    cudaMemsetAsync(out, 0, (size_t)out_size * sizeof(float), 0);
    cudaEventRecord(evM, 0);
    k_prep<<<(WBLOB + 255) / 256, 256, 0, sA>>>(Wy000, Wy110, Wm1, Wm2, Wm3);
    cudaEventRecord(evPd, sA);
    k_node<<<(NN + 63) / 64, 256, 0, sB>>>(x_a, x_v, WL0, WL1);
    cudaEventRecord(evN, sB);

    // chunk A: edge1 on s0 (needs node; memset in-stream)
    cudaStreamWaitEvent(0, evN, 0);
    k_edge1<<<EA_END / 128, 256, smem1, 0>>>(r_ij, src, dst, Wenc, benc,
                                             Wy011, Wy101, Wy111, Bv, 0, EA_END);

    // chunk B: edge1 on sB (has node in-stream; needs memset)
    cudaStreamWaitEvent(sB, evM, 0);
    k_edge1<<<(NE - EA_END + 127) / 128, 256, smem1, sB>>>(r_ij, src, dst, Wenc, benc,
                                                           Wy011, Wy101, Wy111, Bv, EA_END, NE);
    cudaEventRecord(ev1B, sB);

    // chunk A: edge2 on s0 (needs prep; edge1_A in-stream) — overlaps edge1_B
    cudaStreamWaitEvent(0, evPd, 0);
    k_edge2<<<EA_END / 128, 256, smem2, 0>>>(bm1, bm2, src, out, 0, EA_END);

    // chunk B: edge2 on s0 after edge1_B joins
    cudaStreamWaitEvent(0, ev1B, 0);
    k_edge2<<<(NE - EA_END + 127) / 128, 256, smem2, 0>>>(bm1, bm2, src, out, EA_END, NE);
}

// round 7
// speedup vs baseline: 4.8377x; 1.2361x over previous
#include <cuda_runtime.h>
#include <cuda_fp16.h>
#include <cstdint>
#include <math.h>

#define NN 50000
#define NE 500000
#define NE_PAD 500096           // 3907 * 128
#define EA_END 249984           // 1953 * 128 — chunk A end
#define LDH 136                 // k_edge2 smem leading dim (halves): 272B rows, conflict-free
#define WBLOBH (128 * LDH)      // one weight image (halves)
#define LD1 36                  // k_edge1 smem leading dim (floats)

// ---------------- scratch (device globals: allocation-free) ----------------
__device__ float g_L0[NN * 32];
__device__ float g_L1[NN * 3 * 32];
__device__ __align__(16) __half g_Y[(size_t)NE_PAD * 64];   // fp16 [e][64]
__device__ __align__(16) __half g_Wb[4][WBLOBH];            // pre-swizzled fp16 weights

// ================= helpers =================
__device__ __forceinline__ uint32_t smem_u32(const void* p) {
    uint32_t a;
    asm("{ .reg .u64 t; cvta.to.shared.u64 t, %1; cvt.u32.u64 %0, t; }" : "=r"(a) : "l"(p));
    return a;
}
__device__ __forceinline__ uint32_t cvt_tf32(float f) {
    uint32_t r; asm("cvt.rna.tf32.f32 %0, %1;" : "=r"(r) : "f"(f)); return r;
}
__device__ __forceinline__ float tf32f(float f) { return __uint_as_float(cvt_tf32(f)); }
__device__ __forceinline__ uint32_t pack_h2(float x, float y) {
    __half2 h = __floats2half2_rn(x, y);
    return *reinterpret_cast<uint32_t*>(&h);
}

__device__ __forceinline__ void cp16(uint32_t d, const void* s) {
    asm volatile("cp.async.cg.shared.global [%0], [%1], 16;" :: "r"(d), "l"(s) : "memory");
}
#define CP_COMMIT() asm volatile("cp.async.commit_group;" ::: "memory")
#define CP_WAIT(n)  asm volatile("cp.async.wait_group %0;" :: "n"(n) : "memory")

__device__ __forceinline__ void red2(float* p, float a, float b) {
    asm volatile("red.global.add.v2.f32 [%0], {%1, %2};" :: "l"(p), "f"(a), "f"(b) : "memory");
}
__device__ __forceinline__ void red4(float* p, float a, float b, float c, float d) {
    asm volatile("red.global.add.v4.f32 [%0], {%1, %2, %3, %4};"
                 :: "l"(p), "f"(a), "f"(b), "f"(c), "f"(d) : "memory");
}
__device__ __forceinline__ float lk(float t) { return (t >= 0.f) ? t : 0.1f * t; }

// tf32 k8 mma (k_edge1)
__device__ __forceinline__ void mma8(float* c, const uint32_t* a, const uint32_t* b) {
    asm volatile("mma.sync.aligned.m16n8k8.row.col.f32.tf32.tf32.f32 "
        "{%0,%1,%2,%3}, {%4,%5,%6,%7}, {%8,%9}, {%0,%1,%2,%3};"
        : "+f"(c[0]), "+f"(c[1]), "+f"(c[2]), "+f"(c[3])
        : "r"(a[0]), "r"(a[1]), "r"(a[2]), "r"(a[3]), "r"(b[0]), "r"(b[1]));
}
// fp16 k16 mma (k_edge2)
__device__ __forceinline__ void mma16(float* c, const uint32_t* a, const uint32_t* b) {
    asm volatile("mma.sync.aligned.m16n8k16.row.col.f32.f16.f16.f32 "
        "{%0,%1,%2,%3}, {%4,%5,%6,%7}, {%8,%9}, {%0,%1,%2,%3};"
        : "+f"(c[0]), "+f"(c[1]), "+f"(c[2]), "+f"(c[3])
        : "r"(a[0]), "r"(a[1]), "r"(a[2]), "r"(a[3]), "r"(b[0]), "r"(b[1]));
}

// fp16 GEMM: A[m][k], W[n][k] halves, LDH leading dim, warp tile 32x64, 8 warps.
__device__ __forceinline__ void gemm_h(const __half* __restrict__ As,
                                       const __half* __restrict__ Ws,
                                       int ksteps, int m0, int n0, int lane,
                                       float acc[2][8][4])
{
    int gr = lane >> 2, tc = lane & 3;
    const uint32_t* Ap0 = (const uint32_t*)(As + (m0 + gr) * LDH) + tc;
    const uint32_t* Ap1 = (const uint32_t*)(As + (m0 + 16 + gr) * LDH) + tc;
    const uint32_t* Wp  = (const uint32_t*)(Ws + (n0 + gr) * LDH) + tc;
    const int ROW8 = 8 * (LDH / 2);     // 8 rows in uints (544)
#pragma unroll 2
    for (int ks = 0; ks < ksteps; ks++) {
        int k0 = ks * 8;                // uints per 16-k step
        uint32_t a[2][4], b[8][2];
        a[0][0] = Ap0[k0];
        a[0][1] = Ap0[k0 + ROW8];
        a[0][2] = Ap0[k0 + 4];
        a[0][3] = Ap0[k0 + ROW8 + 4];
        a[1][0] = Ap1[k0];
        a[1][1] = Ap1[k0 + ROW8];
        a[1][2] = Ap1[k0 + 4];
        a[1][3] = Ap1[k0 + ROW8 + 4];
#pragma unroll
        for (int ni = 0; ni < 8; ni++) {
            const uint32_t* q = Wp + ni * ROW8 + k0;
            b[ni][0] = q[0];
            b[ni][1] = q[4];
        }
#pragma unroll
        for (int mi = 0; mi < 2; mi++)
#pragma unroll
            for (int ni = 0; ni < 8; ni++) mma16(acc[mi][ni], a[mi], b[ni]);
    }
}

// ---------------- K_prep: weights -> fp16 blobs ----------------
__global__ void k_prep(const float* __restrict__ Wy000, const float* __restrict__ Wy110,
                       const float* __restrict__ Wm1, const float* __restrict__ Wm2,
                       const float* __restrict__ Wm3)
{
    int idx = blockIdx.x * 256 + threadIdx.x;
    if (idx >= WBLOBH) return;
    int n = idx / LDH, k = idx % LDH;
    float w0 = 0.f, w1 = 0.f, w2 = 0.f, w3 = 0.f;
    if (k < 64)  w0 = (k < 32) ? Wy000[n * 32 + k] : Wy110[n * 32 + (k - 32)];
    if (k < 128) { w1 = Wm1[n * 128 + k]; w2 = Wm2[n * 128 + k]; w3 = Wm3[n * 128 + k]; }
    g_Wb[0][idx] = __float2half_rn(w0);
    g_Wb[1][idx] = __float2half_rn(w1);
    g_Wb[2][idx] = __float2half_rn(w2);
    g_Wb[3][idx] = __float2half_rn(w3);
}

// ---------------- K0: node projections (64 nodes/block) ----------------
__global__ void __launch_bounds__(256) k_node(
    const float* __restrict__ xa, const float* __restrict__ xv,
    const float* __restrict__ WL0, const float* __restrict__ WL1)
{
    __shared__ float sW0t[32][132];
    __shared__ float sW1t[32][33];
    int tid = threadIdx.x;
    for (int idx = tid; idx < 4096; idx += 256) {
        int c = idx >> 7, d = idx & 127;
        sW0t[c][d] = WL0[idx];
    }
    for (int idx = tid; idx < 1024; idx += 256) {
        int c = idx >> 5, d = idx & 31;
        sW1t[c][d] = WL1[idx];
    }
    __syncthreads();

    int w = tid >> 5, lane = tid & 31;
    const float4* wv = (const float4*)&sW0t[lane][0];

#pragma unroll 2
    for (int it = 0; it < 8; it++) {
        int n = blockIdx.x * 64 + it * 8 + w;
        if (n >= NN) return;

        const float4* x4 = (const float4*)(xa + n * 128);
        float acc = 0.f;
#pragma unroll 8
        for (int d4 = 0; d4 < 32; d4++) {
            float4 a = __ldg(x4 + d4), b = wv[d4];
            acc += a.x * b.x + a.y * b.y + a.z * b.z + a.w * b.w;
        }
        g_L0[n * 32 + lane] = acc;

        const float* xvp = xv + n * 96;
        float a0 = 0.f, a1 = 0.f, a2 = 0.f;
#pragma unroll 8
        for (int d = 0; d < 32; d++) {
            float wd = sW1t[lane][d];
            a0 += __ldg(xvp + 3 * d)     * wd;
            a1 += __ldg(xvp + 3 * d + 1) * wd;
            a2 += __ldg(xvp + 3 * d + 2) * wd;
        }
        g_L1[n * 96 +      lane] = a0;
        g_L1[n * 96 + 32 + lane] = a1;
        g_L1[n * 96 + 64 + lane] = a2;
    }
}

// ---------------- K1: edge light path, tensor-core psi_v, red4 scatter ----------------
__global__ void __launch_bounds__(256, 2) k_edge1(
    const float* __restrict__ rij, const int* __restrict__ src,
    const int* __restrict__ dst,
    const float* __restrict__ Wenc, const float* __restrict__ benc,
    const float* __restrict__ W011, const float* __restrict__ W101,
    const float* __restrict__ W111,
    float* __restrict__ Bv, int e_base, int e_end)
{
    extern __shared__ __align__(16) float s1[];
    float* sY0 = s1;                   // 128 x LD1
    float* sGx = sY0 + 128 * LD1;
    float* sGy = sGx + 128 * LD1;
    float* sGz = sGy + 128 * LD1;
    float* sW  = sGz + 128 * LD1;      // 3 x 32 x LD1
    float* s_rs = sW + 3 * 32 * LD1;   // 128 x 4
    float* sP  = s1;                   // reuse after GEMMs: 128 x 96
    __shared__ float sWe[8 * 32];
    __shared__ float sbe[32];
    __shared__ int   s_src[128];

    int tid = threadIdx.x, wid = tid >> 5, lane = tid & 31;
    int e0 = e_base + blockIdx.x * 128;

    for (int idx = tid; idx < 256; idx += 256) {
        int c = idx >> 3, k = idx & 7;
        sWe[k * 32 + c] = Wenc[idx];
    }
    if (tid < 32) sbe[tid] = benc[tid];
    for (int idx = tid; idx < 3 * 1024; idx += 256) {
        int wi = idx >> 10, r = idx & 1023;
        int d = r >> 5, c = r & 31;
        const float* Wsrc = (wi == 0) ? W011 : ((wi == 1) ? W101 : W111);
        sW[wi * 32 * LD1 + d * LD1 + c] = tf32f(Wsrc[d * 32 + c]);
    }
    if (tid < 128) s_src[tid] = (e0 + tid < e_end) ? src[e0 + tid] : -1;
    __syncthreads();

    // ---- phase 1: per-edge elementwise (warp per edge) ----
    for (int it = 0; it < 16; it++) {
        int el = it * 8 + wid;
        int e  = e0 + el;
        float y0 = 0.f, gx = 0.f, gy = 0.f, gz = 0.f;
        float sx = 0.f, sy = 0.f, sz = 0.f;
        if (e < e_end) {
            float rx = rij[3 * e], ry = rij[3 * e + 1], rz = rij[3 * e + 2];
            float rn = sqrtf(rx * rx + ry * ry + rz * rz);
            float ek = 0.f;
            if (lane < 8) {
                float t = (rn - (5.0f / 7.0f) * (float)lane) * 1.6f;
                ek = expf(-t * t);
            }
            float sq_l = 0.f;
            if (lane == 8) {
                float n14 = 1.4f * rn;
                sq_l = tanhf(n14) / fmaxf(n14, 1e-6f);
            }
            float sq = __shfl_sync(0xffffffffu, sq_l, 8);
            sx = 1.4f * rx * sq; sy = 1.4f * ry * sq; sz = 1.4f * rz * sq;

            float g = sbe[lane];
#pragma unroll
            for (int k = 0; k < 8; k++)
                g += __shfl_sync(0xffffffffu, ek, k) * sWe[k * 32 + lane];

            int dn = dst[e];
            float la  = g_L0[dn * 32 + lane];
            float lvx = g_L1[dn * 96 +      lane];
            float lvy = g_L1[dn * 96 + 32 + lane];
            float lvz = g_L1[dn * 96 + 64 + lane];

            y0 = tf32f(la * g);
            gx = tf32f(g * lvx); gy = tf32f(g * lvy); gz = tf32f(g * lvz);

            g_Y[(size_t)e * 64 + lane]      = __float2half_rn(la * g);
            g_Y[(size_t)e * 64 + 32 + lane] = __float2half_rn((lvx * sx + lvy * sy + lvz * sz) * g);
        }
        sY0[el * LD1 + lane] = y0;
        sGx[el * LD1 + lane] = gx;
        sGy[el * LD1 + lane] = gy;
        sGz[el * LD1 + lane] = gz;
        if (lane == 0) {
            s_rs[el * 4]     = sx;
            s_rs[el * 4 + 1] = sy;
            s_rs[el * 4 + 2] = sz;
        }
    }
    __syncthreads();

    // ---- phase 2: 7 GEMMs per pass (q, u_xyz, v_xyz) ----
    int cg = wid & 1, rg = wid >> 1;
    int n0 = cg * 16;
    int ar = lane >> 2, ac = lane & 3;

    float P[2][2][4][3];

#pragma unroll
    for (int pass = 0; pass < 2; pass++) {
        int m0 = pass * 64 + rg * 16;
        float q[2][4], u[3][2][4], vv[3][2][4];
#pragma unroll
        for (int ni = 0; ni < 2; ni++)
#pragma unroll
            for (int j = 0; j < 4; j++) {
                q[ni][j] = 0.f;
#pragma unroll
                for (int i = 0; i < 3; i++) { u[i][ni][j] = 0.f; vv[i][ni][j] = 0.f; }
            }

        const float* Ay  = sY0 + (m0 + ar) * LD1 + ac;
        const float* Agx = sGx + (m0 + ar) * LD1 + ac;
        const float* Agy = sGy + (m0 + ar) * LD1 + ac;
        const float* Agz = sGz + (m0 + ar) * LD1 + ac;
        const float* B0 = sW + 0 * 32 * LD1 + (n0 + ar) * LD1 + ac;
        const float* B1 = sW + 1 * 32 * LD1 + (n0 + ar) * LD1 + ac;
        const float* B2 = sW + 2 * 32 * LD1 + (n0 + ar) * LD1 + ac;

#pragma unroll
        for (int ks = 0; ks < 4; ks++) {
            int k0 = ks * 8;
            uint32_t ay[4], ag[3][4];
            ay[0] = __float_as_uint(Ay[k0]);
            ay[1] = __float_as_uint(Ay[k0 + 8 * LD1]);
            ay[2] = __float_as_uint(Ay[k0 + 4]);
            ay[3] = __float_as_uint(Ay[k0 + 8 * LD1 + 4]);
            const float* Ags[3] = {Agx, Agy, Agz};
#pragma unroll
            for (int i = 0; i < 3; i++) {
                ag[i][0] = __float_as_uint(Ags[i][k0]);
                ag[i][1] = __float_as_uint(Ags[i][k0 + 8 * LD1]);
                ag[i][2] = __float_as_uint(Ags[i][k0 + 4]);
                ag[i][3] = __float_as_uint(Ags[i][k0 + 8 * LD1 + 4]);
            }
            uint32_t b0[2][2], b1[2][2], b2[2][2];
#pragma unroll
            for (int ni = 0; ni < 2; ni++) {
                b0[ni][0] = __float_as_uint(B0[ni * 8 * LD1 + k0]);
                b0[ni][1] = __float_as_uint(B0[ni * 8 * LD1 + k0 + 4]);
                b1[ni][0] = __float_as_uint(B1[ni * 8 * LD1 + k0]);
                b1[ni][1] = __float_as_uint(B1[ni * 8 * LD1 + k0 + 4]);
                b2[ni][0] = __float_as_uint(B2[ni * 8 * LD1 + k0]);
                b2[ni][1] = __float_as_uint(B2[ni * 8 * LD1 + k0 + 4]);
            }
#pragma unroll
            for (int ni = 0; ni < 2; ni++) {
                mma8(q[ni], ay, b0[ni]);
#pragma unroll
                for (int i = 0; i < 3; i++) {
                    mma8(u[i][ni],  ag[i], b1[ni]);
                    mma8(vv[i][ni], ag[i], b2[ni]);
                }
            }
        }

        int r0 = m0 + ar, r1 = r0 + 8;
        float rx0 = s_rs[r0 * 4], ry0 = s_rs[r0 * 4 + 1], rz0 = s_rs[r0 * 4 + 2];
        float rx1 = s_rs[r1 * 4], ry1 = s_rs[r1 * 4 + 1], rz1 = s_rs[r1 * 4 + 2];
#pragma unroll
        for (int ni = 0; ni < 2; ni++)
#pragma unroll
            for (int j = 0; j < 4; j++) {
                float rx = (j < 2) ? rx0 : rx1;
                float ry = (j < 2) ? ry0 : ry1;
                float rz = (j < 2) ? rz0 : rz1;
                float qq = q[ni][j];
                P[pass][ni][j][0] = 0.1f * (qq * rx + u[0][ni][j] + vv[1][ni][j] * rz - vv[2][ni][j] * ry);
                P[pass][ni][j][1] = 0.1f * (qq * ry + u[1][ni][j] + vv[2][ni][j] * rx - vv[0][ni][j] * rz);
                P[pass][ni][j][2] = 0.1f * (qq * rz + u[2][ni][j] + vv[0][ni][j] * ry - vv[1][ni][j] * rx);
            }
    }
    __syncthreads();

    // ---- transpose to sP[128][96] ----
#pragma unroll
    for (int pass = 0; pass < 2; pass++)
#pragma unroll
        for (int ni = 0; ni < 2; ni++)
#pragma unroll
            for (int j = 0; j < 4; j++) {
                int row = pass * 64 + rg * 16 + ar + ((j >= 2) ? 8 : 0);
                int col = n0 + ni * 8 + 2 * ac + (j & 1);
                float* p = sP + row * 96 + col * 3;
                p[0] = P[pass][ni][j][0];
                p[1] = P[pass][ni][j][1];
                p[2] = P[pass][ni][j][2];
            }
    __syncthreads();

    // ---- vector scatter: 24 red4 per edge ----
    const float4* sP4 = (const float4*)sP;
    for (int it = 0; it < 16; it++) {
        int el = it * 8 + wid;
        int sn = s_src[el];
        if (sn >= 0 && lane < 24) {
            float4 v = sP4[el * 24 + lane];
            red4(Bv + (size_t)sn * 96 + lane * 4, v.x, v.y, v.z, v.w);
        }
    }
}

// ---------------- K2: fp16 mma fused MLP chain (256 thr, 8 warps) ----------------
__global__ void __launch_bounds__(256)
k_edge2(const float* __restrict__ bm1, const float* __restrict__ bm2,
        const int* __restrict__ src, float* __restrict__ Ba, int e_base, int e_end)
{
    extern __shared__ __align__(16) __half smh[];
    __half* As = smh;
    __half* W0 = smh + WBLOBH;
    __half* W1 = smh + 2 * WBLOBH;
    __shared__ float s_b1[128], s_b2[128];
    __shared__ int s_src[128];

    int tid = threadIdx.x, wid = tid >> 5, lane = tid & 31;
    int m0 = (wid >> 1) * 32, n0 = (wid & 1) * 64;
    int gr = lane >> 2, tc = lane & 3;
    int e0 = e_base + blockIdx.x * 128;

    if (tid < 128) {
        s_b1[tid] = bm1[tid];
        s_b2[tid] = bm2[tid];
        int e = e0 + tid;
        s_src[tid] = (e < e_end) ? src[e] : -1;
    }

    uint32_t uA  = smem_u32(As);
    uint32_t uW0 = smem_u32(W0);
    uint32_t uW1 = smem_u32(W1);

    // A: 128 rows x 64 halves (128B/row contiguous in g_Y) -> As rows (272B stride)
    for (int idx = tid; idx < 1024; idx += 256) {
        int m = idx >> 3, c = idx & 7;
        cp16(uA + (uint32_t)(m * (LDH * 2) + c * 16),
             (const char*)(g_Y + (size_t)(e0 + m) * 64) + c * 16);
    }
    for (int idx = tid; idx < 2176; idx += 256)
        cp16(uW0 + (uint32_t)(idx * 16), (const char*)g_Wb[0] + idx * 16);
    CP_COMMIT();
    for (int idx = tid; idx < 2176; idx += 256)
        cp16(uW1 + (uint32_t)(idx * 16), (const char*)g_Wb[1] + idx * 16);
    CP_COMMIT();
    CP_WAIT(1);
    __syncthreads();

    float acc[2][8][4];
#pragma unroll
    for (int mi = 0; mi < 2; mi++)
#pragma unroll
        for (int ni = 0; ni < 8; ni++)
#pragma unroll
            for (int j = 0; j < 4; j++) acc[mi][ni][j] = 0.f;

    // ---- GEMM1: psi0 = Y @ Wcat^T (K=64 -> 4 ksteps) ----
    gemm_h(As, W0, 4, m0, n0, lane, acc);

    float psi[2][8][4];
#pragma unroll
    for (int mi = 0; mi < 2; mi++)
#pragma unroll
        for (int ni = 0; ni < 8; ni++)
#pragma unroll
            for (int j = 0; j < 4; j++) psi[mi][ni][j] = acc[mi][ni][j];

    __syncthreads();
#pragma unroll
    for (int mi = 0; mi < 2; mi++)
#pragma unroll
        for (int ni = 0; ni < 8; ni++) {
            int row = m0 + mi * 16 + gr;
            int cu = (n0 + ni * 8) / 2 + tc;   // uint index of col pair
            ((uint32_t*)(As + row * LDH))[cu]       = pack_h2(acc[mi][ni][0], acc[mi][ni][1]);
            ((uint32_t*)(As + (row + 8) * LDH))[cu] = pack_h2(acc[mi][ni][2], acc[mi][ni][3]);
        }
    for (int idx = tid; idx < 2176; idx += 256)
        cp16(uW0 + (uint32_t)(idx * 16), (const char*)g_Wb[2] + idx * 16);
    CP_COMMIT();
    CP_WAIT(1);
    __syncthreads();

    // ---- GEMM2: h1 = leaky(psi0 @ Wm1^T + b1) ----
#pragma unroll
    for (int mi = 0; mi < 2; mi++)
#pragma unroll
        for (int ni = 0; ni < 8; ni++)
#pragma unroll
            for (int j = 0; j < 4; j++) acc[mi][ni][j] = 0.f;
    gemm_h(As, W1, 8, m0, n0, lane, acc);
    __syncthreads();
#pragma unroll
    for (int mi = 0; mi < 2; mi++)
#pragma unroll
        for (int ni = 0; ni < 8; ni++) {
            int row = m0 + mi * 16 + gr;
            int col = n0 + ni * 8 + 2 * tc;
            int cu = col >> 1;
            float2 bb = *(const float2*)(s_b1 + col);
            ((uint32_t*)(As + row * LDH))[cu] =
                pack_h2(lk(acc[mi][ni][0] + bb.x), lk(acc[mi][ni][1] + bb.y));
            ((uint32_t*)(As + (row + 8) * LDH))[cu] =
                pack_h2(lk(acc[mi][ni][2] + bb.x), lk(acc[mi][ni][3] + bb.y));
        }
    for (int idx = tid; idx < 2176; idx += 256)
        cp16(uW1 + (uint32_t)(idx * 16), (const char*)g_Wb[3] + idx * 16);
    CP_COMMIT();
    CP_WAIT(1);
    __syncthreads();

    // ---- GEMM3: h2 = leaky(h1 @ Wm2^T + b2) ----
#pragma unroll
    for (int mi = 0; mi < 2; mi++)
#pragma unroll
        for (int ni = 0; ni < 8; ni++)
#pragma unroll
            for (int j = 0; j < 4; j++) acc[mi][ni][j] = 0.f;
    gemm_h(As, W0, 8, m0, n0, lane, acc);
    __syncthreads();
#pragma unroll
    for (int mi = 0; mi < 2; mi++)
#pragma unroll
        for (int ni = 0; ni < 8; ni++) {
            int row = m0 + mi * 16 + gr;
            int col = n0 + ni * 8 + 2 * tc;
            int cu = col >> 1;
            float2 bb = *(const float2*)(s_b2 + col);
            ((uint32_t*)(As + row * LDH))[cu] =
                pack_h2(lk(acc[mi][ni][0] + bb.x), lk(acc[mi][ni][1] + bb.y));
            ((uint32_t*)(As + (row + 8) * LDH))[cu] =
                pack_h2(lk(acc[mi][ni][2] + bb.x), lk(acc[mi][ni][3] + bb.y));
        }
    CP_WAIT(0);
    __syncthreads();

    // ---- GEMM4: psi_a = psi0 + h2 @ Wm3^T ; scatter ----
#pragma unroll
    for (int mi = 0; mi < 2; mi++)
#pragma unroll
        for (int ni = 0; ni < 8; ni++)
#pragma unroll
            for (int j = 0; j < 4; j++) acc[mi][ni][j] = psi[mi][ni][j];
    gemm_h(As, W1, 8, m0, n0, lane, acc);

#pragma unroll
    for (int mi = 0; mi < 2; mi++) {
        int row = m0 + mi * 16 + gr;
        int sn0 = s_src[row];
        int sn1 = s_src[row + 8];
#pragma unroll
        for (int ni = 0; ni < 8; ni++) {
            int col = n0 + ni * 8 + 2 * tc;
            if (sn0 >= 0)
                red2(Ba + (size_t)sn0 * 128 + col, 0.1f * acc[mi][ni][0], 0.1f * acc[mi][ni][1]);
            if (sn1 >= 0)
                red2(Ba + (size_t)sn1 * 128 + col, 0.1f * acc[mi][ni][2], 0.1f * acc[mi][ni][3]);
        }
    }
}

// ---------------- launch (multi-stream graph fork) ----------------
extern "C" void kernel_launch(void* const* d_in, const int* in_sizes, int n_in,
                              void* d_out, int out_size)
{
    const float* x_a   = (const float*)d_in[0];
    const float* x_v   = (const float*)d_in[1];
    const float* r_ij  = (const float*)d_in[2];
    const int*   src   = (const int*)  d_in[3];
    const int*   dst   = (const int*)  d_in[4];
    const float* WL0   = (const float*)d_in[5];
    const float* WL1   = (const float*)d_in[6];
    const float* Wenc  = (const float*)d_in[7];
    const float* benc  = (const float*)d_in[8];
    const float* Wy000 = (const float*)d_in[9];
    const float* Wy110 = (const float*)d_in[10];
    const float* Wy011 = (const float*)d_in[11];
    const float* Wy101 = (const float*)d_in[12];
    const float* Wy111 = (const float*)d_in[13];
    const float* Wm1   = (const float*)d_in[14];
    const float* bm1   = (const float*)d_in[15];
    const float* Wm2   = (const float*)d_in[16];
    const float* bm2   = (const float*)d_in[17];
    const float* Wm3   = (const float*)d_in[18];
    float* out = (float*)d_out;
    float* Bv  = out + (size_t)NN * 128;

    static cudaStream_t sA = nullptr, sB = nullptr;
    static cudaEvent_t evRoot, evM, evN, evPd, ev1B;
    if (!sA) {
        cudaStreamCreateWithFlags(&sA, cudaStreamNonBlocking);
        cudaStreamCreateWithFlags(&sB, cudaStreamNonBlocking);
        cudaEventCreateWithFlags(&evRoot, cudaEventDisableTiming);
        cudaEventCreateWithFlags(&evM,    cudaEventDisableTiming);
        cudaEventCreateWithFlags(&evN,    cudaEventDisableTiming);
        cudaEventCreateWithFlags(&evPd,   cudaEventDisableTiming);
        cudaEventCreateWithFlags(&ev1B,   cudaEventDisableTiming);

        int smem1 = (4 * 128 * LD1 + 3 * 32 * LD1 + 128 * 4) * (int)sizeof(float);
        int smem2 = 3 * WBLOBH * (int)sizeof(__half);
        cudaFuncSetAttribute(k_edge1, cudaFuncAttributeMaxDynamicSharedMemorySize, smem1);
        cudaFuncSetAttribute(k_edge2, cudaFuncAttributeMaxDynamicSharedMemorySize, smem2);
    }
    const int smem1 = (4 * 128 * LD1 + 3 * 32 * LD1 + 128 * 4) * (int)sizeof(float); // 89,600
    const int smem2 = 3 * WBLOBH * (int)sizeof(__half);                              // 104,448

    // fork
    cudaEventRecord(evRoot, 0);
    cudaStreamWaitEvent(sA, evRoot, 0);
    cudaStreamWaitEvent(sB, evRoot, 0);

    // head: memset (s0) || prep (sA) || node (sB)
    cudaMemsetAsync(out, 0, (size_t)out_size * sizeof(float), 0);
    cudaEventRecord(evM, 0);
    k_prep<<<(WBLOBH + 255) / 256, 256, 0, sA>>>(Wy000, Wy110, Wm1, Wm2, Wm3);
    cudaEventRecord(evPd, sA);
    k_node<<<(NN + 63) / 64, 256, 0, sB>>>(x_a, x_v, WL0, WL1);
    cudaEventRecord(evN, sB);

    // chunk A: edge1 on s0
    cudaStreamWaitEvent(0, evN, 0);
    k_edge1<<<EA_END / 128, 256, smem1, 0>>>(r_ij, src, dst, Wenc, benc,
                                             Wy011, Wy101, Wy111, Bv, 0, EA_END);

    // chunk B: edge1 on sB
    cudaStreamWaitEvent(sB, evM, 0);
    k_edge1<<<(NE - EA_END + 127) / 128, 256, smem1, sB>>>(r_ij, src, dst, Wenc, benc,
                                                           Wy011, Wy101, Wy111, Bv, EA_END, NE);
    cudaEventRecord(ev1B, sB);

    // chunk A: edge2 on s0 — overlaps edge1_B
    cudaStreamWaitEvent(0, evPd, 0);
    k_edge2<<<EA_END / 128, 256, smem2, 0>>>(bm1, bm2, src, out, 0, EA_END);

    // chunk B: edge2 on s0 after edge1_B joins
    cudaStreamWaitEvent(0, ev1B, 0);
    k_edge2<<<(NE - EA_END + 127) / 128, 256, smem2, 0>>>(bm1, bm2, src, out, EA_END, NE);
}

// round 8
// speedup vs baseline: 6.1009x; 1.2611x over previous
#include <cuda_runtime.h>
#include <cuda_fp16.h>
#include <cstdint>
#include <math.h>

#define NN 50000
#define NE 500000
#define NE_PAD 500096           // 3907 * 128
#define EA_END 249984           // 1953 * 128 — chunk A end
#define LDH 136                 // k_edge2 smem leading dim (halves)
#define WBLOBH (128 * LDH)      // one weight image (halves)
#define LD1 36                  // k_edge1 smem leading dim (floats)
#define W1B_N (3 * 32 * LD1)    // edge1 weight blob floats (3456)

// ---------------- scratch (device globals: allocation-free) ----------------
__device__ float g_L0[NN * 32];
__device__ float g_L1[NN * 3 * 32];
__device__ __align__(16) __half g_Y[(size_t)NE_PAD * 64];   // fp16 [e][64]
__device__ __align__(16) __half g_Wb[4][WBLOBH];            // fp16 MLP weights
__device__ __align__(16) float  g_W1b[W1B_N];               // tf32 edge1 weights

// ================= helpers =================
__device__ __forceinline__ uint32_t smem_u32(const void* p) {
    uint32_t a;
    asm("{ .reg .u64 t; cvta.to.shared.u64 t, %1; cvt.u32.u64 %0, t; }" : "=r"(a) : "l"(p));
    return a;
}
__device__ __forceinline__ uint32_t cvt_tf32(float f) {
    uint32_t r; asm("cvt.rna.tf32.f32 %0, %1;" : "=r"(r) : "f"(f)); return r;
}
__device__ __forceinline__ float tf32f(float f) { return __uint_as_float(cvt_tf32(f)); }
__device__ __forceinline__ uint32_t pack_h2(float x, float y) {
    __half2 h = __floats2half2_rn(x, y);
    return *reinterpret_cast<uint32_t*>(&h);
}

__device__ __forceinline__ void cp16(uint32_t d, const void* s) {
    asm volatile("cp.async.cg.shared.global [%0], [%1], 16;" :: "r"(d), "l"(s) : "memory");
}
#define CP_COMMIT() asm volatile("cp.async.commit_group;" ::: "memory")
#define CP_WAIT(n)  asm volatile("cp.async.wait_group %0;" :: "n"(n) : "memory")

__device__ __forceinline__ void red2(float* p, float a, float b) {
    asm volatile("red.global.add.v2.f32 [%0], {%1, %2};" :: "l"(p), "f"(a), "f"(b) : "memory");
}
__device__ __forceinline__ void red4(float* p, float a, float b, float c, float d) {
    asm volatile("red.global.add.v4.f32 [%0], {%1, %2, %3, %4};"
                 :: "l"(p), "f"(a), "f"(b), "f"(c), "f"(d) : "memory");
}
__device__ __forceinline__ float lk(float t) { return (t >= 0.f) ? t : 0.1f * t; }

__device__ __forceinline__ void mma8(float* c, const uint32_t* a, const uint32_t* b) {
    asm volatile("mma.sync.aligned.m16n8k8.row.col.f32.tf32.tf32.f32 "
        "{%0,%1,%2,%3}, {%4,%5,%6,%7}, {%8,%9}, {%0,%1,%2,%3};"
        : "+f"(c[0]), "+f"(c[1]), "+f"(c[2]), "+f"(c[3])
        : "r"(a[0]), "r"(a[1]), "r"(a[2]), "r"(a[3]), "r"(b[0]), "r"(b[1]));
}
__device__ __forceinline__ void mma16(float* c, const uint32_t* a, const uint32_t* b) {
    asm volatile("mma.sync.aligned.m16n8k16.row.col.f32.f16.f16.f32 "
        "{%0,%1,%2,%3}, {%4,%5,%6,%7}, {%8,%9}, {%0,%1,%2,%3};"
        : "+f"(c[0]), "+f"(c[1]), "+f"(c[2]), "+f"(c[3])
        : "r"(a[0]), "r"(a[1]), "r"(a[2]), "r"(a[3]), "r"(b[0]), "r"(b[1]));
}

// fp16 GEMM: A[m][k], W[n][k] halves, LDH leading dim, warp tile 32x64, 8 warps.
__device__ __forceinline__ void gemm_h(const __half* __restrict__ As,
                                       const __half* __restrict__ Ws,
                                       int ksteps, int m0, int n0, int lane,
                                       float acc[2][8][4])
{
    int gr = lane >> 2, tc = lane & 3;
    const uint32_t* Ap0 = (const uint32_t*)(As + (m0 + gr) * LDH) + tc;
    const uint32_t* Ap1 = (const uint32_t*)(As + (m0 + 16 + gr) * LDH) + tc;
    const uint32_t* Wp  = (const uint32_t*)(Ws + (n0 + gr) * LDH) + tc;
    const int ROW8 = 8 * (LDH / 2);
#pragma unroll 2
    for (int ks = 0; ks < ksteps; ks++) {
        int k0 = ks * 8;
        uint32_t a[2][4], b[8][2];
        a[0][0] = Ap0[k0];
        a[0][1] = Ap0[k0 + ROW8];
        a[0][2] = Ap0[k0 + 4];
        a[0][3] = Ap0[k0 + ROW8 + 4];
        a[1][0] = Ap1[k0];
        a[1][1] = Ap1[k0 + ROW8];
        a[1][2] = Ap1[k0 + 4];
        a[1][3] = Ap1[k0 + ROW8 + 4];
#pragma unroll
        for (int ni = 0; ni < 8; ni++) {
            const uint32_t* q = Wp + ni * ROW8 + k0;
            b[ni][0] = q[0];
            b[ni][1] = q[4];
        }
#pragma unroll
        for (int mi = 0; mi < 2; mi++)
#pragma unroll
            for (int ni = 0; ni < 8; ni++) mma16(acc[mi][ni], a[mi], b[ni]);
    }
}

// ---------------- K_prep: weights -> fp16 blobs + edge1 tf32 blob ----------------
__global__ void k_prep(const float* __restrict__ Wy000, const float* __restrict__ Wy110,
                       const float* __restrict__ Wm1, const float* __restrict__ Wm2,
                       const float* __restrict__ Wm3,
                       const float* __restrict__ W011, const float* __restrict__ W101,
                       const float* __restrict__ W111)
{
    int idx = blockIdx.x * 256 + threadIdx.x;
    if (idx < W1B_N) {
        int wi = idx / (32 * LD1), r = idx % (32 * LD1);
        int d = r / LD1, c = r % LD1;
        const float* Wsrc = (wi == 0) ? W011 : ((wi == 1) ? W101 : W111);
        g_W1b[idx] = (c < 32) ? tf32f(Wsrc[d * 32 + c]) : 0.f;
    }
    if (idx >= WBLOBH) return;
    int n = idx / LDH, k = idx % LDH;
    float w0 = 0.f, w1 = 0.f, w2 = 0.f, w3 = 0.f;
    if (k < 64)  w0 = (k < 32) ? Wy000[n * 32 + k] : Wy110[n * 32 + (k - 32)];
    if (k < 128) { w1 = Wm1[n * 128 + k]; w2 = Wm2[n * 128 + k]; w3 = Wm3[n * 128 + k]; }
    g_Wb[0][idx] = __float2half_rn(w0);
    g_Wb[1][idx] = __float2half_rn(w1);
    g_Wb[2][idx] = __float2half_rn(w2);
    g_Wb[3][idx] = __float2half_rn(w3);
}

// ---------------- K0: node projections (64 nodes/block) ----------------
__global__ void __launch_bounds__(256) k_node(
    const float* __restrict__ xa, const float* __restrict__ xv,
    const float* __restrict__ WL0, const float* __restrict__ WL1)
{
    __shared__ float sW0t[32][132];
    __shared__ float sW1t[32][33];
    int tid = threadIdx.x;
    for (int idx = tid; idx < 4096; idx += 256) {
        int c = idx >> 7, d = idx & 127;
        sW0t[c][d] = WL0[idx];
    }
    for (int idx = tid; idx < 1024; idx += 256) {
        int c = idx >> 5, d = idx & 31;
        sW1t[c][d] = WL1[idx];
    }
    __syncthreads();

    int w = tid >> 5, lane = tid & 31;
    const float4* wv = (const float4*)&sW0t[lane][0];

#pragma unroll 2
    for (int it = 0; it < 8; it++) {
        int n = blockIdx.x * 64 + it * 8 + w;
        if (n >= NN) return;

        const float4* x4 = (const float4*)(xa + n * 128);
        float acc = 0.f;
#pragma unroll 8
        for (int d4 = 0; d4 < 32; d4++) {
            float4 a = __ldg(x4 + d4), b = wv[d4];
            acc += a.x * b.x + a.y * b.y + a.z * b.z + a.w * b.w;
        }
        g_L0[n * 32 + lane] = acc;

        const float* xvp = xv + n * 96;
        float a0 = 0.f, a1 = 0.f, a2 = 0.f;
#pragma unroll 8
        for (int d = 0; d < 32; d++) {
            float wd = sW1t[lane][d];
            a0 += __ldg(xvp + 3 * d)     * wd;
            a1 += __ldg(xvp + 3 * d + 1) * wd;
            a2 += __ldg(xvp + 3 * d + 2) * wd;
        }
        g_L1[n * 96 +      lane] = a0;
        g_L1[n * 96 + 32 + lane] = a1;
        g_L1[n * 96 + 64 + lane] = a2;
    }
}

// ---------------- K1: edge light path ----------------
__global__ void __launch_bounds__(256, 2) k_edge1(
    const float* __restrict__ rij, const int* __restrict__ src,
    const int* __restrict__ dst,
    const float* __restrict__ Wenc, const float* __restrict__ benc,
    float* __restrict__ Bv, int e_base, int e_end)
{
    extern __shared__ __align__(16) float s1[];
    float* sY0 = s1;                   // 128 x LD1
    float* sGx = sY0 + 128 * LD1;
    float* sGy = sGx + 128 * LD1;
    float* sGz = sGy + 128 * LD1;
    float* sW  = sGz + 128 * LD1;      // 3 x 32 x LD1 (cp.async from g_W1b)
    float* s_rs = sW + W1B_N;          // 128 x 4
    float* s_ek = s_rs + 128 * 4;      // 128 x 8
    float* sP  = s1;                   // reuse after GEMMs: 128 x 96
    __shared__ float sWe[8 * 32];
    __shared__ float sbe[32];
    __shared__ int   s_src[128];
    __shared__ int   s_dst[128];

    int tid = threadIdx.x, wid = tid >> 5, lane = tid & 31;
    int e0 = e_base + blockIdx.x * 128;

    // weights via cp.async (pre-converted)
    {
        uint32_t uSW = smem_u32(sW);
        for (int idx = tid; idx < W1B_N / 4; idx += 256)
            cp16(uSW + (uint32_t)(idx * 16), (const char*)g_W1b + idx * 16);
        CP_COMMIT();
    }
    for (int idx = tid; idx < 256; idx += 256) {
        int c = idx >> 3, k = idx & 7;
        sWe[k * 32 + c] = Wenc[idx];
    }
    if (tid < 32) sbe[tid] = benc[tid];
    if (tid < 128) s_src[tid] = (e0 + tid < e_end) ? src[e0 + tid] : -1;

    // ---- prologue: thread-per-edge RBF + tanh ----
    if (tid < 128) {
        int e = e0 + tid;
        float sx = 0.f, sy = 0.f, sz = 0.f;
        if (e < e_end) {
            float rx = rij[3 * e], ry = rij[3 * e + 1], rz = rij[3 * e + 2];
            float rn = sqrtf(rx * rx + ry * ry + rz * rz);
#pragma unroll
            for (int k = 0; k < 8; k++) {
                float t = (rn - (5.0f / 7.0f) * (float)k) * 1.6f;
                s_ek[tid * 8 + k] = __expf(-t * t);
            }
            float n14 = 1.4f * rn;
            float em = __expf(-2.f * n14);
            float sq = __fdividef(1.f - em, (1.f + em) * fmaxf(n14, 1e-6f));
            sx = 1.4f * rx * sq; sy = 1.4f * ry * sq; sz = 1.4f * rz * sq;
            s_dst[tid] = dst[e];
        } else {
#pragma unroll
            for (int k = 0; k < 8; k++) s_ek[tid * 8 + k] = 0.f;
            s_dst[tid] = 0;
        }
        s_rs[tid * 4]     = sx;
        s_rs[tid * 4 + 1] = sy;
        s_rs[tid * 4 + 2] = sz;
    }
    CP_WAIT(0);
    __syncthreads();

    // ---- phase 1: per-edge channels (warp per edge) ----
    for (int it = 0; it < 16; it++) {
        int el = it * 8 + wid;
        int e  = e0 + el;
        bool ok = (e < e_end);
        float sx = s_rs[el * 4], sy = s_rs[el * 4 + 1], sz = s_rs[el * 4 + 2];

        float g = sbe[lane];
#pragma unroll
        for (int k = 0; k < 8; k++)
            g += s_ek[el * 8 + k] * sWe[k * 32 + lane];

        int dn = s_dst[el];
        float la  = g_L0[dn * 32 + lane];
        float lvx = g_L1[dn * 96 +      lane];
        float lvy = g_L1[dn * 96 + 32 + lane];
        float lvz = g_L1[dn * 96 + 64 + lane];

        float y0 = ok ? tf32f(la * g) : 0.f;
        float gx = ok ? tf32f(g * lvx) : 0.f;
        float gy = ok ? tf32f(g * lvy) : 0.f;
        float gz = ok ? tf32f(g * lvz) : 0.f;

        if (ok) {
            g_Y[(size_t)e * 64 + lane]      = __float2half_rn(la * g);
            g_Y[(size_t)e * 64 + 32 + lane] = __float2half_rn((lvx * sx + lvy * sy + lvz * sz) * g);
        }
        sY0[el * LD1 + lane] = y0;
        sGx[el * LD1 + lane] = gx;
        sGy[el * LD1 + lane] = gy;
        sGz[el * LD1 + lane] = gz;
    }
    __syncthreads();

    // ---- phase 2: 7 GEMMs per pass (q, u_xyz, v_xyz) ----
    int cg = wid & 1, rg = wid >> 1;
    int n0 = cg * 16;
    int ar = lane >> 2, ac = lane & 3;

    float P[2][2][4][3];

#pragma unroll
    for (int pass = 0; pass < 2; pass++) {
        int m0 = pass * 64 + rg * 16;
        float q[2][4], u[3][2][4], vv[3][2][4];
#pragma unroll
        for (int ni = 0; ni < 2; ni++)
#pragma unroll
            for (int j = 0; j < 4; j++) {
                q[ni][j] = 0.f;
#pragma unroll
                for (int i = 0; i < 3; i++) { u[i][ni][j] = 0.f; vv[i][ni][j] = 0.f; }
            }

        const float* Ay  = sY0 + (m0 + ar) * LD1 + ac;
        const float* Agx = sGx + (m0 + ar) * LD1 + ac;
        const float* Agy = sGy + (m0 + ar) * LD1 + ac;
        const float* Agz = sGz + (m0 + ar) * LD1 + ac;
        const float* B0 = sW + 0 * 32 * LD1 + (n0 + ar) * LD1 + ac;
        const float* B1 = sW + 1 * 32 * LD1 + (n0 + ar) * LD1 + ac;
        const float* B2 = sW + 2 * 32 * LD1 + (n0 + ar) * LD1 + ac;

#pragma unroll
        for (int ks = 0; ks < 4; ks++) {
            int k0 = ks * 8;
            uint32_t ay[4], ag[3][4];
            ay[0] = __float_as_uint(Ay[k0]);
            ay[1] = __float_as_uint(Ay[k0 + 8 * LD1]);
            ay[2] = __float_as_uint(Ay[k0 + 4]);
            ay[3] = __float_as_uint(Ay[k0 + 8 * LD1 + 4]);
            const float* Ags[3] = {Agx, Agy, Agz};
#pragma unroll
            for (int i = 0; i < 3; i++) {
                ag[i][0] = __float_as_uint(Ags[i][k0]);
                ag[i][1] = __float_as_uint(Ags[i][k0 + 8 * LD1]);
                ag[i][2] = __float_as_uint(Ags[i][k0 + 4]);
                ag[i][3] = __float_as_uint(Ags[i][k0 + 8 * LD1 + 4]);
            }
            uint32_t b0[2][2], b1[2][2], b2[2][2];
#pragma unroll
            for (int ni = 0; ni < 2; ni++) {
                b0[ni][0] = __float_as_uint(B0[ni * 8 * LD1 + k0]);
                b0[ni][1] = __float_as_uint(B0[ni * 8 * LD1 + k0 + 4]);
                b1[ni][0] = __float_as_uint(B1[ni * 8 * LD1 + k0]);
                b1[ni][1] = __float_as_uint(B1[ni * 8 * LD1 + k0 + 4]);
                b2[ni][0] = __float_as_uint(B2[ni * 8 * LD1 + k0]);
                b2[ni][1] = __float_as_uint(B2[ni * 8 * LD1 + k0 + 4]);
            }
#pragma unroll
            for (int ni = 0; ni < 2; ni++) {
                mma8(q[ni], ay, b0[ni]);
#pragma unroll
                for (int i = 0; i < 3; i++) {
                    mma8(u[i][ni],  ag[i], b1[ni]);
                    mma8(vv[i][ni], ag[i], b2[ni]);
                }
            }
        }

        int r0 = m0 + ar, r1 = r0 + 8;
        float rx0 = s_rs[r0 * 4], ry0 = s_rs[r0 * 4 + 1], rz0 = s_rs[r0 * 4 + 2];
        float rx1 = s_rs[r1 * 4], ry1 = s_rs[r1 * 4 + 1], rz1 = s_rs[r1 * 4 + 2];
#pragma unroll
        for (int ni = 0; ni < 2; ni++)
#pragma unroll
            for (int j = 0; j < 4; j++) {
                float rx = (j < 2) ? rx0 : rx1;
                float ry = (j < 2) ? ry0 : ry1;
                float rz = (j < 2) ? rz0 : rz1;
                float qq = q[ni][j];
                P[pass][ni][j][0] = 0.1f * (qq * rx + u[0][ni][j] + vv[1][ni][j] * rz - vv[2][ni][j] * ry);
                P[pass][ni][j][1] = 0.1f * (qq * ry + u[1][ni][j] + vv[2][ni][j] * rx - vv[0][ni][j] * rz);
                P[pass][ni][j][2] = 0.1f * (qq * rz + u[2][ni][j] + vv[0][ni][j] * ry - vv[1][ni][j] * rx);
            }
    }
    __syncthreads();

    // ---- transpose to sP[128][96] ----
#pragma unroll
    for (int pass = 0; pass < 2; pass++)
#pragma unroll
        for (int ni = 0; ni < 2; ni++)
#pragma unroll
            for (int j = 0; j < 4; j++) {
                int row = pass * 64 + rg * 16 + ar + ((j >= 2) ? 8 : 0);
                int col = n0 + ni * 8 + 2 * ac + (j & 1);
                float* p = sP + row * 96 + col * 3;
                p[0] = P[pass][ni][j][0];
                p[1] = P[pass][ni][j][1];
                p[2] = P[pass][ni][j][2];
            }
    __syncthreads();

    // ---- vector scatter: 24 red4 per edge ----
    const float4* sP4 = (const float4*)sP;
    for (int it = 0; it < 16; it++) {
        int el = it * 8 + wid;
        int sn = s_src[el];
        if (sn >= 0 && lane < 24) {
            float4 v = sP4[el * 24 + lane];
            red4(Bv + (size_t)sn * 96 + lane * 4, v.x, v.y, v.z, v.w);
        }
    }
}

// ---------------- K2: fp16 mma fused MLP chain (256 thr, 8 warps) ----------------
__global__ void __launch_bounds__(256)
k_edge2(const float* __restrict__ bm1, const float* __restrict__ bm2,
        const int* __restrict__ src, float* __restrict__ Ba, int e_base, int e_end)
{
    extern __shared__ __align__(16) __half smh[];
    __half* As = smh;
    __half* W0 = smh + WBLOBH;
    __half* W1 = smh + 2 * WBLOBH;
    __shared__ float s_b1[128], s_b2[128];
    __shared__ int s_src[128];

    int tid = threadIdx.x, wid = tid >> 5, lane = tid & 31;
    int m0 = (wid >> 1) * 32, n0 = (wid & 1) * 64;
    int gr = lane >> 2, tc = lane & 3;
    int e0 = e_base + blockIdx.x * 128;

    if (tid < 128) {
        s_b1[tid] = bm1[tid];
        s_b2[tid] = bm2[tid];
        int e = e0 + tid;
        s_src[tid] = (e < e_end) ? src[e] : -1;
    }

    uint32_t uA  = smem_u32(As);
    uint32_t uW0 = smem_u32(W0);
    uint32_t uW1 = smem_u32(W1);

    for (int idx = tid; idx < 1024; idx += 256) {
        int m = idx >> 3, c = idx & 7;
        cp16(uA + (uint32_t)(m * (LDH * 2) + c * 16),
             (const char*)(g_Y + (size_t)(e0 + m) * 64) + c * 16);
    }
    for (int idx = tid; idx < 2176; idx += 256)
        cp16(uW0 + (uint32_t)(idx * 16), (const char*)g_Wb[0] + idx * 16);
    CP_COMMIT();
    for (int idx = tid; idx < 2176; idx += 256)
        cp16(uW1 + (uint32_t)(idx * 16), (const char*)g_Wb[1] + idx * 16);
    CP_COMMIT();
    CP_WAIT(1);
    __syncthreads();

    float acc[2][8][4];
#pragma unroll
    for (int mi = 0; mi < 2; mi++)
#pragma unroll
        for (int ni = 0; ni < 8; ni++)
#pragma unroll
            for (int j = 0; j < 4; j++) acc[mi][ni][j] = 0.f;

    gemm_h(As, W0, 4, m0, n0, lane, acc);

    float psi[2][8][4];
#pragma unroll
    for (int mi = 0; mi < 2; mi++)
#pragma unroll
        for (int ni = 0; ni < 8; ni++)
#pragma unroll
            for (int j = 0; j < 4; j++) psi[mi][ni][j] = acc[mi][ni][j];

    __syncthreads();
#pragma unroll
    for (int mi = 0; mi < 2; mi++)
#pragma unroll
        for (int ni = 0; ni < 8; ni++) {
            int row = m0 + mi * 16 + gr;
            int cu = (n0 + ni * 8) / 2 + tc;
            ((uint32_t*)(As + row * LDH))[cu]       = pack_h2(acc[mi][ni][0], acc[mi][ni][1]);
            ((uint32_t*)(As + (row + 8) * LDH))[cu] = pack_h2(acc[mi][ni][2], acc[mi][ni][3]);
        }
    for (int idx = tid; idx < 2176; idx += 256)
        cp16(uW0 + (uint32_t)(idx * 16), (const char*)g_Wb[2] + idx * 16);
    CP_COMMIT();
    CP_WAIT(1);
    __syncthreads();

#pragma unroll
    for (int mi = 0; mi < 2; mi++)
#pragma unroll
        for (int ni = 0; ni < 8; ni++)
#pragma unroll
            for (int j = 0; j < 4; j++) acc[mi][ni][j] = 0.f;
    gemm_h(As, W1, 8, m0, n0, lane, acc);
    __syncthreads();
#pragma unroll
    for (int mi = 0; mi < 2; mi++)
#pragma unroll
        for (int ni = 0; ni < 8; ni++) {
            int row = m0 + mi * 16 + gr;
            int col = n0 + ni * 8 + 2 * tc;
            int cu = col >> 1;
            float2 bb = *(const float2*)(s_b1 + col);
            ((uint32_t*)(As + row * LDH))[cu] =
                pack_h2(lk(acc[mi][ni][0] + bb.x), lk(acc[mi][ni][1] + bb.y));
            ((uint32_t*)(As + (row + 8) * LDH))[cu] =
                pack_h2(lk(acc[mi][ni][2] + bb.x), lk(acc[mi][ni][3] + bb.y));
        }
    for (int idx = tid; idx < 2176; idx += 256)
        cp16(uW1 + (uint32_t)(idx * 16), (const char*)g_Wb[3] + idx * 16);
    CP_COMMIT();
    CP_WAIT(1);
    __syncthreads();

#pragma unroll
    for (int mi = 0; mi < 2; mi++)
#pragma unroll
        for (int ni = 0; ni < 8; ni++)
#pragma unroll
            for (int j = 0; j < 4; j++) acc[mi][ni][j] = 0.f;
    gemm_h(As, W0, 8, m0, n0, lane, acc);
    __syncthreads();
#pragma unroll
    for (int mi = 0; mi < 2; mi++)
#pragma unroll
        for (int ni = 0; ni < 8; ni++) {
            int row = m0 + mi * 16 + gr;
            int col = n0 + ni * 8 + 2 * tc;
            int cu = col >> 1;
            float2 bb = *(const float2*)(s_b2 + col);
            ((uint32_t*)(As + row * LDH))[cu] =
                pack_h2(lk(acc[mi][ni][0] + bb.x), lk(acc[mi][ni][1] + bb.y));
            ((uint32_t*)(As + (row + 8) * LDH))[cu] =
                pack_h2(lk(acc[mi][ni][2] + bb.x), lk(acc[mi][ni][3] + bb.y));
        }
    CP_WAIT(0);
    __syncthreads();

#pragma unroll
    for (int mi = 0; mi < 2; mi++)
#pragma unroll
        for (int ni = 0; ni < 8; ni++)
#pragma unroll
            for (int j = 0; j < 4; j++) acc[mi][ni][j] = psi[mi][ni][j];
    gemm_h(As, W1, 8, m0, n0, lane, acc);

#pragma unroll
    for (int mi = 0; mi < 2; mi++) {
        int row = m0 + mi * 16 + gr;
        int sn0 = s_src[row];
        int sn1 = s_src[row + 8];
#pragma unroll
        for (int ni = 0; ni < 8; ni++) {
            int col = n0 + ni * 8 + 2 * tc;
            if (sn0 >= 0)
                red2(Ba + (size_t)sn0 * 128 + col, 0.1f * acc[mi][ni][0], 0.1f * acc[mi][ni][1]);
            if (sn1 >= 0)
                red2(Ba + (size_t)sn1 * 128 + col, 0.1f * acc[mi][ni][2], 0.1f * acc[mi][ni][3]);
        }
    }
}

// ---------------- launch (multi-stream graph fork) ----------------
extern "C" void kernel_launch(void* const* d_in, const int* in_sizes, int n_in,
                              void* d_out, int out_size)
{
    const float* x_a   = (const float*)d_in[0];
    const float* x_v   = (const float*)d_in[1];
    const float* r_ij  = (const float*)d_in[2];
    const int*   src   = (const int*)  d_in[3];
    const int*   dst   = (const int*)  d_in[4];
    const float* WL0   = (const float*)d_in[5];
    const float* WL1   = (const float*)d_in[6];
    const float* Wenc  = (const float*)d_in[7];
    const float* benc  = (const float*)d_in[8];
    const float* Wy000 = (const float*)d_in[9];
    const float* Wy110 = (const float*)d_in[10];
    const float* Wy011 = (const float*)d_in[11];
    const float* Wy101 = (const float*)d_in[12];
    const float* Wy111 = (const float*)d_in[13];
    const float* Wm1   = (const float*)d_in[14];
    const float* bm1   = (const float*)d_in[15];
    const float* Wm2   = (const float*)d_in[16];
    const float* bm2   = (const float*)d_in[17];
    const float* Wm3   = (const float*)d_in[18];
    float* out = (float*)d_out;
    float* Bv  = out + (size_t)NN * 128;

    static cudaStream_t sA = nullptr, sB = nullptr;
    static cudaEvent_t evRoot, evM, evN, evPd, ev1B;
    if (!sA) {
        cudaStreamCreateWithFlags(&sA, cudaStreamNonBlocking);
        cudaStreamCreateWithFlags(&sB, cudaStreamNonBlocking);
        cudaEventCreateWithFlags(&evRoot, cudaEventDisableTiming);
        cudaEventCreateWithFlags(&evM,    cudaEventDisableTiming);
        cudaEventCreateWithFlags(&evN,    cudaEventDisableTiming);
        cudaEventCreateWithFlags(&evPd,   cudaEventDisableTiming);
        cudaEventCreateWithFlags(&ev1B,   cudaEventDisableTiming);

        int smem1 = (4 * 128 * LD1 + W1B_N + 128 * 4 + 128 * 8) * (int)sizeof(float);
        int smem2 = 3 * WBLOBH * (int)sizeof(__half);
        cudaFuncSetAttribute(k_edge1, cudaFuncAttributeMaxDynamicSharedMemorySize, smem1);
        cudaFuncSetAttribute(k_edge2, cudaFuncAttributeMaxDynamicSharedMemorySize, smem2);
    }
    const int smem1 = (4 * 128 * LD1 + W1B_N + 128 * 4 + 128 * 8) * (int)sizeof(float); // 93,696
    const int smem2 = 3 * WBLOBH * (int)sizeof(__half);                                 // 104,448

    // fork
    cudaEventRecord(evRoot, 0);
    cudaStreamWaitEvent(sA, evRoot, 0);
    cudaStreamWaitEvent(sB, evRoot, 0);

    // head: memset (s0) || prep (sA) || node (sB)
    cudaMemsetAsync(out, 0, (size_t)out_size * sizeof(float), 0);
    cudaEventRecord(evM, 0);
    k_prep<<<(WBLOBH + 255) / 256, 256, 0, sA>>>(Wy000, Wy110, Wm1, Wm2, Wm3,
                                                 Wy011, Wy101, Wy111);
    cudaEventRecord(evPd, sA);
    k_node<<<(NN + 63) / 64, 256, 0, sB>>>(x_a, x_v, WL0, WL1);
    cudaEventRecord(evN, sB);

    // chunk A: edge1 on s0 (needs node + prep)
    cudaStreamWaitEvent(0, evN, 0);
    cudaStreamWaitEvent(0, evPd, 0);
    k_edge1<<<EA_END / 128, 256, smem1, 0>>>(r_ij, src, dst, Wenc, benc, Bv, 0, EA_END);

    // chunk B: edge1 on sB (node in-stream; needs memset + prep)
    cudaStreamWaitEvent(sB, evM, 0);
    cudaStreamWaitEvent(sB, evPd, 0);
    k_edge1<<<(NE - EA_END + 127) / 128, 256, smem1, sB>>>(r_ij, src, dst, Wenc, benc,
                                                           Bv, EA_END, NE);
    cudaEventRecord(ev1B, sB);

    // chunk A: edge2 on s0 — overlaps edge1_B
    k_edge2<<<EA_END / 128, 256, smem2, 0>>>(bm1, bm2, src, out, 0, EA_END);

    // chunk B: edge2 on s0 after edge1_B joins
    cudaStreamWaitEvent(0, ev1B, 0);
    k_edge2<<<(NE - EA_END + 127) / 128, 256, smem2, 0>>>(bm1, bm2, src, out, EA_END, NE);
}

// round 9
// speedup vs baseline: 6.4732x; 1.0610x over previous
#include <cuda_runtime.h>
#include <cuda_fp16.h>
#include <cstdint>
#include <math.h>

#define NN 50000
#define NE 500000
#define NE_PAD 500096           // 3907 * 128
#define EA_END 249984           // 1953 * 128 — chunk A end
#define LDH 136                 // k_edge2 smem leading dim (halves)
#define WBLOBH (128 * LDH)      // one weight image (halves)
#define LD1H 40                 // k_edge1 smem leading dim (halves): 80B rows, conflict-free
#define W1H_N (3 * 32 * LD1H)   // edge1 fp16 weight blob halves (3840)

// ---------------- scratch (device globals: allocation-free) ----------------
__device__ float g_L0[NN * 32];
__device__ float g_L1[NN * 3 * 32];
__device__ __align__(16) __half g_Y[(size_t)NE_PAD * 64];   // fp16 [e][64]
__device__ __align__(16) __half g_Wb[4][WBLOBH];            // fp16 MLP weights
__device__ __align__(16) __half g_W1h[W1H_N];               // fp16 edge1 weights

// ================= helpers =================
__device__ __forceinline__ uint32_t smem_u32(const void* p) {
    uint32_t a;
    asm("{ .reg .u64 t; cvta.to.shared.u64 t, %1; cvt.u32.u64 %0, t; }" : "=r"(a) : "l"(p));
    return a;
}
__device__ __forceinline__ uint32_t pack_h2(float x, float y) {
    __half2 h = __floats2half2_rn(x, y);
    return *reinterpret_cast<uint32_t*>(&h);
}

__device__ __forceinline__ void cp16(uint32_t d, const void* s) {
    asm volatile("cp.async.cg.shared.global [%0], [%1], 16;" :: "r"(d), "l"(s) : "memory");
}
#define CP_COMMIT() asm volatile("cp.async.commit_group;" ::: "memory")
#define CP_WAIT(n)  asm volatile("cp.async.wait_group %0;" :: "n"(n) : "memory")

__device__ __forceinline__ void red2(float* p, float a, float b) {
    asm volatile("red.global.add.v2.f32 [%0], {%1, %2};" :: "l"(p), "f"(a), "f"(b) : "memory");
}
__device__ __forceinline__ void red4(float* p, float a, float b, float c, float d) {
    asm volatile("red.global.add.v4.f32 [%0], {%1, %2, %3, %4};"
                 :: "l"(p), "f"(a), "f"(b), "f"(c), "f"(d) : "memory");
}
__device__ __forceinline__ float lk(float t) { return (t >= 0.f) ? t : 0.1f * t; }

__device__ __forceinline__ void mma16(float* c, const uint32_t* a, const uint32_t* b) {
    asm volatile("mma.sync.aligned.m16n8k16.row.col.f32.f16.f16.f32 "
        "{%0,%1,%2,%3}, {%4,%5,%6,%7}, {%8,%9}, {%0,%1,%2,%3};"
        : "+f"(c[0]), "+f"(c[1]), "+f"(c[2]), "+f"(c[3])
        : "r"(a[0]), "r"(a[1]), "r"(a[2]), "r"(a[3]), "r"(b[0]), "r"(b[1]));
}

// fp16 GEMM: A[m][k], W[n][k] halves, LDH leading dim, warp tile 32x64, 8 warps. (k_edge2)
__device__ __forceinline__ void gemm_h(const __half* __restrict__ As,
                                       const __half* __restrict__ Ws,
                                       int ksteps, int m0, int n0, int lane,
                                       float acc[2][8][4])
{
    int gr = lane >> 2, tc = lane & 3;
    const uint32_t* Ap0 = (const uint32_t*)(As + (m0 + gr) * LDH) + tc;
    const uint32_t* Ap1 = (const uint32_t*)(As + (m0 + 16 + gr) * LDH) + tc;
    const uint32_t* Wp  = (const uint32_t*)(Ws + (n0 + gr) * LDH) + tc;
    const int ROW8 = 8 * (LDH / 2);
#pragma unroll 2
    for (int ks = 0; ks < ksteps; ks++) {
        int k0 = ks * 8;
        uint32_t a[2][4], b[8][2];
        a[0][0] = Ap0[k0];
        a[0][1] = Ap0[k0 + ROW8];
        a[0][2] = Ap0[k0 + 4];
        a[0][3] = Ap0[k0 + ROW8 + 4];
        a[1][0] = Ap1[k0];
        a[1][1] = Ap1[k0 + ROW8];
        a[1][2] = Ap1[k0 + 4];
        a[1][3] = Ap1[k0 + ROW8 + 4];
#pragma unroll
        for (int ni = 0; ni < 8; ni++) {
            const uint32_t* q = Wp + ni * ROW8 + k0;
            b[ni][0] = q[0];
            b[ni][1] = q[4];
        }
#pragma unroll
        for (int mi = 0; mi < 2; mi++)
#pragma unroll
            for (int ni = 0; ni < 8; ni++) mma16(acc[mi][ni], a[mi], b[ni]);
    }
}

// ---------------- K_prep: weights -> fp16 blobs ----------------
__global__ void k_prep(const float* __restrict__ Wy000, const float* __restrict__ Wy110,
                       const float* __restrict__ Wm1, const float* __restrict__ Wm2,
                       const float* __restrict__ Wm3,
                       const float* __restrict__ W011, const float* __restrict__ W101,
                       const float* __restrict__ W111)
{
    int idx = blockIdx.x * 256 + threadIdx.x;
    if (idx < W1H_N) {
        int wi = idx / (32 * LD1H), r = idx % (32 * LD1H);
        int d = r / LD1H, c = r % LD1H;
        const float* Wsrc = (wi == 0) ? W011 : ((wi == 1) ? W101 : W111);
        g_W1h[idx] = __float2half_rn((c < 32) ? Wsrc[d * 32 + c] : 0.f);
    }
    if (idx >= WBLOBH) return;
    int n = idx / LDH, k = idx % LDH;
    float w0 = 0.f, w1 = 0.f, w2 = 0.f, w3 = 0.f;
    if (k < 64)  w0 = (k < 32) ? Wy000[n * 32 + k] : Wy110[n * 32 + (k - 32)];
    if (k < 128) { w1 = Wm1[n * 128 + k]; w2 = Wm2[n * 128 + k]; w3 = Wm3[n * 128 + k]; }
    g_Wb[0][idx] = __float2half_rn(w0);
    g_Wb[1][idx] = __float2half_rn(w1);
    g_Wb[2][idx] = __float2half_rn(w2);
    g_Wb[3][idx] = __float2half_rn(w3);
}

// ---------------- K0: node projections (64 nodes/block) ----------------
__global__ void __launch_bounds__(256) k_node(
    const float* __restrict__ xa, const float* __restrict__ xv,
    const float* __restrict__ WL0, const float* __restrict__ WL1)
{
    __shared__ float sW0t[32][132];
    __shared__ float sW1t[32][33];
    int tid = threadIdx.x;
    for (int idx = tid; idx < 4096; idx += 256) {
        int c = idx >> 7, d = idx & 127;
        sW0t[c][d] = WL0[idx];
    }
    for (int idx = tid; idx < 1024; idx += 256) {
        int c = idx >> 5, d = idx & 31;
        sW1t[c][d] = WL1[idx];
    }
    __syncthreads();

    int w = tid >> 5, lane = tid & 31;
    const float4* wv = (const float4*)&sW0t[lane][0];

#pragma unroll 2
    for (int it = 0; it < 8; it++) {
        int n = blockIdx.x * 64 + it * 8 + w;
        if (n >= NN) return;

        const float4* x4 = (const float4*)(xa + n * 128);
        float acc = 0.f;
#pragma unroll 8
        for (int d4 = 0; d4 < 32; d4++) {
            float4 a = __ldg(x4 + d4), b = wv[d4];
            acc += a.x * b.x + a.y * b.y + a.z * b.z + a.w * b.w;
        }
        g_L0[n * 32 + lane] = acc;

        const float* xvp = xv + n * 96;
        float a0 = 0.f, a1 = 0.f, a2 = 0.f;
#pragma unroll 8
        for (int d = 0; d < 32; d++) {
            float wd = sW1t[lane][d];
            a0 += __ldg(xvp + 3 * d)     * wd;
            a1 += __ldg(xvp + 3 * d + 1) * wd;
            a2 += __ldg(xvp + 3 * d + 2) * wd;
        }
        g_L1[n * 96 +      lane] = a0;
        g_L1[n * 96 + 32 + lane] = a1;
        g_L1[n * 96 + 64 + lane] = a2;
    }
}

// ---------------- K1: edge light path (fp16 phase-2) ----------------
// dyn smem layout (bytes):
//   [0 .. 40960)        sH: 4 tiles of 128 x LD1H halves (Y0, Gx, Gy, Gz)
//   [40960 .. 48640)    sWh: 3 x 32 x LD1H halves
//   [48640 .. 50688)    s_rs: 128 x 4 floats
//   [50688 .. 54784)    s_ek: 128 x 8 floats
//   sP (reuse from 0):  128 x 96 floats = 49152 (valid: all earlier regions dead)
__global__ void __launch_bounds__(256, 2) k_edge1(
    const float* __restrict__ rij, const int* __restrict__ src,
    const int* __restrict__ dst,
    const float* __restrict__ Wenc, const float* __restrict__ benc,
    float* __restrict__ Bv, int e_base, int e_end)
{
    extern __shared__ __align__(16) char s1c[];
    __half* sH   = (__half*)s1c;                  // 4 x 128 x LD1H
    __half* sWh  = (__half*)(s1c + 40960);
    float*  s_rs = (float*)(s1c + 48640);
    float*  s_ek = (float*)(s1c + 50688);
    float*  sP   = (float*)s1c;                   // reuse after GEMMs
    __shared__ float sWe[8 * 32];
    __shared__ float sbe[32];
    __shared__ int   s_src[128];
    __shared__ int   s_dst[128];

    int tid = threadIdx.x, wid = tid >> 5, lane = tid & 31;
    int e0 = e_base + blockIdx.x * 128;

    // weights via cp.async (pre-converted fp16)
    {
        uint32_t uSW = smem_u32(sWh);
        for (int idx = tid; idx < W1H_N * 2 / 16; idx += 256)
            cp16(uSW + (uint32_t)(idx * 16), (const char*)g_W1h + idx * 16);
        CP_COMMIT();
    }
    for (int idx = tid; idx < 256; idx += 256) {
        int c = idx >> 3, k = idx & 7;
        sWe[k * 32 + c] = Wenc[idx];
    }
    if (tid < 32) sbe[tid] = benc[tid];
    if (tid < 128) s_src[tid] = (e0 + tid < e_end) ? src[e0 + tid] : -1;

    // ---- prologue: thread-per-edge RBF + tanh ----
    if (tid < 128) {
        int e = e0 + tid;
        float sx = 0.f, sy = 0.f, sz = 0.f;
        if (e < e_end) {
            float rx = rij[3 * e], ry = rij[3 * e + 1], rz = rij[3 * e + 2];
            float rn = sqrtf(rx * rx + ry * ry + rz * rz);
#pragma unroll
            for (int k = 0; k < 8; k++) {
                float t = (rn - (5.0f / 7.0f) * (float)k) * 1.6f;
                s_ek[tid * 8 + k] = __expf(-t * t);
            }
            float n14 = 1.4f * rn;
            float em = __expf(-2.f * n14);
            float sq = __fdividef(1.f - em, (1.f + em) * fmaxf(n14, 1e-6f));
            sx = 1.4f * rx * sq; sy = 1.4f * ry * sq; sz = 1.4f * rz * sq;
            s_dst[tid] = dst[e];
        } else {
#pragma unroll
            for (int k = 0; k < 8; k++) s_ek[tid * 8 + k] = 0.f;
            s_dst[tid] = 0;
        }
        s_rs[tid * 4]     = sx;
        s_rs[tid * 4 + 1] = sy;
        s_rs[tid * 4 + 2] = sz;
    }
    CP_WAIT(0);
    __syncthreads();

    // ---- phase 1: per-edge channels (warp per edge) ----
    __half* sY0 = sH;
    __half* sGx = sH + 128 * LD1H;
    __half* sGy = sH + 2 * 128 * LD1H;
    __half* sGz = sH + 3 * 128 * LD1H;
    for (int it = 0; it < 16; it++) {
        int el = it * 8 + wid;
        int e  = e0 + el;
        bool ok = (e < e_end);
        float sx = s_rs[el * 4], sy = s_rs[el * 4 + 1], sz = s_rs[el * 4 + 2];

        float g = sbe[lane];
#pragma unroll
        for (int k = 0; k < 8; k++)
            g += s_ek[el * 8 + k] * sWe[k * 32 + lane];

        int dn = s_dst[el];
        float la  = g_L0[dn * 32 + lane];
        float lvx = g_L1[dn * 96 +      lane];
        float lvy = g_L1[dn * 96 + 32 + lane];
        float lvz = g_L1[dn * 96 + 64 + lane];

        __half y0 = __float2half_rn(ok ? la * g : 0.f);
        __half gx = __float2half_rn(ok ? g * lvx : 0.f);
        __half gy = __float2half_rn(ok ? g * lvy : 0.f);
        __half gz = __float2half_rn(ok ? g * lvz : 0.f);

        if (ok) {
            g_Y[(size_t)e * 64 + lane]      = y0;
            g_Y[(size_t)e * 64 + 32 + lane] = __float2half_rn((lvx * sx + lvy * sy + lvz * sz) * g);
        }
        sY0[el * LD1H + lane] = y0;
        sGx[el * LD1H + lane] = gx;
        sGy[el * LD1H + lane] = gy;
        sGz[el * LD1H + lane] = gz;
    }
    __syncthreads();

    // ---- phase 2: 7 fp16 GEMMs per pass (q, u_xyz, v_xyz) ----
    int cg = wid & 1, rg = wid >> 1;
    int n0 = cg * 16;
    int ar = lane >> 2, ac = lane & 3;
    const int ROW8H = 8 * (LD1H / 2);   // 160 uints

    float P[2][2][4][3];

#pragma unroll
    for (int pass = 0; pass < 2; pass++) {
        int m0 = pass * 64 + rg * 16;
        float q[2][4], u[3][2][4], vv[3][2][4];
#pragma unroll
        for (int ni = 0; ni < 2; ni++)
#pragma unroll
            for (int j = 0; j < 4; j++) {
                q[ni][j] = 0.f;
#pragma unroll
                for (int i = 0; i < 3; i++) { u[i][ni][j] = 0.f; vv[i][ni][j] = 0.f; }
            }

        const uint32_t* Ay  = (const uint32_t*)(sY0 + (m0 + ar) * LD1H) + ac;
        const uint32_t* Agx = (const uint32_t*)(sGx + (m0 + ar) * LD1H) + ac;
        const uint32_t* Agy = (const uint32_t*)(sGy + (m0 + ar) * LD1H) + ac;
        const uint32_t* Agz = (const uint32_t*)(sGz + (m0 + ar) * LD1H) + ac;
        const uint32_t* B0 = (const uint32_t*)(sWh + 0 * 32 * LD1H + (n0 + ar) * LD1H) + ac;
        const uint32_t* B1 = (const uint32_t*)(sWh + 1 * 32 * LD1H + (n0 + ar) * LD1H) + ac;
        const uint32_t* B2 = (const uint32_t*)(sWh + 2 * 32 * LD1H + (n0 + ar) * LD1H) + ac;

#pragma unroll
        for (int ks = 0; ks < 2; ks++) {
            int k0 = ks * 8;
            uint32_t ay[4], ag[3][4];
            ay[0] = Ay[k0];
            ay[1] = Ay[k0 + ROW8H];
            ay[2] = Ay[k0 + 4];
            ay[3] = Ay[k0 + ROW8H + 4];
            const uint32_t* Ags[3] = {Agx, Agy, Agz};
#pragma unroll
            for (int i = 0; i < 3; i++) {
                ag[i][0] = Ags[i][k0];
                ag[i][1] = Ags[i][k0 + ROW8H];
                ag[i][2] = Ags[i][k0 + 4];
                ag[i][3] = Ags[i][k0 + ROW8H + 4];
            }
            uint32_t b0[2][2], b1[2][2], b2[2][2];
#pragma unroll
            for (int ni = 0; ni < 2; ni++) {
                b0[ni][0] = B0[ni * ROW8H + k0];
                b0[ni][1] = B0[ni * ROW8H + k0 + 4];
                b1[ni][0] = B1[ni * ROW8H + k0];
                b1[ni][1] = B1[ni * ROW8H + k0 + 4];
                b2[ni][0] = B2[ni * ROW8H + k0];
                b2[ni][1] = B2[ni * ROW8H + k0 + 4];
            }
#pragma unroll
            for (int ni = 0; ni < 2; ni++) {
                mma16(q[ni], ay, b0[ni]);
#pragma unroll
                for (int i = 0; i < 3; i++) {
                    mma16(u[i][ni],  ag[i], b1[ni]);
                    mma16(vv[i][ni], ag[i], b2[ni]);
                }
            }
        }

        int r0 = m0 + ar, r1 = r0 + 8;
        float rx0 = s_rs[r0 * 4], ry0 = s_rs[r0 * 4 + 1], rz0 = s_rs[r0 * 4 + 2];
        float rx1 = s_rs[r1 * 4], ry1 = s_rs[r1 * 4 + 1], rz1 = s_rs[r1 * 4 + 2];
#pragma unroll
        for (int ni = 0; ni < 2; ni++)
#pragma unroll
            for (int j = 0; j < 4; j++) {
                float rx = (j < 2) ? rx0 : rx1;
                float ry = (j < 2) ? ry0 : ry1;
                float rz = (j < 2) ? rz0 : rz1;
                float qq = q[ni][j];
                P[pass][ni][j][0] = 0.1f * (qq * rx + u[0][ni][j] + vv[1][ni][j] * rz - vv[2][ni][j] * ry);
                P[pass][ni][j][1] = 0.1f * (qq * ry + u[1][ni][j] + vv[2][ni][j] * rx - vv[0][ni][j] * rz);
                P[pass][ni][j][2] = 0.1f * (qq * rz + u[2][ni][j] + vv[0][ni][j] * ry - vv[1][ni][j] * rx);
            }
    }
    __syncthreads();

    // ---- transpose to sP[128][96] ----
#pragma unroll
    for (int pass = 0; pass < 2; pass++)
#pragma unroll
        for (int ni = 0; ni < 2; ni++)
#pragma unroll
            for (int j = 0; j < 4; j++) {
                int row = pass * 64 + rg * 16 + ar + ((j >= 2) ? 8 : 0);
                int col = n0 + ni * 8 + 2 * ac + (j & 1);
                float* p = sP + row * 96 + col * 3;
                p[0] = P[pass][ni][j][0];
                p[1] = P[pass][ni][j][1];
                p[2] = P[pass][ni][j][2];
            }
    __syncthreads();

    // ---- vector scatter: 24 red4 per edge ----
    const float4* sP4 = (const float4*)sP;
    for (int it = 0; it < 16; it++) {
        int el = it * 8 + wid;
        int sn = s_src[el];
        if (sn >= 0 && lane < 24) {
            float4 v = sP4[el * 24 + lane];
            red4(Bv + (size_t)sn * 96 + lane * 4, v.x, v.y, v.z, v.w);
        }
    }
}

// ---------------- K2: fp16 mma fused MLP chain (256 thr, 8 warps) ----------------
__global__ void __launch_bounds__(256)
k_edge2(const float* __restrict__ bm1, const float* __restrict__ bm2,
        const int* __restrict__ src, float* __restrict__ Ba, int e_base, int e_end)
{
    extern __shared__ __align__(16) __half smh[];
    __half* As = smh;
    __half* W0 = smh + WBLOBH;
    __half* W1 = smh + 2 * WBLOBH;
    __shared__ float s_b1[128], s_b2[128];
    __shared__ int s_src[128];

    int tid = threadIdx.x, wid = tid >> 5, lane = tid & 31;
    int m0 = (wid >> 1) * 32, n0 = (wid & 1) * 64;
    int gr = lane >> 2, tc = lane & 3;
    int e0 = e_base + blockIdx.x * 128;

    if (tid < 128) {
        s_b1[tid] = bm1[tid];
        s_b2[tid] = bm2[tid];
        int e = e0 + tid;
        s_src[tid] = (e < e_end) ? src[e] : -1;
    }

    uint32_t uA  = smem_u32(As);
    uint32_t uW0 = smem_u32(W0);
    uint32_t uW1 = smem_u32(W1);

    for (int idx = tid; idx < 1024; idx += 256) {
        int m = idx >> 3, c = idx & 7;
        cp16(uA + (uint32_t)(m * (LDH * 2) + c * 16),
             (const char*)(g_Y + (size_t)(e0 + m) * 64) + c * 16);
    }
    for (int idx = tid; idx < 2176; idx += 256)
        cp16(uW0 + (uint32_t)(idx * 16), (const char*)g_Wb[0] + idx * 16);
    CP_COMMIT();
    for (int idx = tid; idx < 2176; idx += 256)
        cp16(uW1 + (uint32_t)(idx * 16), (const char*)g_Wb[1] + idx * 16);
    CP_COMMIT();
    CP_WAIT(1);
    __syncthreads();

    float acc[2][8][4];
#pragma unroll
    for (int mi = 0; mi < 2; mi++)
#pragma unroll
        for (int ni = 0; ni < 8; ni++)
#pragma unroll
            for (int j = 0; j < 4; j++) acc[mi][ni][j] = 0.f;

    gemm_h(As, W0, 4, m0, n0, lane, acc);

    float psi[2][8][4];
#pragma unroll
    for (int mi = 0; mi < 2; mi++)
#pragma unroll
        for (int ni = 0; ni < 8; ni++)
#pragma unroll
            for (int j = 0; j < 4; j++) psi[mi][ni][j] = acc[mi][ni][j];

    __syncthreads();
#pragma unroll
    for (int mi = 0; mi < 2; mi++)
#pragma unroll
        for (int ni = 0; ni < 8; ni++) {
            int row = m0 + mi * 16 + gr;
            int cu = (n0 + ni * 8) / 2 + tc;
            ((uint32_t*)(As + row * LDH))[cu]       = pack_h2(acc[mi][ni][0], acc[mi][ni][1]);
            ((uint32_t*)(As + (row + 8) * LDH))[cu] = pack_h2(acc[mi][ni][2], acc[mi][ni][3]);
        }
    for (int idx = tid; idx < 2176; idx += 256)
        cp16(uW0 + (uint32_t)(idx * 16), (const char*)g_Wb[2] + idx * 16);
    CP_COMMIT();
    CP_WAIT(1);
    __syncthreads();

#pragma unroll
    for (int mi = 0; mi < 2; mi++)
#pragma unroll
        for (int ni = 0; ni < 8; ni++)
#pragma unroll
            for (int j = 0; j < 4; j++) acc[mi][ni][j] = 0.f;
    gemm_h(As, W1, 8, m0, n0, lane, acc);
    __syncthreads();
#pragma unroll
    for (int mi = 0; mi < 2; mi++)
#pragma unroll
        for (int ni = 0; ni < 8; ni++) {
            int row = m0 + mi * 16 + gr;
            int col = n0 + ni * 8 + 2 * tc;
            int cu = col >> 1;
            float2 bb = *(const float2*)(s_b1 + col);
            ((uint32_t*)(As + row * LDH))[cu] =
                pack_h2(lk(acc[mi][ni][0] + bb.x), lk(acc[mi][ni][1] + bb.y));
            ((uint32_t*)(As + (row + 8) * LDH))[cu] =
                pack_h2(lk(acc[mi][ni][2] + bb.x), lk(acc[mi][ni][3] + bb.y));
        }
    for (int idx = tid; idx < 2176; idx += 256)
        cp16(uW1 + (uint32_t)(idx * 16), (const char*)g_Wb[3] + idx * 16);
    CP_COMMIT();
    CP_WAIT(1);
    __syncthreads();

#pragma unroll
    for (int mi = 0; mi < 2; mi++)
#pragma unroll
        for (int ni = 0; ni < 8; ni++)
#pragma unroll
            for (int j = 0; j < 4; j++) acc[mi][ni][j] = 0.f;
    gemm_h(As, W0, 8, m0, n0, lane, acc);
    __syncthreads();
#pragma unroll
    for (int mi = 0; mi < 2; mi++)
#pragma unroll
        for (int ni = 0; ni < 8; ni++) {
            int row = m0 + mi * 16 + gr;
            int col = n0 + ni * 8 + 2 * tc;
            int cu = col >> 1;
            float2 bb = *(const float2*)(s_b2 + col);
            ((uint32_t*)(As + row * LDH))[cu] =
                pack_h2(lk(acc[mi][ni][0] + bb.x), lk(acc[mi][ni][1] + bb.y));
            ((uint32_t*)(As + (row + 8) * LDH))[cu] =
                pack_h2(lk(acc[mi][ni][2] + bb.x), lk(acc[mi][ni][3] + bb.y));
        }
    CP_WAIT(0);
    __syncthreads();

#pragma unroll
    for (int mi = 0; mi < 2; mi++)
#pragma unroll
        for (int ni = 0; ni < 8; ni++)
#pragma unroll
            for (int j = 0; j < 4; j++) acc[mi][ni][j] = psi[mi][ni][j];
    gemm_h(As, W1, 8, m0, n0, lane, acc);

#pragma unroll
    for (int mi = 0; mi < 2; mi++) {
        int row = m0 + mi * 16 + gr;
        int sn0 = s_src[row];
        int sn1 = s_src[row + 8];
#pragma unroll
        for (int ni = 0; ni < 8; ni++) {
            int col = n0 + ni * 8 + 2 * tc;
            if (sn0 >= 0)
                red2(Ba + (size_t)sn0 * 128 + col, 0.1f * acc[mi][ni][0], 0.1f * acc[mi][ni][1]);
            if (sn1 >= 0)
                red2(Ba + (size_t)sn1 * 128 + col, 0.1f * acc[mi][ni][2], 0.1f * acc[mi][ni][3]);
        }
    }
}

// ---------------- launch (multi-stream graph fork) ----------------
extern "C" void kernel_launch(void* const* d_in, const int* in_sizes, int n_in,
                              void* d_out, int out_size)
{
    const float* x_a   = (const float*)d_in[0];
    const float* x_v   = (const float*)d_in[1];
    const float* r_ij  = (const float*)d_in[2];
    const int*   src   = (const int*)  d_in[3];
    const int*   dst   = (const int*)  d_in[4];
    const float* WL0   = (const float*)d_in[5];
    const float* WL1   = (const float*)d_in[6];
    const float* Wenc  = (const float*)d_in[7];
    const float* benc  = (const float*)d_in[8];
    const float* Wy000 = (const float*)d_in[9];
    const float* Wy110 = (const float*)d_in[10];
    const float* Wy011 = (const float*)d_in[11];
    const float* Wy101 = (const float*)d_in[12];
    const float* Wy111 = (const float*)d_in[13];
    const float* Wm1   = (const float*)d_in[14];
    const float* bm1   = (const float*)d_in[15];
    const float* Wm2   = (const float*)d_in[16];
    const float* bm2   = (const float*)d_in[17];
    const float* Wm3   = (const float*)d_in[18];
    float* out = (float*)d_out;
    float* Bv  = out + (size_t)NN * 128;

    static cudaStream_t sA = nullptr, sB = nullptr;
    static cudaEvent_t evRoot, evM, evN, evPd, ev1B;
    if (!sA) {
        cudaStreamCreateWithFlags(&sA, cudaStreamNonBlocking);
        cudaStreamCreateWithFlags(&sB, cudaStreamNonBlocking);
        cudaEventCreateWithFlags(&evRoot, cudaEventDisableTiming);
        cudaEventCreateWithFlags(&evM,    cudaEventDisableTiming);
        cudaEventCreateWithFlags(&evN,    cudaEventDisableTiming);
        cudaEventCreateWithFlags(&evPd,   cudaEventDisableTiming);
        cudaEventCreateWithFlags(&ev1B,   cudaEventDisableTiming);

        int smem1 = 54784;
        int smem2 = 3 * WBLOBH * (int)sizeof(__half);
        cudaFuncSetAttribute(k_edge1, cudaFuncAttributeMaxDynamicSharedMemorySize, smem1);
        cudaFuncSetAttribute(k_edge2, cudaFuncAttributeMaxDynamicSharedMemorySize, smem2);
    }
    const int smem1 = 54784;
    const int smem2 = 3 * WBLOBH * (int)sizeof(__half);   // 104,448

    // fork
    cudaEventRecord(evRoot, 0);
    cudaStreamWaitEvent(sA, evRoot, 0);
    cudaStreamWaitEvent(sB, evRoot, 0);

    // head: memset (s0) || prep (sA) || node (sB)
    cudaMemsetAsync(out, 0, (size_t)out_size * sizeof(float), 0);
    cudaEventRecord(evM, 0);
    k_prep<<<(WBLOBH + 255) / 256, 256, 0, sA>>>(Wy000, Wy110, Wm1, Wm2, Wm3,
                                                 Wy011, Wy101, Wy111);
    cudaEventRecord(evPd, sA);
    k_node<<<(NN + 63) / 64, 256, 0, sB>>>(x_a, x_v, WL0, WL1);
    cudaEventRecord(evN, sB);

    // chunk A: edge1 on s0 (needs node + prep)
    cudaStreamWaitEvent(0, evN, 0);
    cudaStreamWaitEvent(0, evPd, 0);
    k_edge1<<<EA_END / 128, 256, smem1, 0>>>(r_ij, src, dst, Wenc, benc, Bv, 0, EA_END);

    // chunk B: edge1 on sB (node in-stream; needs memset + prep)
    cudaStreamWaitEvent(sB, evM, 0);
    cudaStreamWaitEvent(sB, evPd, 0);
    k_edge1<<<(NE - EA_END + 127) / 128, 256, smem1, sB>>>(r_ij, src, dst, Wenc, benc,
                                                           Bv, EA_END, NE);
    cudaEventRecord(ev1B, sB);

    // chunk A: edge2 on s0 — overlaps edge1_B
    k_edge2<<<EA_END / 128, 256, smem2, 0>>>(bm1, bm2, src, out, 0, EA_END);

    // chunk B: edge2 on s0 after edge1_B joins
    cudaStreamWaitEvent(0, ev1B, 0);
    k_edge2<<<(NE - EA_END + 127) / 128, 256, smem2, 0>>>(bm1, bm2, src, out, EA_END, NE);
}